// round 1
// baseline (speedup 1.0000x reference)
#include <cuda_runtime.h>
#include <math.h>
#include <stdint.h>

#define BB  2
#define TT  2048
#define DM  2048
#define NH  32
#define NKV 8
#define DH  64
#define BT  (BB*TT)
#define KVD (NKV*DH)   /* 512 */

// ---------------- scratch (device globals; no allocations allowed) ----------
__device__ float g_Q[(size_t)BT * DM];    // (B*T, 32*64) roped queries
__device__ float g_K[(size_t)BT * KVD];   // (B*T, 8*64)  roped keys
__device__ float g_V[(size_t)BT * KVD];   // (B*T, 8*64)  values
__device__ float g_A[(size_t)BT * DM];    // attention output (B*T, C)
__device__ float g_cos[TT * 32];
__device__ float g_sin[TT * 32];

// ---------------------------------------------------------------------------
// GEMM: C[M,N] = A[M,K] @ W[N,K]^T   (both operands K-contiguous, row-major)
// 128x128 tile, BK=16, 256 threads, 8x8 micro-tile.
// ---------------------------------------------------------------------------
__global__ void __launch_bounds__(256) gemm_nt(const float* __restrict__ A,
                                               const float* __restrict__ W,
                                               float* __restrict__ C,
                                               int M, int N, int K)
{
    __shared__ float As[16][132];   // [k][m], pad 132: conflict-free f4 reads
    __shared__ float Bs[16][132];   // [k][n]

    const int tid = threadIdx.x;
    const int tx = tid & 15;        // col group
    const int ty = tid >> 4;        // row group
    const int m0 = blockIdx.y * 128;
    const int n0 = blockIdx.x * 128;

    float acc[8][8];
#pragma unroll
    for (int i = 0; i < 8; i++)
#pragma unroll
        for (int j = 0; j < 8; j++) acc[i][j] = 0.f;

    for (int k0 = 0; k0 < K; k0 += 16) {
#pragma unroll
        for (int l = 0; l < 2; l++) {
            int idx = tid + l * 256;        // 0..511
            int m   = idx >> 2;             // 0..127
            int kq  = (idx & 3) << 2;       // 0,4,8,12
            float4 av = *(const float4*)(A + (size_t)(m0 + m) * K + k0 + kq);
            As[kq + 0][m] = av.x; As[kq + 1][m] = av.y;
            As[kq + 2][m] = av.z; As[kq + 3][m] = av.w;
            float4 bv = *(const float4*)(W + (size_t)(n0 + m) * K + k0 + kq);
            Bs[kq + 0][m] = bv.x; Bs[kq + 1][m] = bv.y;
            Bs[kq + 2][m] = bv.z; Bs[kq + 3][m] = bv.w;
        }
        __syncthreads();
#pragma unroll
        for (int k = 0; k < 16; k++) {
            float4 a0 = *(const float4*)&As[k][ty * 8];
            float4 a1 = *(const float4*)&As[k][ty * 8 + 4];
            float4 b0 = *(const float4*)&Bs[k][tx * 8];
            float4 b1 = *(const float4*)&Bs[k][tx * 8 + 4];
            float a[8] = {a0.x, a0.y, a0.z, a0.w, a1.x, a1.y, a1.z, a1.w};
            float b[8] = {b0.x, b0.y, b0.z, b0.w, b1.x, b1.y, b1.z, b1.w};
#pragma unroll
            for (int i = 0; i < 8; i++)
#pragma unroll
                for (int j = 0; j < 8; j++) acc[i][j] += a[i] * b[j];
        }
        __syncthreads();
    }

#pragma unroll
    for (int i = 0; i < 8; i++) {
        size_t row = (size_t)(m0 + ty * 8 + i) * N + n0 + tx * 8;
        *(float4*)(C + row)     = make_float4(acc[i][0], acc[i][1], acc[i][2], acc[i][3]);
        *(float4*)(C + row + 4) = make_float4(acc[i][4], acc[i][5], acc[i][6], acc[i][7]);
    }
}

// ---------------------------------------------------------------------------
// RoPE table (double precision angles -> fp32 table). T*32 threads, trivial.
// ---------------------------------------------------------------------------
__global__ void rope_table_kernel()
{
    int idx = blockIdx.x * blockDim.x + threadIdx.x;
    if (idx >= TT * 32) return;
    int t = idx >> 5;
    int i = idx & 31;
    double inv = pow(10000.0, -(double)i / 32.0);
    double a   = (double)t * inv;
    g_cos[idx] = (float)cos(a);
    g_sin[idx] = (float)sin(a);
}

// ---------------------------------------------------------------------------
// Apply RoPE in-place to Q (32 heads) and K (8 heads).
// One thread per (token, head, i<32) pair handles the (i, i+32) rotation.
// ---------------------------------------------------------------------------
__global__ void rope_apply_kernel()
{
    int idx = blockIdx.x * blockDim.x + threadIdx.x;
    const int total = BT * (NH + NKV) * 32;
    if (idx >= total) return;
    int i    = idx & 31;
    int rest = idx >> 5;
    int h    = rest % (NH + NKV);
    int bt   = rest / (NH + NKV);
    int t    = bt & (TT - 1);

    float c = g_cos[t * 32 + i];
    float s = g_sin[t * 32 + i];

    float* p;
    if (h < NH) p = g_Q + (size_t)bt * DM  + h * DH;
    else        p = g_K + (size_t)bt * KVD + (h - NH) * DH;

    float v0 = p[i];
    float v1 = p[i + 32];
    p[i]      = v0 * c - v1 * s;
    p[i + 32] = v1 * c + v0 * s;
}

// ---------------------------------------------------------------------------
// Flash attention (causal, GQA 32q/8kv, d=64).
// Block: 128 queries x one head. 256 threads (16x16), 8 rows x 4 key-cols
// micro-tile for S, 8 rows x 4 dim-cols for O.
// smem (dynamic, 100 KB): Qs[d][r] Ks[d][s] Vs[s][c] Ps[s][r]
// ---------------------------------------------------------------------------
#define AT_M 128
#define AT_S 64
#define PQ 132   // r-dim pad
#define PS 68    // s/c-dim pad

__global__ void __launch_bounds__(256) attn_kernel()
{
    extern __shared__ float sm[];
    float* Qs = sm;                    // [64][PQ]
    float* Ks = Qs + 64 * PQ;          // [64][PS]
    float* Vs = Ks + 64 * PS;          // [64][PS]
    float* Ps = Vs + 64 * PS;          // [64][PQ]

    const int tid = threadIdx.x;
    const int tx = tid & 15;           // 16 key/dim col groups (x4)
    const int ty = tid >> 4;           // 16 row groups (x8)
    const int q0 = blockIdx.x * AT_M;
    const int h  = blockIdx.y;
    const int b  = blockIdx.z;
    const int g  = h >> 2;             // kv head
    const float scale = 0.125f;        // 1/sqrt(64)

    // load Q tile, transposed to [d][r]
    const size_t qbase = ((size_t)b * TT + q0) * DM + h * DH;
#pragma unroll
    for (int l = 0; l < 8; l++) {
        int i  = tid + l * 256;        // 0..2047
        int r  = i >> 4;
        int d4 = (i & 15) << 2;
        float4 v = *(const float4*)(g_Q + qbase + (size_t)r * DM + d4);
        Qs[(d4 + 0) * PQ + r] = v.x;
        Qs[(d4 + 1) * PQ + r] = v.y;
        Qs[(d4 + 2) * PQ + r] = v.z;
        Qs[(d4 + 3) * PQ + r] = v.w;
    }

    float m_r[8], l_r[8], o[8][4];
#pragma unroll
    for (int i = 0; i < 8; i++) {
        m_r[i] = -INFINITY; l_r[i] = 0.f;
#pragma unroll
        for (int j = 0; j < 4; j++) o[i][j] = 0.f;
    }

    const int s_end = q0 + AT_M;
    for (int s0 = 0; s0 < s_end; s0 += AT_S) {
        __syncthreads();  // prior PV done with Ps/Vs; prior S done with Ks
        // load K (transposed [d][s]) and V ([s][c])
#pragma unroll
        for (int l = 0; l < 4; l++) {
            int i  = tid + l * 256;    // 0..1023
            int s  = i >> 4;
            int d4 = (i & 15) << 2;
            size_t gi = ((size_t)b * TT + s0 + s) * KVD + g * DH + d4;
            float4 kv = *(const float4*)(g_K + gi);
            Ks[(d4 + 0) * PS + s] = kv.x;
            Ks[(d4 + 1) * PS + s] = kv.y;
            Ks[(d4 + 2) * PS + s] = kv.z;
            Ks[(d4 + 3) * PS + s] = kv.w;
            float4 vv = *(const float4*)(g_V + gi);
            *(float4*)(Vs + s * PS + d4) = vv;
        }
        __syncthreads();

        // S = Q K^T  (rows ty*8+i, cols tx*4+j)
        float acc[8][4];
#pragma unroll
        for (int i = 0; i < 8; i++)
#pragma unroll
            for (int j = 0; j < 4; j++) acc[i][j] = 0.f;

#pragma unroll 16
        for (int d = 0; d < 64; d++) {
            float4 a0 = *(const float4*)(Qs + d * PQ + ty * 8);
            float4 a1 = *(const float4*)(Qs + d * PQ + ty * 8 + 4);
            float4 bb = *(const float4*)(Ks + d * PS + tx * 4);
            float a[8] = {a0.x, a0.y, a0.z, a0.w, a1.x, a1.y, a1.z, a1.w};
            float bv[4] = {bb.x, bb.y, bb.z, bb.w};
#pragma unroll
            for (int i = 0; i < 8; i++)
#pragma unroll
                for (int j = 0; j < 4; j++) acc[i][j] += a[i] * bv[j];
        }

        // scale + causal mask
        const bool need_mask = (s0 + AT_S - 1 > q0);
#pragma unroll
        for (int i = 0; i < 8; i++)
#pragma unroll
            for (int j = 0; j < 4; j++) {
                float v = acc[i][j] * scale;
                if (need_mask && (s0 + tx * 4 + j > q0 + ty * 8 + i))
                    v = -INFINITY;
                acc[i][j] = v;
            }

        // online softmax per row
#pragma unroll
        for (int i = 0; i < 8; i++) {
            float mx = acc[i][0];
            mx = fmaxf(mx, acc[i][1]);
            mx = fmaxf(mx, acc[i][2]);
            mx = fmaxf(mx, acc[i][3]);
#pragma unroll
            for (int off = 8; off > 0; off >>= 1)
                mx = fmaxf(mx, __shfl_xor_sync(0xffffffffu, mx, off, 16));
            float mnew  = fmaxf(m_r[i], mx);
            float alpha = __expf(m_r[i] - mnew);
            float rs = 0.f;
#pragma unroll
            for (int j = 0; j < 4; j++) {
                float p = __expf(acc[i][j] - mnew);
                Ps[(tx * 4 + j) * PQ + ty * 8 + i] = p;   // transposed [s][r]
                rs += p;
            }
#pragma unroll
            for (int off = 8; off > 0; off >>= 1)
                rs += __shfl_xor_sync(0xffffffffu, rs, off, 16);
            l_r[i] = l_r[i] * alpha + rs;
            m_r[i] = mnew;
#pragma unroll
            for (int j = 0; j < 4; j++) o[i][j] *= alpha;
        }
        __syncthreads();   // Ps visible to all

        // O += P V   (rows ty*8+i, dim cols tx*4+j)
#pragma unroll 16
        for (int s = 0; s < 64; s++) {
            float4 p0 = *(const float4*)(Ps + s * PQ + ty * 8);
            float4 p1 = *(const float4*)(Ps + s * PQ + ty * 8 + 4);
            float4 vv = *(const float4*)(Vs + s * PS + tx * 4);
            float p[8] = {p0.x, p0.y, p0.z, p0.w, p1.x, p1.y, p1.z, p1.w};
            float v[4] = {vv.x, vv.y, vv.z, vv.w};
#pragma unroll
            for (int i = 0; i < 8; i++)
#pragma unroll
                for (int j = 0; j < 4; j++) o[i][j] += p[i] * v[j];
        }
    }

    // epilogue: normalize, write to g_A in (B,T,C) layout
#pragma unroll
    for (int i = 0; i < 8; i++) {
        float inv = 1.f / l_r[i];
        size_t oi = ((size_t)b * TT + q0 + ty * 8 + i) * DM + h * DH + tx * 4;
        *(float4*)(g_A + oi) =
            make_float4(o[i][0] * inv, o[i][1] * inv, o[i][2] * inv, o[i][3] * inv);
    }
}

// ---------------------------------------------------------------------------
extern "C" void kernel_launch(void* const* d_in, const int* in_sizes, int n_in,
                              void* d_out, int out_size)
{
    const float* x  = (const float*)d_in[0];
    const float* Wq = (const float*)d_in[1];
    const float* Wk = (const float*)d_in[2];
    const float* Wv = (const float*)d_in[3];
    const float* Wo = (const float*)d_in[4];
    float* out = (float*)d_out;

    float *gq, *gk, *gv, *ga;
    cudaGetSymbolAddress((void**)&gq, g_Q);
    cudaGetSymbolAddress((void**)&gk, g_K);
    cudaGetSymbolAddress((void**)&gv, g_V);
    cudaGetSymbolAddress((void**)&ga, g_A);

    const int attn_smem = (64 * PQ + 64 * PS + 64 * PS + 64 * PQ) * (int)sizeof(float);
    cudaFuncSetAttribute(attn_kernel, cudaFuncAttributeMaxDynamicSharedMemorySize,
                         attn_smem);

    // QKV projections
    gemm_nt<<<dim3(DM  / 128, BT / 128), 256>>>(x, Wq, gq, BT, DM,  DM);
    gemm_nt<<<dim3(KVD / 128, BT / 128), 256>>>(x, Wk, gk, BT, KVD, DM);
    gemm_nt<<<dim3(KVD / 128, BT / 128), 256>>>(x, Wv, gv, BT, KVD, DM);

    // RoPE
    rope_table_kernel<<<(TT * 32 + 255) / 256, 256>>>();
    {
        int total = BT * (NH + NKV) * 32;
        rope_apply_kernel<<<(total + 255) / 256, 256>>>();
    }

    // attention
    attn_kernel<<<dim3(TT / AT_M, NH, BB), 256, attn_smem>>>();

    // output projection
    gemm_nt<<<dim3(DM / 128, BT / 128), 256>>>(ga, Wo, out, BT, DM, DM);
}

// round 3
// speedup vs baseline: 1.5961x; 1.5961x over previous
#include <cuda_runtime.h>
#include <cuda_bf16.h>
#include <math.h>
#include <stdint.h>

#define BB  2
#define TT  2048
#define DM  2048
#define NH  32
#define NKV 8
#define DH  64
#define BT  (BB*TT)
#define KVD (NKV*DH)   /* 512 */

// ---------------- scratch (device globals; no allocations allowed) ----------
__device__ float g_Q[(size_t)BT * DM];
__device__ float g_K[(size_t)BT * KVD];
__device__ float g_V[(size_t)BT * KVD];
__device__ float g_A[(size_t)BT * DM];
__device__ float g_cos[TT * 32];
__device__ float g_sin[TT * 32];

// ===================== helpers ======================
__device__ __forceinline__ uint32_t smem_u32(const void* p) {
    uint32_t a;
    asm("{ .reg .u64 t; cvta.to.shared.u64 t, %1; cvt.u32.u64 %0, t; }"
        : "=r"(a) : "l"(p));
    return a;
}

__device__ __forceinline__ void ldmx4(uint32_t& r0, uint32_t& r1,
                                      uint32_t& r2, uint32_t& r3, uint32_t a) {
    asm volatile("ldmatrix.sync.aligned.m8n8.x4.shared.b16 {%0,%1,%2,%3}, [%4];"
                 : "=r"(r0), "=r"(r1), "=r"(r2), "=r"(r3) : "r"(a));
}

__device__ __forceinline__ void mma16816(float* d, const uint32_t* a,
                                         const uint32_t* b) {
    asm volatile(
        "mma.sync.aligned.m16n8k16.row.col.f32.bf16.bf16.f32 "
        "{%0,%1,%2,%3},{%4,%5,%6,%7},{%8,%9},{%0,%1,%2,%3};"
        : "+f"(d[0]), "+f"(d[1]), "+f"(d[2]), "+f"(d[3])
        : "r"(a[0]), "r"(a[1]), "r"(a[2]), "r"(a[3]), "r"(b[0]), "r"(b[1]));
}

// split fp32 -> (hi, lo) bf16 pairs, packed as bf16x2 words
__device__ __forceinline__ void split4(float4 v, uint2& h, uint2& l) {
    __nv_bfloat16 hx = __float2bfloat16(v.x);
    __nv_bfloat16 hy = __float2bfloat16(v.y);
    __nv_bfloat16 hz = __float2bfloat16(v.z);
    __nv_bfloat16 hw = __float2bfloat16(v.w);
    float lx = v.x - __bfloat162float(hx);
    float ly = v.y - __bfloat162float(hy);
    float lz = v.z - __bfloat162float(hz);
    float lw = v.w - __bfloat162float(hw);
    __nv_bfloat162 h0 = __halves2bfloat162(hx, hy);
    __nv_bfloat162 h1 = __halves2bfloat162(hz, hw);
    __nv_bfloat162 l0 = __halves2bfloat162(__float2bfloat16(lx), __float2bfloat16(ly));
    __nv_bfloat162 l1 = __halves2bfloat162(__float2bfloat16(lz), __float2bfloat16(lw));
    h.x = *reinterpret_cast<uint32_t*>(&h0);
    h.y = *reinterpret_cast<uint32_t*>(&h1);
    l.x = *reinterpret_cast<uint32_t*>(&l0);
    l.y = *reinterpret_cast<uint32_t*>(&l1);
}

// ---------------------------------------------------------------------------
// GEMM: C[M,N] = A[M,K] @ W[N,K]^T via 3x bf16 mma.sync (hi/lo split).
// 128x128 CTA tile, 8 warps (32m x 64n each), BK=32, double-buffered smem.
// smem per stage: Ahi | Alo | Whi | Wlo, each 128 rows x 40 halves (80B pitch).
// ---------------------------------------------------------------------------
#define PITCH 40                 /* halves per row (32 data + 8 pad) */
#define MAT   (128 * PITCH * 2)  /* 10240 B per matrix */
#define STAGE (4 * MAT)          /* 40960 B */
#define GEMM_SMEM (2 * STAGE)    /* 81920 B */

__global__ void __launch_bounds__(256, 1)
gemm_bf16x3(const float* __restrict__ A, const float* __restrict__ W,
            float* __restrict__ C, int M, int N, int K)
{
    extern __shared__ char smc[];
    const uint32_t sb = smem_u32(smc);

    const int tid  = threadIdx.x;
    const int lane = tid & 31;
    const int wid  = tid >> 5;
    const int wm = (wid & 3) * 32;     // warp m offset in tile
    const int wn = (wid >> 2) * 64;    // warp n offset in tile
    const int m0 = blockIdx.y * 128;
    const int n0 = blockIdx.x * 128;

    float acc[2][8][4];
#pragma unroll
    for (int mt = 0; mt < 2; mt++)
#pragma unroll
        for (int nt = 0; nt < 8; nt++)
#pragma unroll
            for (int j = 0; j < 4; j++) acc[mt][nt][j] = 0.f;

    // ldmatrix lane-address components
    const int quad = lane >> 3;
    const int arow_off = (lane & 7) + (quad & 1) * 8;   // A: quad0/2 low rows
    const int acol_off = (quad >> 1) * 8;
    const int brow_off = (lane & 7) + (quad >> 1) * 8;  // B: quad2/3 upper rows
    const int bcol_off = (quad & 1) * 8;

    // per-thread global load coords: 4 x float4 per operand per chunk
    const int grow = tid >> 3;         // 0..31 base row (x4 iters -> stride 32? no)
    // actually: idx = tid + l*256; row = idx>>3 (0..127), q = idx&7
    float4 pa[4], pw[4];

    const int nch = K / 32;

    // ---- prologue: load + store chunk 0
    {
        const float* Ap = A + (size_t)m0 * K;
        const float* Wp = W + (size_t)n0 * K;
#pragma unroll
        for (int l = 0; l < 4; l++) {
            int idx = tid + l * 256;
            int row = idx >> 3, q = idx & 7;
            pa[l] = *(const float4*)(Ap + (size_t)row * K + q * 4);
            pw[l] = *(const float4*)(Wp + (size_t)row * K + q * 4);
        }
#pragma unroll
        for (int l = 0; l < 4; l++) {
            int idx = tid + l * 256;
            int row = idx >> 3, q = idx & 7;
            uint32_t off = (uint32_t)(row * PITCH + q * 4) * 2;
            uint2 h, lo;
            split4(pa[l], h, lo);
            *(uint2*)(smc + off)           = h;
            *(uint2*)(smc + MAT + off)     = lo;
            split4(pw[l], h, lo);
            *(uint2*)(smc + 2 * MAT + off) = h;
            *(uint2*)(smc + 3 * MAT + off) = lo;
        }
    }
    __syncthreads();

    for (int c = 0; c < nch; c++) {
        // prefetch next chunk into registers
        if (c + 1 < nch) {
            const float* Ap = A + (size_t)m0 * K + (c + 1) * 32;
            const float* Wp = W + (size_t)n0 * K + (c + 1) * 32;
#pragma unroll
            for (int l = 0; l < 4; l++) {
                int idx = tid + l * 256;
                int row = idx >> 3, q = idx & 7;
                pa[l] = *(const float4*)(Ap + (size_t)row * K + q * 4);
                pw[l] = *(const float4*)(Wp + (size_t)row * K + q * 4);
            }
        }

        // compute on buffer c&1
        const uint32_t base = sb + (c & 1) * STAGE;
#pragma unroll
        for (int ks = 0; ks < 32; ks += 16) {
            uint32_t ah[2][4], al[2][4];
#pragma unroll
            for (int mt = 0; mt < 2; mt++) {
                uint32_t addr = base +
                    ((uint32_t)((wm + mt * 16 + arow_off) * PITCH + ks + acol_off) << 1);
                ldmx4(ah[mt][0], ah[mt][1], ah[mt][2], ah[mt][3], addr);
                ldmx4(al[mt][0], al[mt][1], al[mt][2], al[mt][3], addr + MAT);
            }
            uint32_t bh[8][2], bl[8][2];
#pragma unroll
            for (int np = 0; np < 4; np++) {
                uint32_t addr = base + 2 * MAT +
                    ((uint32_t)((wn + np * 16 + brow_off) * PITCH + ks + bcol_off) << 1);
                uint32_t r0, r1, r2, r3;
                ldmx4(r0, r1, r2, r3, addr);
                bh[2 * np][0] = r0; bh[2 * np][1] = r1;
                bh[2 * np + 1][0] = r2; bh[2 * np + 1][1] = r3;
                ldmx4(r0, r1, r2, r3, addr + MAT);
                bl[2 * np][0] = r0; bl[2 * np][1] = r1;
                bl[2 * np + 1][0] = r2; bl[2 * np + 1][1] = r3;
            }
#pragma unroll
            for (int mt = 0; mt < 2; mt++)
#pragma unroll
                for (int nt = 0; nt < 8; nt++) {
                    mma16816(acc[mt][nt], ah[mt], bh[nt]);
                    mma16816(acc[mt][nt], ah[mt], bl[nt]);
                    mma16816(acc[mt][nt], al[mt], bh[nt]);
                }
        }

        // store next chunk into other buffer
        if (c + 1 < nch) {
            char* dst = smc + ((c + 1) & 1) * STAGE;
#pragma unroll
            for (int l = 0; l < 4; l++) {
                int idx = tid + l * 256;
                int row = idx >> 3, q = idx & 7;
                uint32_t off = (uint32_t)(row * PITCH + q * 4) * 2;
                uint2 h, lo;
                split4(pa[l], h, lo);
                *(uint2*)(dst + off)           = h;
                *(uint2*)(dst + MAT + off)     = lo;
                split4(pw[l], h, lo);
                *(uint2*)(dst + 2 * MAT + off) = h;
                *(uint2*)(dst + 3 * MAT + off) = lo;
            }
        }
        __syncthreads();
    }

    // epilogue: direct stores (each pair of accum regs = 8B aligned float2)
#pragma unroll
    for (int mt = 0; mt < 2; mt++) {
        int row = m0 + wm + mt * 16 + (lane >> 2);
#pragma unroll
        for (int nt = 0; nt < 8; nt++) {
            int col = n0 + wn + nt * 8 + (lane & 3) * 2;
            *(float2*)(C + (size_t)row * N + col) =
                make_float2(acc[mt][nt][0], acc[mt][nt][1]);
            *(float2*)(C + (size_t)(row + 8) * N + col) =
                make_float2(acc[mt][nt][2], acc[mt][nt][3]);
        }
    }
}

// ---------------------------------------------------------------------------
// RoPE table (double precision angles -> fp32 table).
// ---------------------------------------------------------------------------
__global__ void rope_table_kernel()
{
    int idx = blockIdx.x * blockDim.x + threadIdx.x;
    if (idx >= TT * 32) return;
    int t = idx >> 5;
    int i = idx & 31;
    double inv = pow(10000.0, -(double)i / 32.0);
    double a   = (double)t * inv;
    g_cos[idx] = (float)cos(a);
    g_sin[idx] = (float)sin(a);
}

// ---------------------------------------------------------------------------
// Apply RoPE in-place to Q (32 heads) and K (8 heads).
// ---------------------------------------------------------------------------
__global__ void rope_apply_kernel()
{
    int idx = blockIdx.x * blockDim.x + threadIdx.x;
    const int total = BT * (NH + NKV) * 32;
    if (idx >= total) return;
    int i    = idx & 31;
    int rest = idx >> 5;
    int h    = rest % (NH + NKV);
    int bt   = rest / (NH + NKV);
    int t    = bt & (TT - 1);

    float c = g_cos[t * 32 + i];
    float s = g_sin[t * 32 + i];

    float* p;
    if (h < NH) p = g_Q + (size_t)bt * DM  + h * DH;
    else        p = g_K + (size_t)bt * KVD + (h - NH) * DH;

    float v0 = p[i];
    float v1 = p[i + 32];
    p[i]      = v0 * c - v1 * s;
    p[i + 32] = v1 * c + v0 * s;
}

// ---------------------------------------------------------------------------
// Flash attention (causal, GQA 32q/8kv, d=64). SIMT fp32 (round-1 version).
// ---------------------------------------------------------------------------
#define AT_M 128
#define AT_S 64
#define PQ 132
#define PS 68

__global__ void __launch_bounds__(256) attn_kernel()
{
    extern __shared__ float sm[];
    float* Qs = sm;
    float* Ks = Qs + 64 * PQ;
    float* Vs = Ks + 64 * PS;
    float* Ps = Vs + 64 * PS;

    const int tid = threadIdx.x;
    const int tx = tid & 15;
    const int ty = tid >> 4;
    const int q0 = blockIdx.x * AT_M;
    const int h  = blockIdx.y;
    const int b  = blockIdx.z;
    const int g  = h >> 2;
    const float scale = 0.125f;

    const size_t qbase = ((size_t)b * TT + q0) * DM + h * DH;
#pragma unroll
    for (int l = 0; l < 8; l++) {
        int i  = tid + l * 256;
        int r  = i >> 4;
        int d4 = (i & 15) << 2;
        float4 v = *(const float4*)(g_Q + qbase + (size_t)r * DM + d4);
        Qs[(d4 + 0) * PQ + r] = v.x;
        Qs[(d4 + 1) * PQ + r] = v.y;
        Qs[(d4 + 2) * PQ + r] = v.z;
        Qs[(d4 + 3) * PQ + r] = v.w;
    }

    float m_r[8], l_r[8], o[8][4];
#pragma unroll
    for (int i = 0; i < 8; i++) {
        m_r[i] = -INFINITY; l_r[i] = 0.f;
#pragma unroll
        for (int j = 0; j < 4; j++) o[i][j] = 0.f;
    }

    const int s_end = q0 + AT_M;
    for (int s0 = 0; s0 < s_end; s0 += AT_S) {
        __syncthreads();
#pragma unroll
        for (int l = 0; l < 4; l++) {
            int i  = tid + l * 256;
            int s  = i >> 4;
            int d4 = (i & 15) << 2;
            size_t gi = ((size_t)b * TT + s0 + s) * KVD + g * DH + d4;
            float4 kv = *(const float4*)(g_K + gi);
            Ks[(d4 + 0) * PS + s] = kv.x;
            Ks[(d4 + 1) * PS + s] = kv.y;
            Ks[(d4 + 2) * PS + s] = kv.z;
            Ks[(d4 + 3) * PS + s] = kv.w;
            float4 vv = *(const float4*)(g_V + gi);
            *(float4*)(Vs + s * PS + d4) = vv;
        }
        __syncthreads();

        float acc[8][4];
#pragma unroll
        for (int i = 0; i < 8; i++)
#pragma unroll
            for (int j = 0; j < 4; j++) acc[i][j] = 0.f;

#pragma unroll 16
        for (int d = 0; d < 64; d++) {
            float4 a0 = *(const float4*)(Qs + d * PQ + ty * 8);
            float4 a1 = *(const float4*)(Qs + d * PQ + ty * 8 + 4);
            float4 bb = *(const float4*)(Ks + d * PS + tx * 4);
            float a[8] = {a0.x, a0.y, a0.z, a0.w, a1.x, a1.y, a1.z, a1.w};
            float bv[4] = {bb.x, bb.y, bb.z, bb.w};
#pragma unroll
            for (int i = 0; i < 8; i++)
#pragma unroll
                for (int j = 0; j < 4; j++) acc[i][j] += a[i] * bv[j];
        }

        const bool need_mask = (s0 + AT_S - 1 > q0);
#pragma unroll
        for (int i = 0; i < 8; i++)
#pragma unroll
            for (int j = 0; j < 4; j++) {
                float v = acc[i][j] * scale;
                if (need_mask && (s0 + tx * 4 + j > q0 + ty * 8 + i))
                    v = -INFINITY;
                acc[i][j] = v;
            }

#pragma unroll
        for (int i = 0; i < 8; i++) {
            float mx = acc[i][0];
            mx = fmaxf(mx, acc[i][1]);
            mx = fmaxf(mx, acc[i][2]);
            mx = fmaxf(mx, acc[i][3]);
#pragma unroll
            for (int off = 8; off > 0; off >>= 1)
                mx = fmaxf(mx, __shfl_xor_sync(0xffffffffu, mx, off, 16));
            float mnew  = fmaxf(m_r[i], mx);
            float alpha = __expf(m_r[i] - mnew);
            float rs = 0.f;
#pragma unroll
            for (int j = 0; j < 4; j++) {
                float p = __expf(acc[i][j] - mnew);
                Ps[(tx * 4 + j) * PQ + ty * 8 + i] = p;
                rs += p;
            }
#pragma unroll
            for (int off = 8; off > 0; off >>= 1)
                rs += __shfl_xor_sync(0xffffffffu, rs, off, 16);
            l_r[i] = l_r[i] * alpha + rs;
            m_r[i] = mnew;
#pragma unroll
            for (int j = 0; j < 4; j++) o[i][j] *= alpha;
        }
        __syncthreads();

#pragma unroll 16
        for (int s = 0; s < 64; s++) {
            float4 p0 = *(const float4*)(Ps + s * PQ + ty * 8);
            float4 p1 = *(const float4*)(Ps + s * PQ + ty * 8 + 4);
            float4 vv = *(const float4*)(Vs + s * PS + tx * 4);
            float p[8] = {p0.x, p0.y, p0.z, p0.w, p1.x, p1.y, p1.z, p1.w};
            float v[4] = {vv.x, vv.y, vv.z, vv.w};
#pragma unroll
            for (int i = 0; i < 8; i++)
#pragma unroll
                for (int j = 0; j < 4; j++) o[i][j] += p[i] * v[j];
        }
    }

#pragma unroll
    for (int i = 0; i < 8; i++) {
        float inv = 1.f / l_r[i];
        size_t oi = ((size_t)b * TT + q0 + ty * 8 + i) * DM + h * DH + tx * 4;
        *(float4*)(g_A + oi) =
            make_float4(o[i][0] * inv, o[i][1] * inv, o[i][2] * inv, o[i][3] * inv);
    }
}

// ---------------------------------------------------------------------------
extern "C" void kernel_launch(void* const* d_in, const int* in_sizes, int n_in,
                              void* d_out, int out_size)
{
    const float* x  = (const float*)d_in[0];
    const float* Wq = (const float*)d_in[1];
    const float* Wk = (const float*)d_in[2];
    const float* Wv = (const float*)d_in[3];
    const float* Wo = (const float*)d_in[4];
    float* out = (float*)d_out;

    float *gq, *gk, *gv, *ga;
    cudaGetSymbolAddress((void**)&gq, g_Q);
    cudaGetSymbolAddress((void**)&gk, g_K);
    cudaGetSymbolAddress((void**)&gv, g_V);
    cudaGetSymbolAddress((void**)&ga, g_A);

    cudaFuncSetAttribute(gemm_bf16x3, cudaFuncAttributeMaxDynamicSharedMemorySize,
                         GEMM_SMEM);
    const int attn_smem = (64 * PQ + 64 * PS + 64 * PS + 64 * PQ) * (int)sizeof(float);
    cudaFuncSetAttribute(attn_kernel, cudaFuncAttributeMaxDynamicSharedMemorySize,
                         attn_smem);

    // QKV projections (tensor core, 3x bf16 split)
    gemm_bf16x3<<<dim3(DM  / 128, BT / 128), 256, GEMM_SMEM>>>(x, Wq, gq, BT, DM,  DM);
    gemm_bf16x3<<<dim3(KVD / 128, BT / 128), 256, GEMM_SMEM>>>(x, Wk, gk, BT, KVD, DM);
    gemm_bf16x3<<<dim3(KVD / 128, BT / 128), 256, GEMM_SMEM>>>(x, Wv, gv, BT, KVD, DM);

    // RoPE
    rope_table_kernel<<<(TT * 32 + 255) / 256, 256>>>();
    {
        int total = BT * (NH + NKV) * 32;
        rope_apply_kernel<<<(total + 255) / 256, 256>>>();
    }

    // attention (SIMT fp32)
    attn_kernel<<<dim3(TT / AT_M, NH, BB), 256, attn_smem>>>();

    // output projection
    gemm_bf16x3<<<dim3(DM / 128, BT / 128), 256, GEMM_SMEM>>>(ga, Wo, out, BT, DM, DM);
}

// round 4
// speedup vs baseline: 2.2894x; 1.4344x over previous
#include <cuda_runtime.h>
#include <cuda_bf16.h>
#include <math.h>
#include <stdint.h>

#define BB  2
#define TT  2048
#define DM  2048
#define NH  32
#define NKV 8
#define DH  64
#define BT  (BB*TT)
#define KVD (NKV*DH)   /* 512 */

// ---------------- scratch (device globals; no allocations allowed) ----------
__device__ float g_Q[(size_t)BT * DM];
__device__ float g_K[(size_t)BT * KVD];
__device__ float g_V[(size_t)BT * KVD];
__device__ float g_A[(size_t)BT * DM];
__device__ float g_cos[TT * 32];
__device__ float g_sin[TT * 32];

// ===================== helpers ======================
__device__ __forceinline__ uint32_t smem_u32(const void* p) {
    uint32_t a;
    asm("{ .reg .u64 t; cvta.to.shared.u64 t, %1; cvt.u32.u64 %0, t; }"
        : "=r"(a) : "l"(p));
    return a;
}

__device__ __forceinline__ void ldmx4(uint32_t& r0, uint32_t& r1,
                                      uint32_t& r2, uint32_t& r3, uint32_t a) {
    asm volatile("ldmatrix.sync.aligned.m8n8.x4.shared.b16 {%0,%1,%2,%3}, [%4];"
                 : "=r"(r0), "=r"(r1), "=r"(r2), "=r"(r3) : "r"(a));
}

__device__ __forceinline__ void mma16816(float* d, const uint32_t* a,
                                         const uint32_t* b) {
    asm volatile(
        "mma.sync.aligned.m16n8k16.row.col.f32.bf16.bf16.f32 "
        "{%0,%1,%2,%3},{%4,%5,%6,%7},{%8,%9},{%0,%1,%2,%3};"
        : "+f"(d[0]), "+f"(d[1]), "+f"(d[2]), "+f"(d[3])
        : "r"(a[0]), "r"(a[1]), "r"(a[2]), "r"(a[3]), "r"(b[0]), "r"(b[1]));
}

// split fp32 -> (hi, lo) bf16 pairs, packed as bf16x2 words
__device__ __forceinline__ void split4(float4 v, uint2& h, uint2& l) {
    __nv_bfloat16 hx = __float2bfloat16(v.x);
    __nv_bfloat16 hy = __float2bfloat16(v.y);
    __nv_bfloat16 hz = __float2bfloat16(v.z);
    __nv_bfloat16 hw = __float2bfloat16(v.w);
    float lx = v.x - __bfloat162float(hx);
    float ly = v.y - __bfloat162float(hy);
    float lz = v.z - __bfloat162float(hz);
    float lw = v.w - __bfloat162float(hw);
    __nv_bfloat162 h0 = __halves2bfloat162(hx, hy);
    __nv_bfloat162 h1 = __halves2bfloat162(hz, hw);
    __nv_bfloat162 l0 = __halves2bfloat162(__float2bfloat16(lx), __float2bfloat16(ly));
    __nv_bfloat162 l1 = __halves2bfloat162(__float2bfloat16(lz), __float2bfloat16(lw));
    h.x = *reinterpret_cast<uint32_t*>(&h0);
    h.y = *reinterpret_cast<uint32_t*>(&h1);
    l.x = *reinterpret_cast<uint32_t*>(&l0);
    l.y = *reinterpret_cast<uint32_t*>(&l1);
}

__device__ __forceinline__ uint32_t packbf(float a, float b) {
    __nv_bfloat162 t = __floats2bfloat162_rn(a, b);
    return *reinterpret_cast<uint32_t*>(&t);
}

// ---------------------------------------------------------------------------
// GEMM: C[M,N] = A[M,K] @ W[N,K]^T via 3x bf16 mma.sync (hi/lo split).
// ---------------------------------------------------------------------------
#define PITCH 40
#define MAT   (128 * PITCH * 2)
#define STAGE (4 * MAT)
#define GEMM_SMEM (2 * STAGE)

__global__ void __launch_bounds__(256, 1)
gemm_bf16x3(const float* __restrict__ A, const float* __restrict__ W,
            float* __restrict__ C, int M, int N, int K)
{
    extern __shared__ char smc[];
    const uint32_t sb = smem_u32(smc);

    const int tid  = threadIdx.x;
    const int lane = tid & 31;
    const int wid  = tid >> 5;
    const int wm = (wid & 3) * 32;
    const int wn = (wid >> 2) * 64;
    const int m0 = blockIdx.y * 128;
    const int n0 = blockIdx.x * 128;

    float acc[2][8][4];
#pragma unroll
    for (int mt = 0; mt < 2; mt++)
#pragma unroll
        for (int nt = 0; nt < 8; nt++)
#pragma unroll
            for (int j = 0; j < 4; j++) acc[mt][nt][j] = 0.f;

    const int quad = lane >> 3;
    const int arow_off = (lane & 7) + (quad & 1) * 8;
    const int acol_off = (quad >> 1) * 8;
    const int brow_off = (lane & 7) + (quad >> 1) * 8;
    const int bcol_off = (quad & 1) * 8;

    float4 pa[4], pw[4];
    const int nch = K / 32;

    {
        const float* Ap = A + (size_t)m0 * K;
        const float* Wp = W + (size_t)n0 * K;
#pragma unroll
        for (int l = 0; l < 4; l++) {
            int idx = tid + l * 256;
            int row = idx >> 3, q = idx & 7;
            pa[l] = *(const float4*)(Ap + (size_t)row * K + q * 4);
            pw[l] = *(const float4*)(Wp + (size_t)row * K + q * 4);
        }
#pragma unroll
        for (int l = 0; l < 4; l++) {
            int idx = tid + l * 256;
            int row = idx >> 3, q = idx & 7;
            uint32_t off = (uint32_t)(row * PITCH + q * 4) * 2;
            uint2 h, lo;
            split4(pa[l], h, lo);
            *(uint2*)(smc + off)           = h;
            *(uint2*)(smc + MAT + off)     = lo;
            split4(pw[l], h, lo);
            *(uint2*)(smc + 2 * MAT + off) = h;
            *(uint2*)(smc + 3 * MAT + off) = lo;
        }
    }
    __syncthreads();

    for (int c = 0; c < nch; c++) {
        if (c + 1 < nch) {
            const float* Ap = A + (size_t)m0 * K + (c + 1) * 32;
            const float* Wp = W + (size_t)n0 * K + (c + 1) * 32;
#pragma unroll
            for (int l = 0; l < 4; l++) {
                int idx = tid + l * 256;
                int row = idx >> 3, q = idx & 7;
                pa[l] = *(const float4*)(Ap + (size_t)row * K + q * 4);
                pw[l] = *(const float4*)(Wp + (size_t)row * K + q * 4);
            }
        }

        const uint32_t base = sb + (c & 1) * STAGE;
#pragma unroll
        for (int ks = 0; ks < 32; ks += 16) {
            uint32_t ah[2][4], al[2][4];
#pragma unroll
            for (int mt = 0; mt < 2; mt++) {
                uint32_t addr = base +
                    ((uint32_t)((wm + mt * 16 + arow_off) * PITCH + ks + acol_off) << 1);
                ldmx4(ah[mt][0], ah[mt][1], ah[mt][2], ah[mt][3], addr);
                ldmx4(al[mt][0], al[mt][1], al[mt][2], al[mt][3], addr + MAT);
            }
            uint32_t bh[8][2], bl[8][2];
#pragma unroll
            for (int np = 0; np < 4; np++) {
                uint32_t addr = base + 2 * MAT +
                    ((uint32_t)((wn + np * 16 + brow_off) * PITCH + ks + bcol_off) << 1);
                uint32_t r0, r1, r2, r3;
                ldmx4(r0, r1, r2, r3, addr);
                bh[2 * np][0] = r0; bh[2 * np][1] = r1;
                bh[2 * np + 1][0] = r2; bh[2 * np + 1][1] = r3;
                ldmx4(r0, r1, r2, r3, addr + MAT);
                bl[2 * np][0] = r0; bl[2 * np][1] = r1;
                bl[2 * np + 1][0] = r2; bl[2 * np + 1][1] = r3;
            }
#pragma unroll
            for (int mt = 0; mt < 2; mt++)
#pragma unroll
                for (int nt = 0; nt < 8; nt++) {
                    mma16816(acc[mt][nt], ah[mt], bh[nt]);
                    mma16816(acc[mt][nt], ah[mt], bl[nt]);
                    mma16816(acc[mt][nt], al[mt], bh[nt]);
                }
        }

        if (c + 1 < nch) {
            char* dst = smc + ((c + 1) & 1) * STAGE;
#pragma unroll
            for (int l = 0; l < 4; l++) {
                int idx = tid + l * 256;
                int row = idx >> 3, q = idx & 7;
                uint32_t off = (uint32_t)(row * PITCH + q * 4) * 2;
                uint2 h, lo;
                split4(pa[l], h, lo);
                *(uint2*)(dst + off)           = h;
                *(uint2*)(dst + MAT + off)     = lo;
                split4(pw[l], h, lo);
                *(uint2*)(dst + 2 * MAT + off) = h;
                *(uint2*)(dst + 3 * MAT + off) = lo;
            }
        }
        __syncthreads();
    }

#pragma unroll
    for (int mt = 0; mt < 2; mt++) {
        int row = m0 + wm + mt * 16 + (lane >> 2);
#pragma unroll
        for (int nt = 0; nt < 8; nt++) {
            int col = n0 + wn + nt * 8 + (lane & 3) * 2;
            *(float2*)(C + (size_t)row * N + col) =
                make_float2(acc[mt][nt][0], acc[mt][nt][1]);
            *(float2*)(C + (size_t)(row + 8) * N + col) =
                make_float2(acc[mt][nt][2], acc[mt][nt][3]);
        }
    }
}

// ---------------------------------------------------------------------------
// RoPE
// ---------------------------------------------------------------------------
__global__ void rope_table_kernel()
{
    int idx = blockIdx.x * blockDim.x + threadIdx.x;
    if (idx >= TT * 32) return;
    int t = idx >> 5;
    int i = idx & 31;
    double inv = pow(10000.0, -(double)i / 32.0);
    double a   = (double)t * inv;
    g_cos[idx] = (float)cos(a);
    g_sin[idx] = (float)sin(a);
}

__global__ void rope_apply_kernel()
{
    int idx = blockIdx.x * blockDim.x + threadIdx.x;
    const int total = BT * (NH + NKV) * 32;
    if (idx >= total) return;
    int i    = idx & 31;
    int rest = idx >> 5;
    int h    = rest % (NH + NKV);
    int bt   = rest / (NH + NKV);
    int t    = bt & (TT - 1);

    float c = g_cos[t * 32 + i];
    float s = g_sin[t * 32 + i];

    float* p;
    if (h < NH) p = g_Q + (size_t)bt * DM  + h * DH;
    else        p = g_K + (size_t)bt * KVD + (h - NH) * DH;

    float v0 = p[i];
    float v1 = p[i + 32];
    p[i]      = v0 * c - v1 * s;
    p[i + 32] = v1 * c + v0 * s;
}

// ---------------------------------------------------------------------------
// Flash attention on tensor cores (3x bf16 split, causal, GQA, d=64).
// CTA: 128 queries x 1 head. 8 warps x 16 q-rows. Key blocks of 128.
// smem: Kh[128][72] Kl[128][72] (halves), Vh[64][136] Vl[64][136] (transposed)
// Q staged through Kh/Kl once, kept in registers.
// ---------------------------------------------------------------------------
#define KP 72
#define MATK (128 * KP * 2)      /* 18432 B */
#define VP 136
#define VOFF (2 * MATK)          /* 36864 */
#define VMAT (64 * VP * 2)       /* 17408 B */
#define ATTN_SMEM (VOFF + 2 * VMAT)  /* 71680 B */

__global__ void __launch_bounds__(256, 1) attn_mma()
{
    extern __shared__ char smc[];
    const uint32_t sb = smem_u32(smc);

    const int tid  = threadIdx.x;
    const int lane = tid & 31;
    const int wid  = tid >> 5;
    const int wq   = wid * 16;

    const int quad = lane >> 3;
    const int arow_off = (lane & 7) + (quad & 1) * 8;
    const int acol_off = (quad >> 1) * 8;
    const int brow_off = (lane & 7) + (quad >> 1) * 8;
    const int bcol_off = (quad & 1) * 8;

    const int q0 = (gridDim.x - 1 - blockIdx.x) * 128;   // big tiles first
    const int h  = blockIdx.y;
    const int b  = blockIdx.z;
    const int g  = h >> 2;

    // ---- stage Q (scaled by 1/8) into Kh/Kl, then ldmatrix into registers
    {
        const float* Qp = g_Q + ((size_t)b * TT + q0) * DM + h * DH;
#pragma unroll
        for (int l = 0; l < 8; l++) {
            int idx = tid + l * 256;       // 0..2047
            int r   = idx >> 4;
            int d4  = (idx & 15) << 2;
            float4 v = *(const float4*)(Qp + (size_t)r * DM + d4);
            v.x *= 0.125f; v.y *= 0.125f; v.z *= 0.125f; v.w *= 0.125f;
            uint2 hh, ll;
            split4(v, hh, ll);
            uint32_t off = (uint32_t)(r * KP + d4) * 2;
            *(uint2*)(smc + off)        = hh;
            *(uint2*)(smc + MATK + off) = ll;
        }
    }
    __syncthreads();

    uint32_t qh[4][4], ql[4][4];
#pragma unroll
    for (int ks = 0; ks < 4; ks++) {
        uint32_t addr = sb + ((uint32_t)((wq + arow_off) * KP + ks * 16 + acol_off) << 1);
        ldmx4(qh[ks][0], qh[ks][1], qh[ks][2], qh[ks][3], addr);
        ldmx4(ql[ks][0], ql[ks][1], ql[ks][2], ql[ks][3], addr + MATK);
    }

    float oacc[8][4];
#pragma unroll
    for (int nt = 0; nt < 8; nt++)
#pragma unroll
        for (int j = 0; j < 4; j++) oacc[nt][j] = 0.f;
    float mrow0 = -1e30f, mrow1 = -1e30f, lrow0 = 0.f, lrow1 = 0.f;

    const int row0 = q0 + wq + (lane >> 2);
    const int row1 = row0 + 8;

    for (int s0 = 0; s0 <= q0; s0 += 128) {
        __syncthreads();
        // load K block (hi/lo) and V block transposed (hi/lo)
        {
            const float* Kp = g_K + ((size_t)b * TT + s0) * KVD + g * DH;
            const float* Vp = g_V + ((size_t)b * TT + s0) * KVD + g * DH;
#pragma unroll
            for (int l = 0; l < 8; l++) {
                int idx = tid + l * 256;
                int s   = idx >> 4;
                int d4  = (idx & 15) << 2;
                float4 kv = *(const float4*)(Kp + (size_t)s * KVD + d4);
                uint2 hh, ll;
                split4(kv, hh, ll);
                uint32_t off = (uint32_t)(s * KP + d4) * 2;
                *(uint2*)(smc + off)        = hh;
                *(uint2*)(smc + MATK + off) = ll;

                float4 vv = *(const float4*)(Vp + (size_t)s * KVD + d4);
                __nv_bfloat16* Vh = (__nv_bfloat16*)(smc + VOFF);
                __nv_bfloat16* Vl = (__nv_bfloat16*)(smc + VOFF + VMAT);
#pragma unroll
                for (int cc = 0; cc < 4; cc++) {
                    float f = (cc == 0) ? vv.x : (cc == 1) ? vv.y : (cc == 2) ? vv.z : vv.w;
                    __nv_bfloat16 fh = __float2bfloat16(f);
                    Vh[(d4 + cc) * VP + s] = fh;
                    Vl[(d4 + cc) * VP + s] = __float2bfloat16(f - __bfloat162float(fh));
                }
            }
        }
        __syncthreads();

        // ---- S = Q K^T (3-term)
        float sacc[16][4];
#pragma unroll
        for (int nt = 0; nt < 16; nt++)
#pragma unroll
            for (int j = 0; j < 4; j++) sacc[nt][j] = 0.f;

#pragma unroll
        for (int np = 0; np < 8; np++) {
#pragma unroll
            for (int ks = 0; ks < 4; ks++) {
                uint32_t addr = sb +
                    ((uint32_t)((np * 16 + brow_off) * KP + ks * 16 + bcol_off) << 1);
                uint32_t h0, h1, h2, h3, l0, l1, l2, l3;
                ldmx4(h0, h1, h2, h3, addr);
                ldmx4(l0, l1, l2, l3, addr + MATK);
                uint32_t bh0[2] = {h0, h1}, bh1[2] = {h2, h3};
                uint32_t bl0[2] = {l0, l1}, bl1[2] = {l2, l3};
                mma16816(sacc[2 * np],     qh[ks], bh0);
                mma16816(sacc[2 * np],     qh[ks], bl0);
                mma16816(sacc[2 * np],     ql[ks], bh0);
                mma16816(sacc[2 * np + 1], qh[ks], bh1);
                mma16816(sacc[2 * np + 1], qh[ks], bl1);
                mma16816(sacc[2 * np + 1], ql[ks], bh1);
            }
        }

        // ---- causal mask on diagonal block
        if (s0 == q0) {
            const int cbase = s0 + (lane & 3) * 2;
#pragma unroll
            for (int nt = 0; nt < 16; nt++) {
                int c0 = cbase + nt * 8;
                if (c0     > row0) sacc[nt][0] = -1e30f;
                if (c0 + 1 > row0) sacc[nt][1] = -1e30f;
                if (c0     > row1) sacc[nt][2] = -1e30f;
                if (c0 + 1 > row1) sacc[nt][3] = -1e30f;
            }
        }

        // ---- online softmax on fragments
        float mx0 = -1e30f, mx1 = -1e30f;
#pragma unroll
        for (int nt = 0; nt < 16; nt++) {
            mx0 = fmaxf(mx0, fmaxf(sacc[nt][0], sacc[nt][1]));
            mx1 = fmaxf(mx1, fmaxf(sacc[nt][2], sacc[nt][3]));
        }
        mx0 = fmaxf(mx0, __shfl_xor_sync(0xffffffffu, mx0, 1));
        mx0 = fmaxf(mx0, __shfl_xor_sync(0xffffffffu, mx0, 2));
        mx1 = fmaxf(mx1, __shfl_xor_sync(0xffffffffu, mx1, 1));
        mx1 = fmaxf(mx1, __shfl_xor_sync(0xffffffffu, mx1, 2));

        float mnew0 = fmaxf(mrow0, mx0);
        float mnew1 = fmaxf(mrow1, mx1);
        float alpha0 = __expf(mrow0 - mnew0);
        float alpha1 = __expf(mrow1 - mnew1);

        uint32_t ph[8][4], pl[8][4];
        float rs0 = 0.f, rs1 = 0.f;
#pragma unroll
        for (int ks = 0; ks < 8; ks++) {
#pragma unroll
            for (int half = 0; half < 2; half++) {
                int nt = 2 * ks + half;
                float p0 = __expf(sacc[nt][0] - mnew0);
                float p1 = __expf(sacc[nt][1] - mnew0);
                float p2 = __expf(sacc[nt][2] - mnew1);
                float p3 = __expf(sacc[nt][3] - mnew1);
                rs0 += p0 + p1;
                rs1 += p2 + p3;
                uint32_t h01 = packbf(p0, p1);
                uint32_t h23 = packbf(p2, p3);
                __nv_bfloat162 hv01 = *reinterpret_cast<__nv_bfloat162*>(&h01);
                __nv_bfloat162 hv23 = *reinterpret_cast<__nv_bfloat162*>(&h23);
                uint32_t lo01 = packbf(p0 - __bfloat162float(hv01.x),
                                       p1 - __bfloat162float(hv01.y));
                uint32_t lo23 = packbf(p2 - __bfloat162float(hv23.x),
                                       p3 - __bfloat162float(hv23.y));
                ph[ks][2 * half]     = h01;
                ph[ks][2 * half + 1] = h23;
                pl[ks][2 * half]     = lo01;
                pl[ks][2 * half + 1] = lo23;
            }
        }
        rs0 += __shfl_xor_sync(0xffffffffu, rs0, 1);
        rs0 += __shfl_xor_sync(0xffffffffu, rs0, 2);
        rs1 += __shfl_xor_sync(0xffffffffu, rs1, 1);
        rs1 += __shfl_xor_sync(0xffffffffu, rs1, 2);

        lrow0 = lrow0 * alpha0 + rs0;
        lrow1 = lrow1 * alpha1 + rs1;
        mrow0 = mnew0;
        mrow1 = mnew1;
#pragma unroll
        for (int nt = 0; nt < 8; nt++) {
            oacc[nt][0] *= alpha0;
            oacc[nt][1] *= alpha0;
            oacc[nt][2] *= alpha1;
            oacc[nt][3] *= alpha1;
        }

        // ---- O += P V (3-term); V already in smem (same sync scope)
#pragma unroll
        for (int np = 0; np < 4; np++) {
#pragma unroll
            for (int ks = 0; ks < 8; ks++) {
                uint32_t addr = sb + VOFF +
                    ((uint32_t)((np * 16 + brow_off) * VP + ks * 16 + bcol_off) << 1);
                uint32_t h0, h1, h2, h3, l0, l1, l2, l3;
                ldmx4(h0, h1, h2, h3, addr);
                ldmx4(l0, l1, l2, l3, addr + VMAT);
                uint32_t bh0[2] = {h0, h1}, bh1[2] = {h2, h3};
                uint32_t bl0[2] = {l0, l1}, bl1[2] = {l2, l3};
                mma16816(oacc[2 * np],     ph[ks], bh0);
                mma16816(oacc[2 * np],     ph[ks], bl0);
                mma16816(oacc[2 * np],     pl[ks], bh0);
                mma16816(oacc[2 * np + 1], ph[ks], bh1);
                mma16816(oacc[2 * np + 1], ph[ks], bl1);
                mma16816(oacc[2 * np + 1], pl[ks], bh1);
            }
        }
    }

    // ---- epilogue
    float inv0 = 1.f / lrow0;
    float inv1 = 1.f / lrow1;
    const size_t o0 = ((size_t)b * TT + row0) * DM + h * DH + (lane & 3) * 2;
    const size_t o1 = ((size_t)b * TT + row1) * DM + h * DH + (lane & 3) * 2;
#pragma unroll
    for (int nt = 0; nt < 8; nt++) {
        *(float2*)(g_A + o0 + nt * 8) = make_float2(oacc[nt][0] * inv0, oacc[nt][1] * inv0);
        *(float2*)(g_A + o1 + nt * 8) = make_float2(oacc[nt][2] * inv1, oacc[nt][3] * inv1);
    }
}

// ---------------------------------------------------------------------------
extern "C" void kernel_launch(void* const* d_in, const int* in_sizes, int n_in,
                              void* d_out, int out_size)
{
    const float* x  = (const float*)d_in[0];
    const float* Wq = (const float*)d_in[1];
    const float* Wk = (const float*)d_in[2];
    const float* Wv = (const float*)d_in[3];
    const float* Wo = (const float*)d_in[4];
    float* out = (float*)d_out;

    float *gq, *gk, *gv, *ga;
    cudaGetSymbolAddress((void**)&gq, g_Q);
    cudaGetSymbolAddress((void**)&gk, g_K);
    cudaGetSymbolAddress((void**)&gv, g_V);
    cudaGetSymbolAddress((void**)&ga, g_A);

    cudaFuncSetAttribute(gemm_bf16x3, cudaFuncAttributeMaxDynamicSharedMemorySize,
                         GEMM_SMEM);
    cudaFuncSetAttribute(attn_mma, cudaFuncAttributeMaxDynamicSharedMemorySize,
                         ATTN_SMEM);

    gemm_bf16x3<<<dim3(DM  / 128, BT / 128), 256, GEMM_SMEM>>>(x, Wq, gq, BT, DM,  DM);
    gemm_bf16x3<<<dim3(KVD / 128, BT / 128), 256, GEMM_SMEM>>>(x, Wk, gk, BT, KVD, DM);
    gemm_bf16x3<<<dim3(KVD / 128, BT / 128), 256, GEMM_SMEM>>>(x, Wv, gv, BT, KVD, DM);

    rope_table_kernel<<<(TT * 32 + 255) / 256, 256>>>();
    {
        int total = BT * (NH + NKV) * 32;
        rope_apply_kernel<<<(total + 255) / 256, 256>>>();
    }

    attn_mma<<<dim3(TT / 128, NH, BB), 256, ATTN_SMEM>>>();

    gemm_bf16x3<<<dim3(DM / 128, BT / 128), 256, GEMM_SMEM>>>(ga, Wo, out, BT, DM, DM);
}

// round 5
// speedup vs baseline: 2.4350x; 1.0636x over previous
#include <cuda_runtime.h>
#include <cuda_bf16.h>
#include <math.h>
#include <stdint.h>

#define BB  2
#define TT  2048
#define DM  2048
#define NH  32
#define NKV 8
#define DH  64
#define BT  (BB*TT)
#define KVD (NKV*DH)   /* 512 */

typedef __nv_bfloat16 bf16;

// ---------------- scratch (device globals; no allocations allowed) ----------
__device__ float g_Q[(size_t)BT * DM];     // fp32 Q pre-RoPE
__device__ float g_K[(size_t)BT * KVD];    // fp32 K pre-RoPE

__device__ bf16 g_xh[(size_t)BT * DM],  g_xl[(size_t)BT * DM];
__device__ bf16 g_Wqh[(size_t)DM * DM], g_Wql[(size_t)DM * DM];
__device__ bf16 g_Wkh[(size_t)KVD * DM], g_Wkl[(size_t)KVD * DM];
__device__ bf16 g_Wvh[(size_t)KVD * DM], g_Wvl[(size_t)KVD * DM];
__device__ bf16 g_Woh[(size_t)DM * DM], g_Wol[(size_t)DM * DM];

__device__ bf16 g_Qh[(size_t)BT * DM],  g_Ql[(size_t)BT * DM];   // roped, x0.125
__device__ bf16 g_Kh[(size_t)BT * KVD], g_Kl[(size_t)BT * KVD];  // roped
__device__ bf16 g_Vth[(size_t)BT * KVD], g_Vtl[(size_t)BT * KVD]; // (b,g,d,t)
__device__ bf16 g_Ah[(size_t)BT * DM],  g_Al[(size_t)BT * DM];   // attn out split

__device__ float g_cos[TT * 32];
__device__ float g_sin[TT * 32];

// ===================== helpers ======================
__device__ __forceinline__ uint32_t smem_u32(const void* p) {
    uint32_t a;
    asm("{ .reg .u64 t; cvta.to.shared.u64 t, %1; cvt.u32.u64 %0, t; }"
        : "=r"(a) : "l"(p));
    return a;
}

#define CP16(dst, src) \
    asm volatile("cp.async.cg.shared.global [%0], [%1], 16;" \
                 :: "r"(dst), "l"(src) : "memory")
#define CPCOMMIT() asm volatile("cp.async.commit_group;" ::: "memory")
#define CPWAIT(n)  asm volatile("cp.async.wait_group %0;" :: "n"(n) : "memory")

__device__ __forceinline__ void ldmx4(uint32_t& r0, uint32_t& r1,
                                      uint32_t& r2, uint32_t& r3, uint32_t a) {
    asm volatile("ldmatrix.sync.aligned.m8n8.x4.shared.b16 {%0,%1,%2,%3}, [%4];"
                 : "=r"(r0), "=r"(r1), "=r"(r2), "=r"(r3) : "r"(a));
}

__device__ __forceinline__ void mma16816(float* d, const uint32_t* a,
                                         const uint32_t* b) {
    asm volatile(
        "mma.sync.aligned.m16n8k16.row.col.f32.bf16.bf16.f32 "
        "{%0,%1,%2,%3},{%4,%5,%6,%7},{%8,%9},{%0,%1,%2,%3};"
        : "+f"(d[0]), "+f"(d[1]), "+f"(d[2]), "+f"(d[3])
        : "r"(a[0]), "r"(a[1]), "r"(a[2]), "r"(a[3]), "r"(b[0]), "r"(b[1]));
}

__device__ __forceinline__ void split4(float4 v, uint2& h, uint2& l) {
    bf16 hx = __float2bfloat16(v.x);
    bf16 hy = __float2bfloat16(v.y);
    bf16 hz = __float2bfloat16(v.z);
    bf16 hw = __float2bfloat16(v.w);
    float lx = v.x - __bfloat162float(hx);
    float ly = v.y - __bfloat162float(hy);
    float lz = v.z - __bfloat162float(hz);
    float lw = v.w - __bfloat162float(hw);
    __nv_bfloat162 h0 = __halves2bfloat162(hx, hy);
    __nv_bfloat162 h1 = __halves2bfloat162(hz, hw);
    __nv_bfloat162 l0 = __halves2bfloat162(__float2bfloat16(lx), __float2bfloat16(ly));
    __nv_bfloat162 l1 = __halves2bfloat162(__float2bfloat16(lz), __float2bfloat16(lw));
    h.x = *reinterpret_cast<uint32_t*>(&h0);
    h.y = *reinterpret_cast<uint32_t*>(&h1);
    l.x = *reinterpret_cast<uint32_t*>(&l0);
    l.y = *reinterpret_cast<uint32_t*>(&l1);
}

__device__ __forceinline__ uint32_t packbf(float a, float b) {
    __nv_bfloat162 t = __floats2bfloat162_rn(a, b);
    return *reinterpret_cast<uint32_t*>(&t);
}

__device__ __forceinline__ void split_store(bf16* H, bf16* L, size_t i, float v) {
    bf16 hv = __float2bfloat16(v);
    H[i] = hv;
    L[i] = __float2bfloat16(v - __bfloat162float(hv));
}

// ---------------------------------------------------------------------------
// split precompute: fp32 array -> hi/lo bf16 arrays (vectorized)
// ---------------------------------------------------------------------------
__global__ void split_kernel(const float* __restrict__ src,
                             bf16* __restrict__ h, bf16* __restrict__ l, int n4)
{
    int i = blockIdx.x * blockDim.x + threadIdx.x;
    if (i >= n4) return;
    float4 v = ((const float4*)src)[i];
    uint2 hh, ll;
    split4(v, hh, ll);
    ((uint2*)h)[i] = hh;
    ((uint2*)l)[i] = ll;
}

// ---------------------------------------------------------------------------
// GEMM on pre-split bf16 operands: C = A @ W^T, 3-term (ah*bh+ah*bl+al*bh).
// 128x128 tile, BK=32, cp.async double buffer, 8 warps.
// MODE 0: write fp32 C.  MODE 1: write V transposed split (b,g,d,t).
// ---------------------------------------------------------------------------
#define PITCH 40
#define MAT   (128 * PITCH * 2)
#define STAGE (4 * MAT)
#define GEMM_SMEM (2 * STAGE)

template<int MODE>
__global__ void __launch_bounds__(256, 1)
gemm_pre(const bf16* __restrict__ Ah, const bf16* __restrict__ Al,
         const bf16* __restrict__ Wh, const bf16* __restrict__ Wl,
         float* __restrict__ C, bf16* __restrict__ Ch, bf16* __restrict__ Cl,
         int M, int N, int K)
{
    extern __shared__ char smc[];
    const uint32_t sb = smem_u32(smc);

    const int tid  = threadIdx.x;
    const int lane = tid & 31;
    const int wid  = tid >> 5;
    const int wm = (wid & 3) * 32;
    const int wn = (wid >> 2) * 64;
    const int m0 = blockIdx.y * 128;
    const int n0 = blockIdx.x * 128;

    float acc[2][8][4];
#pragma unroll
    for (int mt = 0; mt < 2; mt++)
#pragma unroll
        for (int nt = 0; nt < 8; nt++)
#pragma unroll
            for (int j = 0; j < 4; j++) acc[mt][nt][j] = 0.f;

    const int quad = lane >> 3;
    const int arow_off = (lane & 7) + (quad & 1) * 8;
    const int acol_off = (quad >> 1) * 8;
    const int brow_off = (lane & 7) + (quad >> 1) * 8;
    const int bcol_off = (quad & 1) * 8;

    const int nch = K / 32;
    const int r_  = tid >> 2;      // 0..63 (l adds 64)
    const int q_  = tid & 3;       // 16B chunk within 32-half row

    // issue cp.async for chunk c into buffer sel
#define LOAD_CHUNK(c, sel) do {                                               \
    const uint32_t d0 = sb + (sel) * STAGE;                                   \
    _Pragma("unroll")                                                         \
    for (int l = 0; l < 2; l++) {                                             \
        int row = r_ + l * 64;                                                \
        uint32_t doff = (uint32_t)(row * PITCH + q_ * 8) * 2;                 \
        size_t soff = (size_t)(m0 + row) * K + (c) * 32 + q_ * 8;             \
        size_t woff = (size_t)(n0 + row) * K + (c) * 32 + q_ * 8;             \
        CP16(d0 + doff,           Ah + soff);                                 \
        CP16(d0 + MAT + doff,     Al + soff);                                 \
        CP16(d0 + 2 * MAT + doff, Wh + woff);                                 \
        CP16(d0 + 3 * MAT + doff, Wl + woff);                                 \
    }                                                                         \
    CPCOMMIT();                                                               \
} while (0)

    LOAD_CHUNK(0, 0);

    for (int c = 0; c < nch; c++) {
        if (c + 1 < nch) {
            LOAD_CHUNK(c + 1, (c + 1) & 1);
            CPWAIT(1);
        } else {
            CPWAIT(0);
        }
        __syncthreads();

        const uint32_t base = sb + (c & 1) * STAGE;
#pragma unroll
        for (int ks = 0; ks < 32; ks += 16) {
            uint32_t ah[2][4], al[2][4];
#pragma unroll
            for (int mt = 0; mt < 2; mt++) {
                uint32_t addr = base +
                    ((uint32_t)((wm + mt * 16 + arow_off) * PITCH + ks + acol_off) << 1);
                ldmx4(ah[mt][0], ah[mt][1], ah[mt][2], ah[mt][3], addr);
                ldmx4(al[mt][0], al[mt][1], al[mt][2], al[mt][3], addr + MAT);
            }
            uint32_t bh[8][2], bl[8][2];
#pragma unroll
            for (int np = 0; np < 4; np++) {
                uint32_t addr = base + 2 * MAT +
                    ((uint32_t)((wn + np * 16 + brow_off) * PITCH + ks + bcol_off) << 1);
                uint32_t r0, r1, r2, r3;
                ldmx4(r0, r1, r2, r3, addr);
                bh[2 * np][0] = r0; bh[2 * np][1] = r1;
                bh[2 * np + 1][0] = r2; bh[2 * np + 1][1] = r3;
                ldmx4(r0, r1, r2, r3, addr + MAT);
                bl[2 * np][0] = r0; bl[2 * np][1] = r1;
                bl[2 * np + 1][0] = r2; bl[2 * np + 1][1] = r3;
            }
#pragma unroll
            for (int mt = 0; mt < 2; mt++)
#pragma unroll
                for (int nt = 0; nt < 8; nt++) {
                    mma16816(acc[mt][nt], ah[mt], bh[nt]);
                    mma16816(acc[mt][nt], ah[mt], bl[nt]);
                    mma16816(acc[mt][nt], al[mt], bh[nt]);
                }
        }
        __syncthreads();
    }
#undef LOAD_CHUNK

    if (MODE == 0) {
#pragma unroll
        for (int mt = 0; mt < 2; mt++) {
            int row = m0 + wm + mt * 16 + (lane >> 2);
#pragma unroll
            for (int nt = 0; nt < 8; nt++) {
                int col = n0 + wn + nt * 8 + (lane & 3) * 2;
                *(float2*)(C + (size_t)row * N + col) =
                    make_float2(acc[mt][nt][0], acc[mt][nt][1]);
                *(float2*)(C + (size_t)(row + 8) * N + col) =
                    make_float2(acc[mt][nt][2], acc[mt][nt][3]);
            }
        }
    } else {
        // V transposed split store: dst[((b*NKV+g)*DH+d)*TT + t]
#pragma unroll
        for (int mt = 0; mt < 2; mt++) {
            int rowt = m0 + wm + mt * 16 + (lane >> 2);
#pragma unroll
            for (int nt = 0; nt < 8; nt++) {
                int col = n0 + wn + nt * 8 + (lane & 3) * 2;
#pragma unroll
                for (int j = 0; j < 4; j++) {
                    int r = rowt + ((j >> 1) << 3);
                    int cc = col + (j & 1);
                    int b = r >> 11, t = r & (TT - 1);
                    size_t di = (((size_t)b * NKV + (cc >> 6)) * DH + (cc & 63)) * TT + t;
                    split_store(Ch, Cl, di, acc[mt][nt][j]);
                }
            }
        }
    }
}

// ---------------------------------------------------------------------------
// RoPE
// ---------------------------------------------------------------------------
__global__ void rope_table_kernel()
{
    int idx = blockIdx.x * blockDim.x + threadIdx.x;
    if (idx >= TT * 32) return;
    int t = idx >> 5;
    int i = idx & 31;
    double inv = pow(10000.0, -(double)i / 32.0);
    double a   = (double)t * inv;
    g_cos[idx] = (float)cos(a);
    g_sin[idx] = (float)sin(a);
}

// read fp32 Q/K, rotate, split to bf16 hi/lo (Q scaled by 1/8, exact)
__global__ void rope_apply_kernel()
{
    int idx = blockIdx.x * blockDim.x + threadIdx.x;
    const int total = BT * (NH + NKV) * 32;
    if (idx >= total) return;
    int i    = idx & 31;
    int rest = idx >> 5;
    int h    = rest % (NH + NKV);
    int bt   = rest / (NH + NKV);
    int t    = bt & (TT - 1);

    float c = g_cos[t * 32 + i];
    float s = g_sin[t * 32 + i];

    if (h < NH) {
        size_t base = (size_t)bt * DM + h * DH;
        float v0 = g_Q[base + i];
        float v1 = g_Q[base + i + 32];
        float r0 = (v0 * c - v1 * s) * 0.125f;
        float r1 = (v1 * c + v0 * s) * 0.125f;
        split_store(g_Qh, g_Ql, base + i,      r0);
        split_store(g_Qh, g_Ql, base + i + 32, r1);
    } else {
        size_t base = (size_t)bt * KVD + (h - NH) * DH;
        float v0 = g_K[base + i];
        float v1 = g_K[base + i + 32];
        split_store(g_Kh, g_Kl, base + i,      v0 * c - v1 * s);
        split_store(g_Kh, g_Kl, base + i + 32, v1 * c + v0 * s);
    }
}

// ---------------------------------------------------------------------------
// Flash attention on tensor cores (pre-split bf16 operands, causal, GQA).
// ---------------------------------------------------------------------------
#define KP 72
#define MATK (128 * KP * 2)
#define VP 136
#define VOFF (2 * MATK)
#define VMAT (64 * VP * 2)
#define ATTN_SMEM (VOFF + 2 * VMAT)

__global__ void __launch_bounds__(256, 1) attn_mma()
{
    extern __shared__ char smc[];
    const uint32_t sb = smem_u32(smc);

    const int tid  = threadIdx.x;
    const int lane = tid & 31;
    const int wid  = tid >> 5;
    const int wq   = wid * 16;

    const int quad = lane >> 3;
    const int arow_off = (lane & 7) + (quad & 1) * 8;
    const int acol_off = (quad >> 1) * 8;
    const int brow_off = (lane & 7) + (quad >> 1) * 8;
    const int bcol_off = (quad & 1) * 8;

    const int q0 = (gridDim.x - 1 - blockIdx.x) * 128;
    const int h  = blockIdx.y;
    const int b  = blockIdx.z;
    const int g  = h >> 2;

    // ---- stage Q (bf16, pre-scaled) via K smem, then into registers
    {
        const bf16* Qph = g_Qh + ((size_t)b * TT + q0) * DM + h * DH;
        const bf16* Qpl = g_Ql + ((size_t)b * TT + q0) * DM + h * DH;
#pragma unroll
        for (int l = 0; l < 4; l++) {
            int idx = tid + l * 256;       // 0..1023
            int r   = idx >> 3;
            int cq  = idx & 7;
            uint32_t off = (uint32_t)(r * KP + cq * 8) * 2;
            *(uint4*)(smc + off)        = *(const uint4*)(Qph + (size_t)r * DM + cq * 8);
            *(uint4*)(smc + MATK + off) = *(const uint4*)(Qpl + (size_t)r * DM + cq * 8);
        }
    }
    __syncthreads();

    uint32_t qh[4][4], ql[4][4];
#pragma unroll
    for (int ks = 0; ks < 4; ks++) {
        uint32_t addr = sb + ((uint32_t)((wq + arow_off) * KP + ks * 16 + acol_off) << 1);
        ldmx4(qh[ks][0], qh[ks][1], qh[ks][2], qh[ks][3], addr);
        ldmx4(ql[ks][0], ql[ks][1], ql[ks][2], ql[ks][3], addr + MATK);
    }

    float oacc[8][4];
#pragma unroll
    for (int nt = 0; nt < 8; nt++)
#pragma unroll
        for (int j = 0; j < 4; j++) oacc[nt][j] = 0.f;
    float mrow0 = -1e30f, mrow1 = -1e30f, lrow0 = 0.f, lrow1 = 0.f;

    const int row0 = q0 + wq + (lane >> 2);
    const int row1 = row0 + 8;

    const bf16* Kbh = g_Kh + (size_t)b * TT * KVD + g * DH;
    const bf16* Kbl = g_Kl + (size_t)b * TT * KVD + g * DH;
    const bf16* Vbh = g_Vth + ((size_t)b * NKV + g) * DH * TT;
    const bf16* Vbl = g_Vtl + ((size_t)b * NKV + g) * DH * TT;

    for (int s0 = 0; s0 <= q0; s0 += 128) {
        __syncthreads();
        // K block: [s][d] rows (128x64 halves), V block: [d][t] rows (64x128)
#pragma unroll
        for (int l = 0; l < 4; l++) {
            int idx = tid + l * 256;       // 0..1023
            {
                int s  = idx >> 3;
                int cq = idx & 7;
                size_t gi = (size_t)(s0 + s) * KVD + cq * 8;
                uint32_t off = (uint32_t)(s * KP + cq * 8) * 2;
                *(uint4*)(smc + off)        = *(const uint4*)(Kbh + gi);
                *(uint4*)(smc + MATK + off) = *(const uint4*)(Kbl + gi);
            }
            {
                int d  = idx >> 4;
                int cq = idx & 15;
                size_t gi = (size_t)d * TT + s0 + cq * 8;
                uint32_t off = VOFF + (uint32_t)(d * VP + cq * 8) * 2;
                *(uint4*)(smc + off)        = *(const uint4*)(Vbh + gi);
                *(uint4*)(smc + VMAT + off) = *(const uint4*)(Vbl + gi);
            }
        }
        __syncthreads();

        // ---- S = Q K^T (3-term)
        float sacc[16][4];
#pragma unroll
        for (int nt = 0; nt < 16; nt++)
#pragma unroll
            for (int j = 0; j < 4; j++) sacc[nt][j] = 0.f;

#pragma unroll
        for (int np = 0; np < 8; np++) {
#pragma unroll
            for (int ks = 0; ks < 4; ks++) {
                uint32_t addr = sb +
                    ((uint32_t)((np * 16 + brow_off) * KP + ks * 16 + bcol_off) << 1);
                uint32_t h0, h1, h2, h3, l0, l1, l2, l3;
                ldmx4(h0, h1, h2, h3, addr);
                ldmx4(l0, l1, l2, l3, addr + MATK);
                uint32_t bh0[2] = {h0, h1}, bh1[2] = {h2, h3};
                uint32_t bl0[2] = {l0, l1}, bl1[2] = {l2, l3};
                mma16816(sacc[2 * np],     qh[ks], bh0);
                mma16816(sacc[2 * np],     qh[ks], bl0);
                mma16816(sacc[2 * np],     ql[ks], bh0);
                mma16816(sacc[2 * np + 1], qh[ks], bh1);
                mma16816(sacc[2 * np + 1], qh[ks], bl1);
                mma16816(sacc[2 * np + 1], ql[ks], bh1);
            }
        }

        // ---- causal mask on diagonal block
        if (s0 == q0) {
            const int cbase = s0 + (lane & 3) * 2;
#pragma unroll
            for (int nt = 0; nt < 16; nt++) {
                int c0 = cbase + nt * 8;
                if (c0     > row0) sacc[nt][0] = -1e30f;
                if (c0 + 1 > row0) sacc[nt][1] = -1e30f;
                if (c0     > row1) sacc[nt][2] = -1e30f;
                if (c0 + 1 > row1) sacc[nt][3] = -1e30f;
            }
        }

        // ---- online softmax on fragments
        float mx0 = -1e30f, mx1 = -1e30f;
#pragma unroll
        for (int nt = 0; nt < 16; nt++) {
            mx0 = fmaxf(mx0, fmaxf(sacc[nt][0], sacc[nt][1]));
            mx1 = fmaxf(mx1, fmaxf(sacc[nt][2], sacc[nt][3]));
        }
        mx0 = fmaxf(mx0, __shfl_xor_sync(0xffffffffu, mx0, 1));
        mx0 = fmaxf(mx0, __shfl_xor_sync(0xffffffffu, mx0, 2));
        mx1 = fmaxf(mx1, __shfl_xor_sync(0xffffffffu, mx1, 1));
        mx1 = fmaxf(mx1, __shfl_xor_sync(0xffffffffu, mx1, 2));

        float mnew0 = fmaxf(mrow0, mx0);
        float mnew1 = fmaxf(mrow1, mx1);
        float alpha0 = __expf(mrow0 - mnew0);
        float alpha1 = __expf(mrow1 - mnew1);

        uint32_t ph[8][4], pl[8][4];
        float rs0 = 0.f, rs1 = 0.f;
#pragma unroll
        for (int ks = 0; ks < 8; ks++) {
#pragma unroll
            for (int half = 0; half < 2; half++) {
                int nt = 2 * ks + half;
                float p0 = __expf(sacc[nt][0] - mnew0);
                float p1 = __expf(sacc[nt][1] - mnew0);
                float p2 = __expf(sacc[nt][2] - mnew1);
                float p3 = __expf(sacc[nt][3] - mnew1);
                rs0 += p0 + p1;
                rs1 += p2 + p3;
                uint32_t h01 = packbf(p0, p1);
                uint32_t h23 = packbf(p2, p3);
                __nv_bfloat162 hv01 = *reinterpret_cast<__nv_bfloat162*>(&h01);
                __nv_bfloat162 hv23 = *reinterpret_cast<__nv_bfloat162*>(&h23);
                uint32_t lo01 = packbf(p0 - __bfloat162float(hv01.x),
                                       p1 - __bfloat162float(hv01.y));
                uint32_t lo23 = packbf(p2 - __bfloat162float(hv23.x),
                                       p3 - __bfloat162float(hv23.y));
                ph[ks][2 * half]     = h01;
                ph[ks][2 * half + 1] = h23;
                pl[ks][2 * half]     = lo01;
                pl[ks][2 * half + 1] = lo23;
            }
        }
        rs0 += __shfl_xor_sync(0xffffffffu, rs0, 1);
        rs0 += __shfl_xor_sync(0xffffffffu, rs0, 2);
        rs1 += __shfl_xor_sync(0xffffffffu, rs1, 1);
        rs1 += __shfl_xor_sync(0xffffffffu, rs1, 2);

        lrow0 = lrow0 * alpha0 + rs0;
        lrow1 = lrow1 * alpha1 + rs1;
        mrow0 = mnew0;
        mrow1 = mnew1;
#pragma unroll
        for (int nt = 0; nt < 8; nt++) {
            oacc[nt][0] *= alpha0;
            oacc[nt][1] *= alpha0;
            oacc[nt][2] *= alpha1;
            oacc[nt][3] *= alpha1;
        }

        // ---- O += P V (3-term)
#pragma unroll
        for (int np = 0; np < 4; np++) {
#pragma unroll
            for (int ks = 0; ks < 8; ks++) {
                uint32_t addr = sb + VOFF +
                    ((uint32_t)((np * 16 + brow_off) * VP + ks * 16 + bcol_off) << 1);
                uint32_t h0, h1, h2, h3, l0, l1, l2, l3;
                ldmx4(h0, h1, h2, h3, addr);
                ldmx4(l0, l1, l2, l3, addr + VMAT);
                uint32_t bh0[2] = {h0, h1}, bh1[2] = {h2, h3};
                uint32_t bl0[2] = {l0, l1}, bl1[2] = {l2, l3};
                mma16816(oacc[2 * np],     ph[ks], bh0);
                mma16816(oacc[2 * np],     ph[ks], bl0);
                mma16816(oacc[2 * np],     pl[ks], bh0);
                mma16816(oacc[2 * np + 1], ph[ks], bh1);
                mma16816(oacc[2 * np + 1], ph[ks], bl1);
                mma16816(oacc[2 * np + 1], pl[ks], bh1);
            }
        }
    }

    // ---- epilogue: normalize and write split bf16 for the output GEMM
    float inv0 = 1.f / lrow0;
    float inv1 = 1.f / lrow1;
    const size_t o0 = ((size_t)b * TT + row0) * DM + h * DH + (lane & 3) * 2;
    const size_t o1 = ((size_t)b * TT + row1) * DM + h * DH + (lane & 3) * 2;
#pragma unroll
    for (int nt = 0; nt < 8; nt++) {
        float v0 = oacc[nt][0] * inv0, v1 = oacc[nt][1] * inv0;
        float v2 = oacc[nt][2] * inv1, v3 = oacc[nt][3] * inv1;
        uint32_t hp0 = packbf(v0, v1);
        uint32_t hp1 = packbf(v2, v3);
        __nv_bfloat162 hv0 = *reinterpret_cast<__nv_bfloat162*>(&hp0);
        __nv_bfloat162 hv1 = *reinterpret_cast<__nv_bfloat162*>(&hp1);
        uint32_t lp0 = packbf(v0 - __bfloat162float(hv0.x), v1 - __bfloat162float(hv0.y));
        uint32_t lp1 = packbf(v2 - __bfloat162float(hv1.x), v3 - __bfloat162float(hv1.y));
        *(uint32_t*)(g_Ah + o0 + nt * 8) = hp0;
        *(uint32_t*)(g_Al + o0 + nt * 8) = lp0;
        *(uint32_t*)(g_Ah + o1 + nt * 8) = hp1;
        *(uint32_t*)(g_Al + o1 + nt * 8) = lp1;
    }
}

// ---------------------------------------------------------------------------
extern "C" void kernel_launch(void* const* d_in, const int* in_sizes, int n_in,
                              void* d_out, int out_size)
{
    const float* x  = (const float*)d_in[0];
    const float* Wq = (const float*)d_in[1];
    const float* Wk = (const float*)d_in[2];
    const float* Wv = (const float*)d_in[3];
    const float* Wo = (const float*)d_in[4];
    float* out = (float*)d_out;

    float *gq, *gk;
    bf16 *xh, *xl, *wqh, *wql, *wkh, *wkl, *wvh, *wvl, *woh, *wol;
    bf16 *vth, *vtl, *ah, *al;
    cudaGetSymbolAddress((void**)&gq, g_Q);
    cudaGetSymbolAddress((void**)&gk, g_K);
    cudaGetSymbolAddress((void**)&xh, g_xh);   cudaGetSymbolAddress((void**)&xl, g_xl);
    cudaGetSymbolAddress((void**)&wqh, g_Wqh); cudaGetSymbolAddress((void**)&wql, g_Wql);
    cudaGetSymbolAddress((void**)&wkh, g_Wkh); cudaGetSymbolAddress((void**)&wkl, g_Wkl);
    cudaGetSymbolAddress((void**)&wvh, g_Wvh); cudaGetSymbolAddress((void**)&wvl, g_Wvl);
    cudaGetSymbolAddress((void**)&woh, g_Woh); cudaGetSymbolAddress((void**)&wol, g_Wol);
    cudaGetSymbolAddress((void**)&vth, g_Vth); cudaGetSymbolAddress((void**)&vtl, g_Vtl);
    cudaGetSymbolAddress((void**)&ah, g_Ah);   cudaGetSymbolAddress((void**)&al, g_Al);
    bf16 *qhh, *qll, *khh, *kll;
    cudaGetSymbolAddress((void**)&qhh, g_Qh);  cudaGetSymbolAddress((void**)&qll, g_Ql);
    cudaGetSymbolAddress((void**)&khh, g_Kh);  cudaGetSymbolAddress((void**)&kll, g_Kl);

    cudaFuncSetAttribute(gemm_pre<0>, cudaFuncAttributeMaxDynamicSharedMemorySize,
                         GEMM_SMEM);
    cudaFuncSetAttribute(gemm_pre<1>, cudaFuncAttributeMaxDynamicSharedMemorySize,
                         GEMM_SMEM);
    cudaFuncSetAttribute(attn_mma, cudaFuncAttributeMaxDynamicSharedMemorySize,
                         ATTN_SMEM);

    // ---- pre-split inputs and weights
    {
        int n4;
        n4 = BT * DM / 4;
        split_kernel<<<(n4 + 255) / 256, 256>>>(x, xh, xl, n4);
        n4 = DM * DM / 4;
        split_kernel<<<(n4 + 255) / 256, 256>>>(Wq, wqh, wql, n4);
        split_kernel<<<(n4 + 255) / 256, 256>>>(Wo, woh, wol, n4);
        n4 = KVD * DM / 4;
        split_kernel<<<(n4 + 255) / 256, 256>>>(Wk, wkh, wkl, n4);
        split_kernel<<<(n4 + 255) / 256, 256>>>(Wv, wvh, wvl, n4);
    }

    // ---- projections
    gemm_pre<0><<<dim3(DM / 128, BT / 128), 256, GEMM_SMEM>>>(
        xh, xl, wqh, wql, gq, nullptr, nullptr, BT, DM, DM);
    gemm_pre<0><<<dim3(KVD / 128, BT / 128), 256, GEMM_SMEM>>>(
        xh, xl, wkh, wkl, gk, nullptr, nullptr, BT, KVD, DM);
    gemm_pre<1><<<dim3(KVD / 128, BT / 128), 256, GEMM_SMEM>>>(
        xh, xl, wvh, wvl, nullptr, vth, vtl, BT, KVD, DM);

    // ---- RoPE (table + apply/split)
    rope_table_kernel<<<(TT * 32 + 255) / 256, 256>>>();
    {
        int total = BT * (NH + NKV) * 32;
        rope_apply_kernel<<<(total + 255) / 256, 256>>>();
    }

    // ---- attention
    attn_mma<<<dim3(TT / 128, NH, BB), 256, ATTN_SMEM>>>();

    // ---- output projection
    gemm_pre<0><<<dim3(DM / 128, BT / 128), 256, GEMM_SMEM>>>(
        ah, al, woh, wol, out, nullptr, nullptr, BT, DM, DM);
}

// round 6
// speedup vs baseline: 3.3878x; 1.3913x over previous
#include <cuda_runtime.h>
#include <cuda_fp16.h>
#include <math.h>
#include <stdint.h>

#define BB  2
#define TT  2048
#define DM  2048
#define NH  32
#define NKV 8
#define DH  64
#define BT  (BB*TT)
#define KVD (NKV*DH)   /* 512 */

// ---------------- scratch (device globals; no allocations allowed) ----------
__device__ float g_Q[(size_t)BT * DM];     // fp32 Q pre-RoPE (natural scale)
__device__ float g_K[(size_t)BT * KVD];    // fp32 K pre-RoPE

__device__ half g_xh[(size_t)BT * DM],  g_xl[(size_t)BT * DM];   // x * 16 split
__device__ half g_Wq[(size_t)DM * DM];                            // W * 64 single
__device__ half g_Wk[(size_t)KVD * DM];
__device__ half g_Wv[(size_t)KVD * DM];
__device__ half g_Wo[(size_t)DM * DM];

__device__ half g_Qh[(size_t)BT * DM],  g_Ql[(size_t)BT * DM];   // roped, x0.125 split
__device__ half g_Kh[(size_t)BT * KVD];                           // roped, single
__device__ half g_Vth[(size_t)BT * KVD], g_Vtl[(size_t)BT * KVD]; // (b,g,d,t) split
__device__ half g_Ah[(size_t)BT * DM],  g_Al[(size_t)BT * DM];   // attn out x16 split

__device__ float g_cos[TT * 32];
__device__ float g_sin[TT * 32];

// ===================== helpers ======================
__device__ __forceinline__ uint32_t smem_u32(const void* p) {
    uint32_t a;
    asm("{ .reg .u64 t; cvta.to.shared.u64 t, %1; cvt.u32.u64 %0, t; }"
        : "=r"(a) : "l"(p));
    return a;
}

#define CP16(dst, src) \
    asm volatile("cp.async.cg.shared.global [%0], [%1], 16;" \
                 :: "r"(dst), "l"(src) : "memory")
#define CPCOMMIT() asm volatile("cp.async.commit_group;" ::: "memory")
#define CPWAIT(n)  asm volatile("cp.async.wait_group %0;" :: "n"(n) : "memory")

__device__ __forceinline__ void ldmx4(uint32_t& r0, uint32_t& r1,
                                      uint32_t& r2, uint32_t& r3, uint32_t a) {
    asm volatile("ldmatrix.sync.aligned.m8n8.x4.shared.b16 {%0,%1,%2,%3}, [%4];"
                 : "=r"(r0), "=r"(r1), "=r"(r2), "=r"(r3) : "r"(a));
}

__device__ __forceinline__ void mma16816(float* d, const uint32_t* a,
                                         const uint32_t* b) {
    asm volatile(
        "mma.sync.aligned.m16n8k16.row.col.f32.f16.f16.f32 "
        "{%0,%1,%2,%3},{%4,%5,%6,%7},{%8,%9},{%0,%1,%2,%3};"
        : "+f"(d[0]), "+f"(d[1]), "+f"(d[2]), "+f"(d[3])
        : "r"(a[0]), "r"(a[1]), "r"(a[2]), "r"(a[3]), "r"(b[0]), "r"(b[1]));
}

__device__ __forceinline__ uint32_t packh(float a, float b) {
    __half2 t = __floats2half2_rn(a, b);
    return *reinterpret_cast<uint32_t*>(&t);
}

// split fp32 (pre-scaled) -> hi/lo fp16 pairs
__device__ __forceinline__ void split4h(float4 v, uint2& h, uint2& l) {
    half hx = __float2half_rn(v.x);
    half hy = __float2half_rn(v.y);
    half hz = __float2half_rn(v.z);
    half hw = __float2half_rn(v.w);
    h.x = packh(__half2float(hx), __half2float(hy));
    h.y = packh(__half2float(hz), __half2float(hw));
    // re-pack exactly (packh re-rounds; use components directly)
    __half2 h0 = __halves2half2(hx, hy);
    __half2 h1 = __halves2half2(hz, hw);
    h.x = *reinterpret_cast<uint32_t*>(&h0);
    h.y = *reinterpret_cast<uint32_t*>(&h1);
    l.x = packh(v.x - __half2float(hx), v.y - __half2float(hy));
    l.y = packh(v.z - __half2float(hz), v.w - __half2float(hw));
}

__device__ __forceinline__ void split_storeh(half* H, half* L, size_t i, float v) {
    half hv = __float2half_rn(v);
    H[i] = hv;
    L[i] = __float2half_rn(v - __half2float(hv));
}

// ---------------------------------------------------------------------------
// precompute kernels
// ---------------------------------------------------------------------------
__global__ void split_x_kernel(const float* __restrict__ src,
                               half* __restrict__ h, half* __restrict__ l, int n4)
{
    int i = blockIdx.x * blockDim.x + threadIdx.x;
    if (i >= n4) return;
    float4 v = ((const float4*)src)[i];
    v.x *= 16.f; v.y *= 16.f; v.z *= 16.f; v.w *= 16.f;
    uint2 hh, ll;
    split4h(v, hh, ll);
    ((uint2*)h)[i] = hh;
    ((uint2*)l)[i] = ll;
}

__global__ void conv_w_kernel(const float* __restrict__ src,
                              half* __restrict__ h, int n4)
{
    int i = blockIdx.x * blockDim.x + threadIdx.x;
    if (i >= n4) return;
    float4 v = ((const float4*)src)[i];
    __half2 a = __floats2half2_rn(v.x * 64.f, v.y * 64.f);
    __half2 b = __floats2half2_rn(v.z * 64.f, v.w * 64.f);
    uint2 o;
    o.x = *reinterpret_cast<uint32_t*>(&a);
    o.y = *reinterpret_cast<uint32_t*>(&b);
    ((uint2*)h)[i] = o;
}

// ---------------------------------------------------------------------------
// 2-term GEMM: C = (Ah+Al) @ Wh^T  (A = 16x split, W = 64x single fp16)
// 128x128 tile, BK=32, cp.async double buffer, 8 warps. Output scale 2^-10.
// ---------------------------------------------------------------------------
#define PITCH 40                 /* halves per row (32 data + 8 pad) */
#define MAT2  (128 * PITCH * 2)  /* 10240 B per matrix */
#define STAGE2 (3 * MAT2)        /* 30720 B */
#define GEMM_SMEM (2 * STAGE2)   /* 61440 B */
#define OUT_SCALE (1.f / 1024.f)

__device__ __forceinline__ void gemm2_mainloop(
    const half* __restrict__ Ah, const half* __restrict__ Al,
    const half* __restrict__ Wh, int K, int m0, int n0,
    char* smc, float acc[2][8][4])
{
    const uint32_t sb = smem_u32(smc);
    const int tid  = threadIdx.x;
    const int lane = tid & 31;
    const int wid  = tid >> 5;
    const int wm = (wid & 3) * 32;
    const int wn = (wid >> 2) * 64;

    const int quad = lane >> 3;
    const int arow_off = (lane & 7) + (quad & 1) * 8;
    const int acol_off = (quad >> 1) * 8;
    const int brow_off = (lane & 7) + (quad >> 1) * 8;
    const int bcol_off = (quad & 1) * 8;

    const int nch = K / 32;
    const int r_  = tid >> 2;      // 0..63 (l adds 64)
    const int q_  = tid & 3;       // 16B chunk within 32-half row

#define LOAD2(c, sel) do {                                                    \
    const uint32_t d0 = sb + (sel) * STAGE2;                                  \
    _Pragma("unroll")                                                         \
    for (int l = 0; l < 2; l++) {                                             \
        int row = r_ + l * 64;                                                \
        uint32_t doff = (uint32_t)(row * PITCH + q_ * 8) * 2;                 \
        size_t aoff = (size_t)(m0 + row) * K + (c) * 32 + q_ * 8;             \
        size_t woff = (size_t)(n0 + row) * K + (c) * 32 + q_ * 8;             \
        CP16(d0 + doff,            Ah + aoff);                                \
        CP16(d0 + MAT2 + doff,     Al + aoff);                                \
        CP16(d0 + 2 * MAT2 + doff, Wh + woff);                                \
    }                                                                         \
    CPCOMMIT();                                                               \
} while (0)

    LOAD2(0, 0);

    for (int c = 0; c < nch; c++) {
        if (c + 1 < nch) {
            LOAD2(c + 1, (c + 1) & 1);
            CPWAIT(1);
        } else {
            CPWAIT(0);
        }
        __syncthreads();

        const uint32_t base = sb + (c & 1) * STAGE2;
#pragma unroll
        for (int ks = 0; ks < 32; ks += 16) {
            uint32_t ah[2][4], al[2][4];
#pragma unroll
            for (int mt = 0; mt < 2; mt++) {
                uint32_t addr = base +
                    ((uint32_t)((wm + mt * 16 + arow_off) * PITCH + ks + acol_off) << 1);
                ldmx4(ah[mt][0], ah[mt][1], ah[mt][2], ah[mt][3], addr);
                ldmx4(al[mt][0], al[mt][1], al[mt][2], al[mt][3], addr + MAT2);
            }
            uint32_t bh[8][2];
#pragma unroll
            for (int np = 0; np < 4; np++) {
                uint32_t addr = base + 2 * MAT2 +
                    ((uint32_t)((wn + np * 16 + brow_off) * PITCH + ks + bcol_off) << 1);
                uint32_t r0, r1, r2, r3;
                ldmx4(r0, r1, r2, r3, addr);
                bh[2 * np][0] = r0; bh[2 * np][1] = r1;
                bh[2 * np + 1][0] = r2; bh[2 * np + 1][1] = r3;
            }
#pragma unroll
            for (int mt = 0; mt < 2; mt++)
#pragma unroll
                for (int nt = 0; nt < 8; nt++) {
                    mma16816(acc[mt][nt], ah[mt], bh[nt]);
                    mma16816(acc[mt][nt], al[mt], bh[nt]);
                }
        }
        __syncthreads();
    }
#undef LOAD2
}

// fp32 output variant (Q, K projections and final O projection)
__global__ void __launch_bounds__(256, 1)
gemm2_f32(const half* __restrict__ Ah, const half* __restrict__ Al,
          const half* __restrict__ Wh, float* __restrict__ C, int N, int K)
{
    extern __shared__ char smc[];
    const int m0 = blockIdx.y * 128;
    const int n0 = blockIdx.x * 128;
    float acc[2][8][4];
#pragma unroll
    for (int mt = 0; mt < 2; mt++)
#pragma unroll
        for (int nt = 0; nt < 8; nt++)
#pragma unroll
            for (int j = 0; j < 4; j++) acc[mt][nt][j] = 0.f;

    gemm2_mainloop(Ah, Al, Wh, K, m0, n0, smc, acc);

    const int lane = threadIdx.x & 31;
    const int wid  = threadIdx.x >> 5;
    const int wm = (wid & 3) * 32;
    const int wn = (wid >> 2) * 64;
#pragma unroll
    for (int mt = 0; mt < 2; mt++) {
        int row = m0 + wm + mt * 16 + (lane >> 2);
#pragma unroll
        for (int nt = 0; nt < 8; nt++) {
            int col = n0 + wn + nt * 8 + (lane & 3) * 2;
            *(float2*)(C + (size_t)row * N + col) =
                make_float2(acc[mt][nt][0] * OUT_SCALE, acc[mt][nt][1] * OUT_SCALE);
            *(float2*)(C + (size_t)(row + 8) * N + col) =
                make_float2(acc[mt][nt][2] * OUT_SCALE, acc[mt][nt][3] * OUT_SCALE);
        }
    }
}

// V variant: write transposed split (b,g,d,t)
__global__ void __launch_bounds__(256, 1)
gemm2_vt(const half* __restrict__ Ah, const half* __restrict__ Al,
         const half* __restrict__ Wh, half* __restrict__ Ch,
         half* __restrict__ Cl, int K)
{
    extern __shared__ char smc[];
    const int m0 = blockIdx.y * 128;
    const int n0 = blockIdx.x * 128;
    float acc[2][8][4];
#pragma unroll
    for (int mt = 0; mt < 2; mt++)
#pragma unroll
        for (int nt = 0; nt < 8; nt++)
#pragma unroll
            for (int j = 0; j < 4; j++) acc[mt][nt][j] = 0.f;

    gemm2_mainloop(Ah, Al, Wh, K, m0, n0, smc, acc);

    const int lane = threadIdx.x & 31;
    const int wid  = threadIdx.x >> 5;
    const int wm = (wid & 3) * 32;
    const int wn = (wid >> 2) * 64;
#pragma unroll
    for (int mt = 0; mt < 2; mt++) {
        int rowt = m0 + wm + mt * 16 + (lane >> 2);
#pragma unroll
        for (int nt = 0; nt < 8; nt++) {
            int col = n0 + wn + nt * 8 + (lane & 3) * 2;
#pragma unroll
            for (int j = 0; j < 4; j++) {
                int r = rowt + ((j >> 1) << 3);
                int cc = col + (j & 1);
                int b = r >> 11, t = r & (TT - 1);
                size_t di = (((size_t)b * NKV + (cc >> 6)) * DH + (cc & 63)) * TT + t;
                split_storeh(Ch, Cl, di, acc[mt][nt][j] * OUT_SCALE);
            }
        }
    }
}

// ---------------------------------------------------------------------------
// RoPE
// ---------------------------------------------------------------------------
__global__ void rope_table_kernel()
{
    int idx = blockIdx.x * blockDim.x + threadIdx.x;
    if (idx >= TT * 32) return;
    int t = idx >> 5;
    int i = idx & 31;
    double inv = pow(10000.0, -(double)i / 32.0);
    double a   = (double)t * inv;
    g_cos[idx] = (float)cos(a);
    g_sin[idx] = (float)sin(a);
}

// Q: rotate, x0.125, split fp16. K: rotate, single fp16.
__global__ void rope_apply_kernel()
{
    int idx = blockIdx.x * blockDim.x + threadIdx.x;
    const int total = BT * (NH + NKV) * 32;
    if (idx >= total) return;
    int i    = idx & 31;
    int rest = idx >> 5;
    int h    = rest % (NH + NKV);
    int bt   = rest / (NH + NKV);
    int t    = bt & (TT - 1);

    float c = g_cos[t * 32 + i];
    float s = g_sin[t * 32 + i];

    if (h < NH) {
        size_t base = (size_t)bt * DM + h * DH;
        float v0 = g_Q[base + i];
        float v1 = g_Q[base + i + 32];
        split_storeh(g_Qh, g_Ql, base + i,      (v0 * c - v1 * s) * 0.125f);
        split_storeh(g_Qh, g_Ql, base + i + 32, (v1 * c + v0 * s) * 0.125f);
    } else {
        size_t base = (size_t)bt * KVD + (h - NH) * DH;
        float v0 = g_K[base + i];
        float v1 = g_K[base + i + 32];
        g_Kh[base + i]      = __float2half_rn(v0 * c - v1 * s);
        g_Kh[base + i + 32] = __float2half_rn(v1 * c + v0 * s);
    }
}

// ---------------------------------------------------------------------------
// Flash attention: S = (qh+ql)*kh (2-term), PV = ph*(vh+vl) (2-term).
// smem: Kh[128][KP] at 0; Vh[64][VP] at VOFF; Vl at VOFF+VMAT.
// Q staged: Qh via K area, Ql via V area (before mainloop).
// ---------------------------------------------------------------------------
#define KP 72
#define MATK (128 * KP * 2)          /* 18432 */
#define VP 136
#define VOFF MATK                    /* 18432 */
#define VMAT (64 * VP * 2)           /* 17408 */
#define ATTN_SMEM (VOFF + 2 * VMAT)  /* 53248 */

__global__ void __launch_bounds__(256, 1) attn_mma()
{
    extern __shared__ char smc[];
    const uint32_t sb = smem_u32(smc);

    const int tid  = threadIdx.x;
    const int lane = tid & 31;
    const int wid  = tid >> 5;
    const int wq   = wid * 16;

    const int quad = lane >> 3;
    const int arow_off = (lane & 7) + (quad & 1) * 8;
    const int acol_off = (quad >> 1) * 8;
    const int brow_off = (lane & 7) + (quad >> 1) * 8;
    const int bcol_off = (quad & 1) * 8;

    const int q0 = (gridDim.x - 1 - blockIdx.x) * 128;
    const int h  = blockIdx.y;
    const int b  = blockIdx.z;
    const int g  = h >> 2;

    // ---- stage Q: hi via K area, lo via V area
    {
        const half* Qph = g_Qh + ((size_t)b * TT + q0) * DM + h * DH;
        const half* Qpl = g_Ql + ((size_t)b * TT + q0) * DM + h * DH;
#pragma unroll
        for (int l = 0; l < 4; l++) {
            int idx = tid + l * 256;       // 0..1023
            int r   = idx >> 3;
            int cq  = idx & 7;
            uint32_t off = (uint32_t)(r * KP + cq * 8) * 2;
            *(uint4*)(smc + off)        = *(const uint4*)(Qph + (size_t)r * DM + cq * 8);
            *(uint4*)(smc + VOFF + off) = *(const uint4*)(Qpl + (size_t)r * DM + cq * 8);
        }
    }
    __syncthreads();

    uint32_t qh[4][4], ql[4][4];
#pragma unroll
    for (int ks = 0; ks < 4; ks++) {
        uint32_t addr = sb + ((uint32_t)((wq + arow_off) * KP + ks * 16 + acol_off) << 1);
        ldmx4(qh[ks][0], qh[ks][1], qh[ks][2], qh[ks][3], addr);
        ldmx4(ql[ks][0], ql[ks][1], ql[ks][2], ql[ks][3], addr + VOFF);
    }

    float oacc[8][4];
#pragma unroll
    for (int nt = 0; nt < 8; nt++)
#pragma unroll
        for (int j = 0; j < 4; j++) oacc[nt][j] = 0.f;
    float mrow0 = -1e30f, mrow1 = -1e30f, lrow0 = 0.f, lrow1 = 0.f;

    const int row0 = q0 + wq + (lane >> 2);
    const int row1 = row0 + 8;

    const half* Kb  = g_Kh  + (size_t)b * TT * KVD + g * DH;
    const half* Vbh = g_Vth + ((size_t)b * NKV + g) * DH * TT;
    const half* Vbl = g_Vtl + ((size_t)b * NKV + g) * DH * TT;

    for (int s0 = 0; s0 <= q0; s0 += 128) {
        __syncthreads();
#pragma unroll
        for (int l = 0; l < 4; l++) {
            int idx = tid + l * 256;       // 0..1023
            {
                int s  = idx >> 3;
                int cq = idx & 7;
                size_t gi = (size_t)(s0 + s) * KVD + cq * 8;
                *(uint4*)(smc + (uint32_t)(s * KP + cq * 8) * 2) =
                    *(const uint4*)(Kb + gi);
            }
            {
                int d  = idx >> 4;
                int cq = idx & 15;
                size_t gi = (size_t)d * TT + s0 + cq * 8;
                uint32_t off = VOFF + (uint32_t)(d * VP + cq * 8) * 2;
                *(uint4*)(smc + off)        = *(const uint4*)(Vbh + gi);
                *(uint4*)(smc + VMAT + off) = *(const uint4*)(Vbl + gi);
            }
        }
        __syncthreads();

        // ---- S = (qh+ql) K^T (2-term)
        float sacc[16][4];
#pragma unroll
        for (int nt = 0; nt < 16; nt++)
#pragma unroll
            for (int j = 0; j < 4; j++) sacc[nt][j] = 0.f;

#pragma unroll
        for (int np = 0; np < 8; np++) {
#pragma unroll
            for (int ks = 0; ks < 4; ks++) {
                uint32_t addr = sb +
                    ((uint32_t)((np * 16 + brow_off) * KP + ks * 16 + bcol_off) << 1);
                uint32_t h0, h1, h2, h3;
                ldmx4(h0, h1, h2, h3, addr);
                uint32_t bh0[2] = {h0, h1}, bh1[2] = {h2, h3};
                mma16816(sacc[2 * np],     qh[ks], bh0);
                mma16816(sacc[2 * np],     ql[ks], bh0);
                mma16816(sacc[2 * np + 1], qh[ks], bh1);
                mma16816(sacc[2 * np + 1], ql[ks], bh1);
            }
        }

        // ---- causal mask on diagonal block
        if (s0 == q0) {
            const int cbase = s0 + (lane & 3) * 2;
#pragma unroll
            for (int nt = 0; nt < 16; nt++) {
                int c0 = cbase + nt * 8;
                if (c0     > row0) sacc[nt][0] = -1e30f;
                if (c0 + 1 > row0) sacc[nt][1] = -1e30f;
                if (c0     > row1) sacc[nt][2] = -1e30f;
                if (c0 + 1 > row1) sacc[nt][3] = -1e30f;
            }
        }

        // ---- online softmax
        float mx0 = -1e30f, mx1 = -1e30f;
#pragma unroll
        for (int nt = 0; nt < 16; nt++) {
            mx0 = fmaxf(mx0, fmaxf(sacc[nt][0], sacc[nt][1]));
            mx1 = fmaxf(mx1, fmaxf(sacc[nt][2], sacc[nt][3]));
        }
        mx0 = fmaxf(mx0, __shfl_xor_sync(0xffffffffu, mx0, 1));
        mx0 = fmaxf(mx0, __shfl_xor_sync(0xffffffffu, mx0, 2));
        mx1 = fmaxf(mx1, __shfl_xor_sync(0xffffffffu, mx1, 1));
        mx1 = fmaxf(mx1, __shfl_xor_sync(0xffffffffu, mx1, 2));

        float mnew0 = fmaxf(mrow0, mx0);
        float mnew1 = fmaxf(mrow1, mx1);
        float alpha0 = __expf(mrow0 - mnew0);
        float alpha1 = __expf(mrow1 - mnew1);

        uint32_t ph[8][4];
        float rs0 = 0.f, rs1 = 0.f;
#pragma unroll
        for (int ks = 0; ks < 8; ks++) {
#pragma unroll
            for (int half_ = 0; half_ < 2; half_++) {
                int nt = 2 * ks + half_;
                float p0 = __expf(sacc[nt][0] - mnew0);
                float p1 = __expf(sacc[nt][1] - mnew0);
                float p2 = __expf(sacc[nt][2] - mnew1);
                float p3 = __expf(sacc[nt][3] - mnew1);
                rs0 += p0 + p1;
                rs1 += p2 + p3;
                ph[ks][2 * half_]     = packh(p0, p1);
                ph[ks][2 * half_ + 1] = packh(p2, p3);
            }
        }
        rs0 += __shfl_xor_sync(0xffffffffu, rs0, 1);
        rs0 += __shfl_xor_sync(0xffffffffu, rs0, 2);
        rs1 += __shfl_xor_sync(0xffffffffu, rs1, 1);
        rs1 += __shfl_xor_sync(0xffffffffu, rs1, 2);

        lrow0 = lrow0 * alpha0 + rs0;
        lrow1 = lrow1 * alpha1 + rs1;
        mrow0 = mnew0;
        mrow1 = mnew1;
#pragma unroll
        for (int nt = 0; nt < 8; nt++) {
            oacc[nt][0] *= alpha0;
            oacc[nt][1] *= alpha0;
            oacc[nt][2] *= alpha1;
            oacc[nt][3] *= alpha1;
        }

        // ---- O += P (Vh+Vl) (2-term)
#pragma unroll
        for (int np = 0; np < 4; np++) {
#pragma unroll
            for (int ks = 0; ks < 8; ks++) {
                uint32_t addr = sb + VOFF +
                    ((uint32_t)((np * 16 + brow_off) * VP + ks * 16 + bcol_off) << 1);
                uint32_t h0, h1, h2, h3, l0, l1, l2, l3;
                ldmx4(h0, h1, h2, h3, addr);
                ldmx4(l0, l1, l2, l3, addr + VMAT);
                uint32_t bh0[2] = {h0, h1}, bh1[2] = {h2, h3};
                uint32_t bl0[2] = {l0, l1}, bl1[2] = {l2, l3};
                mma16816(oacc[2 * np],     ph[ks], bh0);
                mma16816(oacc[2 * np],     ph[ks], bl0);
                mma16816(oacc[2 * np + 1], ph[ks], bh1);
                mma16816(oacc[2 * np + 1], ph[ks], bl1);
            }
        }
    }

    // ---- epilogue: normalize, x16, split fp16 for the Wo GEMM
    float inv0 = 16.f / lrow0;
    float inv1 = 16.f / lrow1;
    const size_t o0 = ((size_t)b * TT + row0) * DM + h * DH + (lane & 3) * 2;
    const size_t o1 = ((size_t)b * TT + row1) * DM + h * DH + (lane & 3) * 2;
#pragma unroll
    for (int nt = 0; nt < 8; nt++) {
        float v0 = oacc[nt][0] * inv0, v1 = oacc[nt][1] * inv0;
        float v2 = oacc[nt][2] * inv1, v3 = oacc[nt][3] * inv1;
        half h0 = __float2half_rn(v0), h1 = __float2half_rn(v1);
        half h2 = __float2half_rn(v2), h3 = __float2half_rn(v3);
        __half2 hp0 = __halves2half2(h0, h1);
        __half2 hp1 = __halves2half2(h2, h3);
        *(uint32_t*)(g_Ah + o0 + nt * 8) = *reinterpret_cast<uint32_t*>(&hp0);
        *(uint32_t*)(g_Ah + o1 + nt * 8) = *reinterpret_cast<uint32_t*>(&hp1);
        *(uint32_t*)(g_Al + o0 + nt * 8) =
            packh(v0 - __half2float(h0), v1 - __half2float(h1));
        *(uint32_t*)(g_Al + o1 + nt * 8) =
            packh(v2 - __half2float(h2), v3 - __half2float(h3));
    }
}

// ---------------------------------------------------------------------------
extern "C" void kernel_launch(void* const* d_in, const int* in_sizes, int n_in,
                              void* d_out, int out_size)
{
    const float* x  = (const float*)d_in[0];
    const float* Wq = (const float*)d_in[1];
    const float* Wk = (const float*)d_in[2];
    const float* Wv = (const float*)d_in[3];
    const float* Wo = (const float*)d_in[4];
    float* out = (float*)d_out;

    float *gq, *gk;
    half *xh, *xl, *wq, *wk, *wv, *wo, *vth, *vtl, *ah, *al;
    cudaGetSymbolAddress((void**)&gq, g_Q);
    cudaGetSymbolAddress((void**)&gk, g_K);
    cudaGetSymbolAddress((void**)&xh, g_xh);   cudaGetSymbolAddress((void**)&xl, g_xl);
    cudaGetSymbolAddress((void**)&wq, g_Wq);   cudaGetSymbolAddress((void**)&wk, g_Wk);
    cudaGetSymbolAddress((void**)&wv, g_Wv);   cudaGetSymbolAddress((void**)&wo, g_Wo);
    cudaGetSymbolAddress((void**)&vth, g_Vth); cudaGetSymbolAddress((void**)&vtl, g_Vtl);
    cudaGetSymbolAddress((void**)&ah, g_Ah);   cudaGetSymbolAddress((void**)&al, g_Al);

    cudaFuncSetAttribute(gemm2_f32, cudaFuncAttributeMaxDynamicSharedMemorySize,
                         GEMM_SMEM);
    cudaFuncSetAttribute(gemm2_vt, cudaFuncAttributeMaxDynamicSharedMemorySize,
                         GEMM_SMEM);
    cudaFuncSetAttribute(attn_mma, cudaFuncAttributeMaxDynamicSharedMemorySize,
                         ATTN_SMEM);

    // ---- precompute: split x (x16), convert weights (x64)
    {
        int n4 = BT * DM / 4;
        split_x_kernel<<<(n4 + 255) / 256, 256>>>(x, xh, xl, n4);
        n4 = DM * DM / 4;
        conv_w_kernel<<<(n4 + 255) / 256, 256>>>(Wq, wq, n4);
        conv_w_kernel<<<(n4 + 255) / 256, 256>>>(Wo, wo, n4);
        n4 = KVD * DM / 4;
        conv_w_kernel<<<(n4 + 255) / 256, 256>>>(Wk, wk, n4);
        conv_w_kernel<<<(n4 + 255) / 256, 256>>>(Wv, wv, n4);
    }

    // ---- projections
    gemm2_f32<<<dim3(DM / 128, BT / 128), 256, GEMM_SMEM>>>(xh, xl, wq, gq, DM, DM);
    gemm2_f32<<<dim3(KVD / 128, BT / 128), 256, GEMM_SMEM>>>(xh, xl, wk, gk, KVD, DM);
    gemm2_vt<<<dim3(KVD / 128, BT / 128), 256, GEMM_SMEM>>>(xh, xl, wv, vth, vtl, DM);

    // ---- RoPE
    rope_table_kernel<<<(TT * 32 + 255) / 256, 256>>>();
    {
        int total = BT * (NH + NKV) * 32;
        rope_apply_kernel<<<(total + 255) / 256, 256>>>();
    }

    // ---- attention
    attn_mma<<<dim3(TT / 128, NH, BB), 256, ATTN_SMEM>>>();

    // ---- output projection
    gemm2_f32<<<dim3(DM / 128, BT / 128), 256, GEMM_SMEM>>>(ah, al, wo, out, DM, DM);
}

// round 8
// speedup vs baseline: 3.4814x; 1.0276x over previous
#include <cuda_runtime.h>
#include <cuda_fp16.h>
#include <math.h>
#include <stdint.h>

#define BB  2
#define TT  2048
#define DM  2048
#define NH  32
#define NKV 8
#define DH  64
#define BT  (BB*TT)
#define KVD (NKV*DH)   /* 512 */

#define S_X    4096.f          /* 2^12 */
#define S_W    262144.f        /* 2^18 */
#define INV_SC (1.f / 1073741824.f)   /* 2^-30 */

// ---------------- scratch (device globals; no allocations allowed) ----------
__device__ float g_Q[(size_t)BT * DM];     // fp32 Q pre-RoPE
__device__ float g_K[(size_t)BT * KVD];    // fp32 K pre-RoPE

__device__ int8_t g_x8h[(size_t)BT * DM],  g_x8l[(size_t)BT * DM];
__device__ int8_t g_Wq8h[(size_t)DM * DM],  g_Wq8l[(size_t)DM * DM];
__device__ int8_t g_Wk8h[(size_t)KVD * DM], g_Wk8l[(size_t)KVD * DM];
__device__ int8_t g_Wv8h[(size_t)KVD * DM], g_Wv8l[(size_t)KVD * DM];

__device__ half g_Wo[(size_t)DM * DM];                            // Wo * 64 single
__device__ half g_Ah[(size_t)BT * DM],  g_Al[(size_t)BT * DM];   // attn out x16 split

__device__ half g_Qh[(size_t)BT * DM],  g_Ql[(size_t)BT * DM];   // roped, x0.125 split
__device__ half g_Kh[(size_t)BT * KVD];                           // roped, single
__device__ half g_Vth[(size_t)BT * KVD], g_Vtl[(size_t)BT * KVD]; // (b,g,d,t) split

__device__ float g_cos[TT * 32];
__device__ float g_sin[TT * 32];

// ===================== helpers ======================
__device__ __forceinline__ uint32_t smem_u32(const void* p) {
    uint32_t a;
    asm("{ .reg .u64 t; cvta.to.shared.u64 t, %1; cvt.u32.u64 %0, t; }"
        : "=r"(a) : "l"(p));
    return a;
}

#define CP16(dst, src) \
    asm volatile("cp.async.cg.shared.global [%0], [%1], 16;" \
                 :: "r"(dst), "l"(src) : "memory")
#define CPCOMMIT() asm volatile("cp.async.commit_group;" ::: "memory")
#define CPWAIT(n)  asm volatile("cp.async.wait_group %0;" :: "n"(n) : "memory")

__device__ __forceinline__ void ldmx4(uint32_t& r0, uint32_t& r1,
                                      uint32_t& r2, uint32_t& r3, uint32_t a) {
    asm volatile("ldmatrix.sync.aligned.m8n8.x4.shared.b16 {%0,%1,%2,%3}, [%4];"
                 : "=r"(r0), "=r"(r1), "=r"(r2), "=r"(r3) : "r"(a));
}

__device__ __forceinline__ void mma16816(float* d, const uint32_t* a,
                                         const uint32_t* b) {
    asm volatile(
        "mma.sync.aligned.m16n8k16.row.col.f32.f16.f16.f32 "
        "{%0,%1,%2,%3},{%4,%5,%6,%7},{%8,%9},{%0,%1,%2,%3};"
        : "+f"(d[0]), "+f"(d[1]), "+f"(d[2]), "+f"(d[3])
        : "r"(a[0]), "r"(a[1]), "r"(a[2]), "r"(a[3]), "r"(b[0]), "r"(b[1]));
}

__device__ __forceinline__ void mma_s8(int* d, const uint32_t* a,
                                       const uint32_t* b) {
    asm volatile(
        "mma.sync.aligned.m16n8k32.row.col.s32.s8.s8.s32 "
        "{%0,%1,%2,%3},{%4,%5,%6,%7},{%8,%9},{%0,%1,%2,%3};"
        : "+r"(d[0]), "+r"(d[1]), "+r"(d[2]), "+r"(d[3])
        : "r"(a[0]), "r"(a[1]), "r"(a[2]), "r"(a[3]), "r"(b[0]), "r"(b[1]));
}

__device__ __forceinline__ uint32_t packh(float a, float b) {
    __half2 t = __floats2half2_rn(a, b);
    return *reinterpret_cast<uint32_t*>(&t);
}

__device__ __forceinline__ void split_storeh(half* H, half* L, size_t i, float v) {
    half hv = __float2half_rn(v);
    H[i] = hv;
    L[i] = __float2half_rn(v - __half2float(hv));
}

// 16-bit fixed point -> two int8 digits (hi*256 + lo == q, exact)
__device__ __forceinline__ void qsplit(float v, float S, int8_t& hi, int8_t& lo) {
    int q = __float2int_rn(v * S);
    q = max(-32512, min(32512, q));
    int l = ((q + 128) & 255) - 128;
    hi = (int8_t)((q - l) >> 8);
    lo = (int8_t)l;
}

// ---------------------------------------------------------------------------
// precompute kernels
// ---------------------------------------------------------------------------
__global__ void quant8_kernel(const float* __restrict__ src,
                              int8_t* __restrict__ h, int8_t* __restrict__ l,
                              float S, int n4)
{
    int i = blockIdx.x * blockDim.x + threadIdx.x;
    if (i >= n4) return;
    float4 v = ((const float4*)src)[i];
    int8_t h0, h1, h2, h3, l0, l1, l2, l3;
    qsplit(v.x, S, h0, l0);
    qsplit(v.y, S, h1, l1);
    qsplit(v.z, S, h2, l2);
    qsplit(v.w, S, h3, l3);
    ((char4*)h)[i] = make_char4(h0, h1, h2, h3);
    ((char4*)l)[i] = make_char4(l0, l1, l2, l3);
}

__global__ void conv_w_kernel(const float* __restrict__ src,
                              half* __restrict__ h, int n4)
{
    int i = blockIdx.x * blockDim.x + threadIdx.x;
    if (i >= n4) return;
    float4 v = ((const float4*)src)[i];
    __half2 a = __floats2half2_rn(v.x * 64.f, v.y * 64.f);
    __half2 b = __floats2half2_rn(v.z * 64.f, v.w * 64.f);
    uint2 o;
    o.x = *reinterpret_cast<uint32_t*>(&a);
    o.y = *reinterpret_cast<uint32_t*>(&b);
    ((uint2*)h)[i] = o;
}

// ---------------------------------------------------------------------------
// int8 2-digit GEMM (QKV projections): HH*2^16 + (HL+LH)*2^8, LL dropped.
// ---------------------------------------------------------------------------
#define PI8  48
#define MAT8 (128 * PI8)        /* 6144 B */
#define STG8 (4 * MAT8)         /* 24576 B */
#define GEMM8_SMEM (2 * STG8)   /* 49152 B */

__device__ __forceinline__ void gemm8_mainloop(
    const int8_t* __restrict__ Ah, const int8_t* __restrict__ Al,
    const int8_t* __restrict__ Wh, const int8_t* __restrict__ Wl,
    int K, int m0, int n0, char* smc, int hh[2][8][4], int mid[2][8][4])
{
    const uint32_t sb = smem_u32(smc);
    const int tid  = threadIdx.x;
    const int lane = tid & 31;
    const int wid  = tid >> 5;
    const int wm = (wid & 3) * 32;
    const int wn = (wid >> 2) * 64;

    const int quad  = lane >> 3;
    const int arow  = (lane & 7) + (quad & 1) * 8;
    const int acolB = (quad >> 1) * 16;
    const int brow  = (lane & 7) + (quad >> 1) * 8;
    const int bcolB = (quad & 1) * 16;

    const int row = tid >> 1;
    const int cc  = tid & 1;
    const int nch = K / 32;

#define L8(c, sel) do {                                                       \
    uint32_t d0 = sb + (sel) * STG8 + (uint32_t)(row * PI8 + cc * 16);        \
    size_t ao = (size_t)(m0 + row) * K + (size_t)(c) * 32 + cc * 16;          \
    size_t wo = (size_t)(n0 + row) * K + (size_t)(c) * 32 + cc * 16;          \
    CP16(d0,            Ah + ao);                                             \
    CP16(d0 + MAT8,     Al + ao);                                             \
    CP16(d0 + 2 * MAT8, Wh + wo);                                             \
    CP16(d0 + 3 * MAT8, Wl + wo);                                             \
    CPCOMMIT();                                                               \
} while (0)

    L8(0, 0);

    for (int c = 0; c < nch; c++) {
        if (c + 1 < nch) {
            L8(c + 1, (c + 1) & 1);
            CPWAIT(1);
        } else {
            CPWAIT(0);
        }
        __syncthreads();

        const uint32_t base = sb + (c & 1) * STG8;

        uint32_t ahi[2][4], alo[2][4];
#pragma unroll
        for (int mt = 0; mt < 2; mt++) {
            uint32_t addr = base + (uint32_t)((wm + mt * 16 + arow) * PI8 + acolB);
            ldmx4(ahi[mt][0], ahi[mt][1], ahi[mt][2], ahi[mt][3], addr);
            ldmx4(alo[mt][0], alo[mt][1], alo[mt][2], alo[mt][3], addr + MAT8);
        }
#pragma unroll
        for (int np = 0; np < 4; np++) {
            uint32_t baddr = base + 2 * MAT8 +
                             (uint32_t)((wn + np * 16 + brow) * PI8 + bcolB);
            uint32_t bh[4], bl[4];
            ldmx4(bh[0], bh[1], bh[2], bh[3], baddr);
            ldmx4(bl[0], bl[1], bl[2], bl[3], baddr + MAT8);
            uint32_t b0h[2] = {bh[0], bh[1]}, b1h[2] = {bh[2], bh[3]};
            uint32_t b0l[2] = {bl[0], bl[1]}, b1l[2] = {bl[2], bl[3]};
#pragma unroll
            for (int mt = 0; mt < 2; mt++) {
                mma_s8(hh[mt][2 * np],      ahi[mt], b0h);
                mma_s8(hh[mt][2 * np + 1],  ahi[mt], b1h);
                mma_s8(mid[mt][2 * np],     ahi[mt], b0l);
                mma_s8(mid[mt][2 * np + 1], ahi[mt], b1l);
                mma_s8(mid[mt][2 * np],     alo[mt], b0h);
                mma_s8(mid[mt][2 * np + 1], alo[mt], b1h);
            }
        }
        __syncthreads();
    }
#undef L8
}

__device__ __forceinline__ float comb8(int hh, int mid) {
    return fmaf((float)hh, 65536.f, (float)mid * 256.f) * INV_SC;
}

// fp32-output variant (Q, K projections)
__global__ void __launch_bounds__(256, 1)
gemm8_f32(const int8_t* __restrict__ Ah, const int8_t* __restrict__ Al,
          const int8_t* __restrict__ Wh, const int8_t* __restrict__ Wl,
          float* __restrict__ C, int N, int K)
{
    extern __shared__ char smc[];
    const int m0 = blockIdx.y * 128;
    const int n0 = blockIdx.x * 128;
    int hh[2][8][4], mid[2][8][4];
#pragma unroll
    for (int mt = 0; mt < 2; mt++)
#pragma unroll
        for (int nt = 0; nt < 8; nt++)
#pragma unroll
            for (int j = 0; j < 4; j++) { hh[mt][nt][j] = 0; mid[mt][nt][j] = 0; }

    gemm8_mainloop(Ah, Al, Wh, Wl, K, m0, n0, smc, hh, mid);

    const int lane = threadIdx.x & 31;
    const int wid  = threadIdx.x >> 5;
    const int wm = (wid & 3) * 32;
    const int wn = (wid >> 2) * 64;
#pragma unroll
    for (int mt = 0; mt < 2; mt++) {
        int row = m0 + wm + mt * 16 + (lane >> 2);
#pragma unroll
        for (int nt = 0; nt < 8; nt++) {
            int col = n0 + wn + nt * 8 + (lane & 3) * 2;
            *(float2*)(C + (size_t)row * N + col) =
                make_float2(comb8(hh[mt][nt][0], mid[mt][nt][0]),
                            comb8(hh[mt][nt][1], mid[mt][nt][1]));
            *(float2*)(C + (size_t)(row + 8) * N + col) =
                make_float2(comb8(hh[mt][nt][2], mid[mt][nt][2]),
                            comb8(hh[mt][nt][3], mid[mt][nt][3]));
        }
    }
}

// V variant: write transposed fp16 split (b,g,d,t)
__global__ void __launch_bounds__(256, 1)
gemm8_vt(const int8_t* __restrict__ Ah, const int8_t* __restrict__ Al,
         const int8_t* __restrict__ Wh, const int8_t* __restrict__ Wl,
         half* __restrict__ Ch, half* __restrict__ Cl, int K)
{
    extern __shared__ char smc[];
    const int m0 = blockIdx.y * 128;
    const int n0 = blockIdx.x * 128;
    int hh[2][8][4], mid[2][8][4];
#pragma unroll
    for (int mt = 0; mt < 2; mt++)
#pragma unroll
        for (int nt = 0; nt < 8; nt++)
#pragma unroll
            for (int j = 0; j < 4; j++) { hh[mt][nt][j] = 0; mid[mt][nt][j] = 0; }

    gemm8_mainloop(Ah, Al, Wh, Wl, K, m0, n0, smc, hh, mid);

    const int lane = threadIdx.x & 31;
    const int wid  = threadIdx.x >> 5;
    const int wm = (wid & 3) * 32;
    const int wn = (wid >> 2) * 64;
#pragma unroll
    for (int mt = 0; mt < 2; mt++) {
        int rowt = m0 + wm + mt * 16 + (lane >> 2);
#pragma unroll
        for (int nt = 0; nt < 8; nt++) {
            int col = n0 + wn + nt * 8 + (lane & 3) * 2;
#pragma unroll
            for (int j = 0; j < 4; j++) {
                int r = rowt + ((j >> 1) << 3);
                int cc2 = col + (j & 1);
                int b = r >> 11, t = r & (TT - 1);
                size_t di = (((size_t)b * NKV + (cc2 >> 6)) * DH + (cc2 & 63)) * TT + t;
                split_storeh(Ch, Cl, di, comb8(hh[mt][nt][j], mid[mt][nt][j]));
            }
        }
    }
}

// ---------------------------------------------------------------------------
// fp16 2-term GEMM (output projection): C = (Ah+Al) @ Wh^T, scale 2^-10.
// ---------------------------------------------------------------------------
#define PITCH 40
#define MAT2  (128 * PITCH * 2)
#define STAGE2 (3 * MAT2)
#define GEMM2_SMEM (2 * STAGE2)
#define OUT_SCALE (1.f / 1024.f)

__global__ void __launch_bounds__(256, 1)
gemm2_f32(const half* __restrict__ Ah, const half* __restrict__ Al,
          const half* __restrict__ Wh, float* __restrict__ C, int N, int K)
{
    extern __shared__ char smc[];
    const uint32_t sb = smem_u32(smc);
    const int tid  = threadIdx.x;
    const int lane = tid & 31;
    const int wid  = tid >> 5;
    const int wm = (wid & 3) * 32;
    const int wn = (wid >> 2) * 64;
    const int m0 = blockIdx.y * 128;
    const int n0 = blockIdx.x * 128;

    float acc[2][8][4];
#pragma unroll
    for (int mt = 0; mt < 2; mt++)
#pragma unroll
        for (int nt = 0; nt < 8; nt++)
#pragma unroll
            for (int j = 0; j < 4; j++) acc[mt][nt][j] = 0.f;

    const int quad = lane >> 3;
    const int arow_off = (lane & 7) + (quad & 1) * 8;
    const int acol_off = (quad >> 1) * 8;
    const int brow_off = (lane & 7) + (quad >> 1) * 8;
    const int bcol_off = (quad & 1) * 8;

    const int nch = K / 32;
    const int r_  = tid >> 2;
    const int q_  = tid & 3;

#define LOAD2(c, sel) do {                                                    \
    const uint32_t d0 = sb + (sel) * STAGE2;                                  \
    _Pragma("unroll")                                                         \
    for (int l = 0; l < 2; l++) {                                             \
        int row = r_ + l * 64;                                                \
        uint32_t doff = (uint32_t)(row * PITCH + q_ * 8) * 2;                 \
        size_t aoff = (size_t)(m0 + row) * K + (c) * 32 + q_ * 8;             \
        size_t woff = (size_t)(n0 + row) * K + (c) * 32 + q_ * 8;             \
        CP16(d0 + doff,            Ah + aoff);                                \
        CP16(d0 + MAT2 + doff,     Al + aoff);                                \
        CP16(d0 + 2 * MAT2 + doff, Wh + woff);                                \
    }                                                                         \
    CPCOMMIT();                                                               \
} while (0)

    LOAD2(0, 0);

    for (int c = 0; c < nch; c++) {
        if (c + 1 < nch) {
            LOAD2(c + 1, (c + 1) & 1);
            CPWAIT(1);
        } else {
            CPWAIT(0);
        }
        __syncthreads();

        const uint32_t base = sb + (c & 1) * STAGE2;
#pragma unroll
        for (int ks = 0; ks < 32; ks += 16) {
            uint32_t ah[2][4], al[2][4];
#pragma unroll
            for (int mt = 0; mt < 2; mt++) {
                uint32_t addr = base +
                    ((uint32_t)((wm + mt * 16 + arow_off) * PITCH + ks + acol_off) << 1);
                ldmx4(ah[mt][0], ah[mt][1], ah[mt][2], ah[mt][3], addr);
                ldmx4(al[mt][0], al[mt][1], al[mt][2], al[mt][3], addr + MAT2);
            }
            uint32_t bh[8][2];
#pragma unroll
            for (int np = 0; np < 4; np++) {
                uint32_t addr = base + 2 * MAT2 +
                    ((uint32_t)((wn + np * 16 + brow_off) * PITCH + ks + bcol_off) << 1);
                uint32_t r0, r1, r2, r3;
                ldmx4(r0, r1, r2, r3, addr);
                bh[2 * np][0] = r0; bh[2 * np][1] = r1;
                bh[2 * np + 1][0] = r2; bh[2 * np + 1][1] = r3;
            }
#pragma unroll
            for (int mt = 0; mt < 2; mt++)
#pragma unroll
                for (int nt = 0; nt < 8; nt++) {
                    mma16816(acc[mt][nt], ah[mt], bh[nt]);
                    mma16816(acc[mt][nt], al[mt], bh[nt]);
                }
        }
        __syncthreads();
    }
#undef LOAD2

#pragma unroll
    for (int mt = 0; mt < 2; mt++) {
        int row = m0 + wm + mt * 16 + (lane >> 2);
#pragma unroll
        for (int nt = 0; nt < 8; nt++) {
            int col = n0 + wn + nt * 8 + (lane & 3) * 2;
            *(float2*)(C + (size_t)row * N + col) =
                make_float2(acc[mt][nt][0] * OUT_SCALE, acc[mt][nt][1] * OUT_SCALE);
            *(float2*)(C + (size_t)(row + 8) * N + col) =
                make_float2(acc[mt][nt][2] * OUT_SCALE, acc[mt][nt][3] * OUT_SCALE);
        }
    }
}

// ---------------------------------------------------------------------------
// RoPE
// ---------------------------------------------------------------------------
__global__ void rope_table_kernel()
{
    int idx = blockIdx.x * blockDim.x + threadIdx.x;
    if (idx >= TT * 32) return;
    int t = idx >> 5;
    int i = idx & 31;
    double inv = pow(10000.0, -(double)i / 32.0);
    double a   = (double)t * inv;
    g_cos[idx] = (float)cos(a);
    g_sin[idx] = (float)sin(a);
}

__global__ void rope_apply_kernel()
{
    int idx = blockIdx.x * blockDim.x + threadIdx.x;
    const int total = BT * (NH + NKV) * 32;
    if (idx >= total) return;
    int i    = idx & 31;
    int rest = idx >> 5;
    int h    = rest % (NH + NKV);
    int bt   = rest / (NH + NKV);
    int t    = bt & (TT - 1);

    float c = g_cos[t * 32 + i];
    float s = g_sin[t * 32 + i];

    if (h < NH) {
        size_t base = (size_t)bt * DM + h * DH;
        float v0 = g_Q[base + i];
        float v1 = g_Q[base + i + 32];
        split_storeh(g_Qh, g_Ql, base + i,      (v0 * c - v1 * s) * 0.125f);
        split_storeh(g_Qh, g_Ql, base + i + 32, (v1 * c + v0 * s) * 0.125f);
    } else {
        size_t base = (size_t)bt * KVD + (h - NH) * DH;
        float v0 = g_K[base + i];
        float v1 = g_K[base + i + 32];
        g_Kh[base + i]      = __float2half_rn(v0 * c - v1 * s);
        g_Kh[base + i + 32] = __float2half_rn(v1 * c + v0 * s);
    }
}

// ---------------------------------------------------------------------------
// Flash attention: S = (qh+ql)*kh, PV = ph*(vh+vl). fp16 split output (x16).
// ---------------------------------------------------------------------------
#define KP 72
#define MATK (128 * KP * 2)
#define VP 136
#define VOFF MATK
#define VMAT (64 * VP * 2)
#define ATTN_SMEM (VOFF + 2 * VMAT)

__global__ void __launch_bounds__(256, 1) attn_mma()
{
    extern __shared__ char smc[];
    const uint32_t sb = smem_u32(smc);

    const int tid  = threadIdx.x;
    const int lane = tid & 31;
    const int wid  = tid >> 5;
    const int wq   = wid * 16;

    const int quad = lane >> 3;
    const int arow_off = (lane & 7) + (quad & 1) * 8;
    const int acol_off = (quad >> 1) * 8;
    const int brow_off = (lane & 7) + (quad >> 1) * 8;
    const int bcol_off = (quad & 1) * 8;

    const int q0 = (gridDim.x - 1 - blockIdx.x) * 128;
    const int h  = blockIdx.y;
    const int b  = blockIdx.z;
    const int g  = h >> 2;

    {
        const half* Qph = g_Qh + ((size_t)b * TT + q0) * DM + h * DH;
        const half* Qpl = g_Ql + ((size_t)b * TT + q0) * DM + h * DH;
#pragma unroll
        for (int l = 0; l < 4; l++) {
            int idx = tid + l * 256;
            int r   = idx >> 3;
            int cq  = idx & 7;
            uint32_t off = (uint32_t)(r * KP + cq * 8) * 2;
            *(uint4*)(smc + off)        = *(const uint4*)(Qph + (size_t)r * DM + cq * 8);
            *(uint4*)(smc + VOFF + off) = *(const uint4*)(Qpl + (size_t)r * DM + cq * 8);
        }
    }
    __syncthreads();

    uint32_t qh[4][4], ql[4][4];
#pragma unroll
    for (int ks = 0; ks < 4; ks++) {
        uint32_t addr = sb + ((uint32_t)((wq + arow_off) * KP + ks * 16 + acol_off) << 1);
        ldmx4(qh[ks][0], qh[ks][1], qh[ks][2], qh[ks][3], addr);
        ldmx4(ql[ks][0], ql[ks][1], ql[ks][2], ql[ks][3], addr + VOFF);
    }

    float oacc[8][4];
#pragma unroll
    for (int nt = 0; nt < 8; nt++)
#pragma unroll
        for (int j = 0; j < 4; j++) oacc[nt][j] = 0.f;
    float mrow0 = -1e30f, mrow1 = -1e30f, lrow0 = 0.f, lrow1 = 0.f;

    const int row0 = q0 + wq + (lane >> 2);
    const int row1 = row0 + 8;

    const half* Kb  = g_Kh  + (size_t)b * TT * KVD + g * DH;
    const half* Vbh = g_Vth + ((size_t)b * NKV + g) * DH * TT;
    const half* Vbl = g_Vtl + ((size_t)b * NKV + g) * DH * TT;

    for (int s0 = 0; s0 <= q0; s0 += 128) {
        __syncthreads();
#pragma unroll
        for (int l = 0; l < 4; l++) {
            int idx = tid + l * 256;
            {
                int s  = idx >> 3;
                int cq = idx & 7;
                size_t gi = (size_t)(s0 + s) * KVD + cq * 8;
                *(uint4*)(smc + (uint32_t)(s * KP + cq * 8) * 2) =
                    *(const uint4*)(Kb + gi);
            }
            {
                int d  = idx >> 4;
                int cq = idx & 15;
                size_t gi = (size_t)d * TT + s0 + cq * 8;
                uint32_t off = VOFF + (uint32_t)(d * VP + cq * 8) * 2;
                *(uint4*)(smc + off)        = *(const uint4*)(Vbh + gi);
                *(uint4*)(smc + VMAT + off) = *(const uint4*)(Vbl + gi);
            }
        }
        __syncthreads();

        float sacc[16][4];
#pragma unroll
        for (int nt = 0; nt < 16; nt++)
#pragma unroll
            for (int j = 0; j < 4; j++) sacc[nt][j] = 0.f;

#pragma unroll
        for (int np = 0; np < 8; np++) {
#pragma unroll
            for (int ks = 0; ks < 4; ks++) {
                uint32_t addr = sb +
                    ((uint32_t)((np * 16 + brow_off) * KP + ks * 16 + bcol_off) << 1);
                uint32_t h0, h1, h2, h3;
                ldmx4(h0, h1, h2, h3, addr);
                uint32_t bh0[2] = {h0, h1}, bh1[2] = {h2, h3};
                mma16816(sacc[2 * np],     qh[ks], bh0);
                mma16816(sacc[2 * np],     ql[ks], bh0);
                mma16816(sacc[2 * np + 1], qh[ks], bh1);
                mma16816(sacc[2 * np + 1], ql[ks], bh1);
            }
        }

        if (s0 == q0) {
            const int cbase = s0 + (lane & 3) * 2;
#pragma unroll
            for (int nt = 0; nt < 16; nt++) {
                int c0 = cbase + nt * 8;
                if (c0     > row0) sacc[nt][0] = -1e30f;
                if (c0 + 1 > row0) sacc[nt][1] = -1e30f;
                if (c0     > row1) sacc[nt][2] = -1e30f;
                if (c0 + 1 > row1) sacc[nt][3] = -1e30f;
            }
        }

        float mx0 = -1e30f, mx1 = -1e30f;
#pragma unroll
        for (int nt = 0; nt < 16; nt++) {
            mx0 = fmaxf(mx0, fmaxf(sacc[nt][0], sacc[nt][1]));
            mx1 = fmaxf(mx1, fmaxf(sacc[nt][2], sacc[nt][3]));
        }
        mx0 = fmaxf(mx0, __shfl_xor_sync(0xffffffffu, mx0, 1));
        mx0 = fmaxf(mx0, __shfl_xor_sync(0xffffffffu, mx0, 2));
        mx1 = fmaxf(mx1, __shfl_xor_sync(0xffffffffu, mx1, 1));
        mx1 = fmaxf(mx1, __shfl_xor_sync(0xffffffffu, mx1, 2));

        float mnew0 = fmaxf(mrow0, mx0);
        float mnew1 = fmaxf(mrow1, mx1);
        float alpha0 = __expf(mrow0 - mnew0);
        float alpha1 = __expf(mrow1 - mnew1);

        uint32_t ph[8][4];
        float rs0 = 0.f, rs1 = 0.f;
#pragma unroll
        for (int ks = 0; ks < 8; ks++) {
#pragma unroll
            for (int half_ = 0; half_ < 2; half_++) {
                int nt = 2 * ks + half_;
                float p0 = __expf(sacc[nt][0] - mnew0);
                float p1 = __expf(sacc[nt][1] - mnew0);
                float p2 = __expf(sacc[nt][2] - mnew1);
                float p3 = __expf(sacc[nt][3] - mnew1);
                rs0 += p0 + p1;
                rs1 += p2 + p3;
                ph[ks][2 * half_]     = packh(p0, p1);
                ph[ks][2 * half_ + 1] = packh(p2, p3);
            }
        }
        rs0 += __shfl_xor_sync(0xffffffffu, rs0, 1);
        rs0 += __shfl_xor_sync(0xffffffffu, rs0, 2);
        rs1 += __shfl_xor_sync(0xffffffffu, rs1, 1);
        rs1 += __shfl_xor_sync(0xffffffffu, rs1, 2);

        lrow0 = lrow0 * alpha0 + rs0;
        lrow1 = lrow1 * alpha1 + rs1;
        mrow0 = mnew0;
        mrow1 = mnew1;
#pragma unroll
        for (int nt = 0; nt < 8; nt++) {
            oacc[nt][0] *= alpha0;
            oacc[nt][1] *= alpha0;
            oacc[nt][2] *= alpha1;
            oacc[nt][3] *= alpha1;
        }

#pragma unroll
        for (int np = 0; np < 4; np++) {
#pragma unroll
            for (int ks = 0; ks < 8; ks++) {
                uint32_t addr = sb + VOFF +
                    ((uint32_t)((np * 16 + brow_off) * VP + ks * 16 + bcol_off) << 1);
                uint32_t h0, h1, h2, h3, l0, l1, l2, l3;
                ldmx4(h0, h1, h2, h3, addr);
                ldmx4(l0, l1, l2, l3, addr + VMAT);
                uint32_t bh0[2] = {h0, h1}, bh1[2] = {h2, h3};
                uint32_t bl0[2] = {l0, l1}, bl1[2] = {l2, l3};
                mma16816(oacc[2 * np],     ph[ks], bh0);
                mma16816(oacc[2 * np],     ph[ks], bl0);
                mma16816(oacc[2 * np + 1], ph[ks], bh1);
                mma16816(oacc[2 * np + 1], ph[ks], bl1);
            }
        }
    }

    // ---- epilogue: normalize, x16, split fp16 for the Wo GEMM
    float inv0 = 16.f / lrow0;
    float inv1 = 16.f / lrow1;
    const size_t o0 = ((size_t)b * TT + row0) * DM + h * DH + (lane & 3) * 2;
    const size_t o1 = ((size_t)b * TT + row1) * DM + h * DH + (lane & 3) * 2;
#pragma unroll
    for (int nt = 0; nt < 8; nt++) {
        float v0 = oacc[nt][0] * inv0, v1 = oacc[nt][1] * inv0;
        float v2 = oacc[nt][2] * inv1, v3 = oacc[nt][3] * inv1;
        half h0 = __float2half_rn(v0), h1 = __float2half_rn(v1);
        half h2 = __float2half_rn(v2), h3 = __float2half_rn(v3);
        __half2 hp0 = __halves2half2(h0, h1);
        __half2 hp1 = __halves2half2(h2, h3);
        *(uint32_t*)(g_Ah + o0 + nt * 8) = *reinterpret_cast<uint32_t*>(&hp0);
        *(uint32_t*)(g_Ah + o1 + nt * 8) = *reinterpret_cast<uint32_t*>(&hp1);
        *(uint32_t*)(g_Al + o0 + nt * 8) =
            packh(v0 - __half2float(h0), v1 - __half2float(h1));
        *(uint32_t*)(g_Al + o1 + nt * 8) =
            packh(v2 - __half2float(h2), v3 - __half2float(h3));
    }
}

// ---------------------------------------------------------------------------
extern "C" void kernel_launch(void* const* d_in, const int* in_sizes, int n_in,
                              void* d_out, int out_size)
{
    const float* x  = (const float*)d_in[0];
    const float* Wq = (const float*)d_in[1];
    const float* Wk = (const float*)d_in[2];
    const float* Wv = (const float*)d_in[3];
    const float* Wo = (const float*)d_in[4];
    float* out = (float*)d_out;

    float *gq, *gk;
    int8_t *x8h, *x8l, *wq8h, *wq8l, *wk8h, *wk8l, *wv8h, *wv8l;
    half *wo, *ah, *al, *vth, *vtl;
    cudaGetSymbolAddress((void**)&gq, g_Q);
    cudaGetSymbolAddress((void**)&gk, g_K);
    cudaGetSymbolAddress((void**)&x8h, g_x8h);   cudaGetSymbolAddress((void**)&x8l, g_x8l);
    cudaGetSymbolAddress((void**)&wq8h, g_Wq8h); cudaGetSymbolAddress((void**)&wq8l, g_Wq8l);
    cudaGetSymbolAddress((void**)&wk8h, g_Wk8h); cudaGetSymbolAddress((void**)&wk8l, g_Wk8l);
    cudaGetSymbolAddress((void**)&wv8h, g_Wv8h); cudaGetSymbolAddress((void**)&wv8l, g_Wv8l);
    cudaGetSymbolAddress((void**)&wo, g_Wo);
    cudaGetSymbolAddress((void**)&ah, g_Ah);     cudaGetSymbolAddress((void**)&al, g_Al);
    cudaGetSymbolAddress((void**)&vth, g_Vth);   cudaGetSymbolAddress((void**)&vtl, g_Vtl);

    cudaFuncSetAttribute(gemm8_f32, cudaFuncAttributeMaxDynamicSharedMemorySize,
                         GEMM8_SMEM);
    cudaFuncSetAttribute(gemm8_vt, cudaFuncAttributeMaxDynamicSharedMemorySize,
                         GEMM8_SMEM);
    cudaFuncSetAttribute(gemm2_f32, cudaFuncAttributeMaxDynamicSharedMemorySize,
                         GEMM2_SMEM);
    cudaFuncSetAttribute(attn_mma, cudaFuncAttributeMaxDynamicSharedMemorySize,
                         ATTN_SMEM);

    // ---- precompute: int8 digits for x + QKV weights; fp16 for Wo
    {
        int n4 = BT * DM / 4;
        quant8_kernel<<<(n4 + 255) / 256, 256>>>(x, x8h, x8l, S_X, n4);
        n4 = DM * DM / 4;
        quant8_kernel<<<(n4 + 255) / 256, 256>>>(Wq, wq8h, wq8l, S_W, n4);
        conv_w_kernel<<<(n4 + 255) / 256, 256>>>(Wo, wo, n4);
        n4 = KVD * DM / 4;
        quant8_kernel<<<(n4 + 255) / 256, 256>>>(Wk, wk8h, wk8l, S_W, n4);
        quant8_kernel<<<(n4 + 255) / 256, 256>>>(Wv, wv8h, wv8l, S_W, n4);
    }

    // ---- projections (IMMA)
    gemm8_f32<<<dim3(DM / 128, BT / 128), 256, GEMM8_SMEM>>>(
        x8h, x8l, wq8h, wq8l, gq, DM, DM);
    gemm8_f32<<<dim3(KVD / 128, BT / 128), 256, GEMM8_SMEM>>>(
        x8h, x8l, wk8h, wk8l, gk, KVD, DM);
    gemm8_vt<<<dim3(KVD / 128, BT / 128), 256, GEMM8_SMEM>>>(
        x8h, x8l, wv8h, wv8l, vth, vtl, DM);

    // ---- RoPE
    rope_table_kernel<<<(TT * 32 + 255) / 256, 256>>>();
    {
        int total = BT * (NH + NKV) * 32;
        rope_apply_kernel<<<(total + 255) / 256, 256>>>();
    }

    // ---- attention (fp16 HMMA)
    attn_mma<<<dim3(TT / 128, NH, BB), 256, ATTN_SMEM>>>();

    // ---- output projection (fp16 2-term)
    gemm2_f32<<<dim3(DM / 128, BT / 128), 256, GEMM2_SMEM>>>(ah, al, wo, out, DM, DM);
}

// round 9
// speedup vs baseline: 4.2337x; 1.2161x over previous
#include <cuda_runtime.h>
#include <cuda_fp16.h>
#include <math.h>
#include <stdint.h>

#define BB  2
#define TT  2048
#define DM  2048
#define NH  32
#define NKV 8
#define DH  64
#define BT  (BB*TT)
#define KVD (NKV*DH)   /* 512 */

#define S_X    4096.f          /* 2^12 */
#define S_W    262144.f        /* 2^18 */
#define INV_SC (1.f / 1073741824.f)   /* 2^-30 */

// ---------------- scratch (device globals; no allocations allowed) ----------
__device__ float g_Q[(size_t)BT * DM];     // fp32 Q pre-RoPE
__device__ float g_K[(size_t)BT * KVD];    // fp32 K pre-RoPE

__device__ int8_t g_x8h[(size_t)BT * DM],  g_x8l[(size_t)BT * DM];
__device__ int8_t g_Wq8h[(size_t)DM * DM],  g_Wq8l[(size_t)DM * DM];
__device__ int8_t g_Wk8h[(size_t)KVD * DM], g_Wk8l[(size_t)KVD * DM];
__device__ int8_t g_Wv8h[(size_t)KVD * DM], g_Wv8l[(size_t)KVD * DM];

__device__ half g_Wo[(size_t)DM * DM];                            // Wo * 64 single
__device__ half g_Ah[(size_t)BT * DM];                            // attn out x16 single

__device__ half g_Qh[(size_t)BT * DM];                            // roped, x0.125 single
__device__ half g_Kh[(size_t)BT * KVD];                           // roped, single
__device__ half g_Vth[(size_t)BT * KVD];                          // (b,g,d,t) single

__device__ float g_cos[TT * 32];
__device__ float g_sin[TT * 32];

// ===================== helpers ======================
__device__ __forceinline__ uint32_t smem_u32(const void* p) {
    uint32_t a;
    asm("{ .reg .u64 t; cvta.to.shared.u64 t, %1; cvt.u32.u64 %0, t; }"
        : "=r"(a) : "l"(p));
    return a;
}

#define CP16(dst, src) \
    asm volatile("cp.async.cg.shared.global [%0], [%1], 16;" \
                 :: "r"(dst), "l"(src) : "memory")
#define CPCOMMIT() asm volatile("cp.async.commit_group;" ::: "memory")
#define CPWAIT(n)  asm volatile("cp.async.wait_group %0;" :: "n"(n) : "memory")

__device__ __forceinline__ void ldmx4(uint32_t& r0, uint32_t& r1,
                                      uint32_t& r2, uint32_t& r3, uint32_t a) {
    asm volatile("ldmatrix.sync.aligned.m8n8.x4.shared.b16 {%0,%1,%2,%3}, [%4];"
                 : "=r"(r0), "=r"(r1), "=r"(r2), "=r"(r3) : "r"(a));
}

__device__ __forceinline__ void mma16816(float* d, const uint32_t* a,
                                         const uint32_t* b) {
    asm volatile(
        "mma.sync.aligned.m16n8k16.row.col.f32.f16.f16.f32 "
        "{%0,%1,%2,%3},{%4,%5,%6,%7},{%8,%9},{%0,%1,%2,%3};"
        : "+f"(d[0]), "+f"(d[1]), "+f"(d[2]), "+f"(d[3])
        : "r"(a[0]), "r"(a[1]), "r"(a[2]), "r"(a[3]), "r"(b[0]), "r"(b[1]));
}

__device__ __forceinline__ void mma_s8(int* d, const uint32_t* a,
                                       const uint32_t* b) {
    asm volatile(
        "mma.sync.aligned.m16n8k32.row.col.s32.s8.s8.s32 "
        "{%0,%1,%2,%3},{%4,%5,%6,%7},{%8,%9},{%0,%1,%2,%3};"
        : "+r"(d[0]), "+r"(d[1]), "+r"(d[2]), "+r"(d[3])
        : "r"(a[0]), "r"(a[1]), "r"(a[2]), "r"(a[3]), "r"(b[0]), "r"(b[1]));
}

__device__ __forceinline__ uint32_t packh(float a, float b) {
    __half2 t = __floats2half2_rn(a, b);
    return *reinterpret_cast<uint32_t*>(&t);
}

// 16-bit fixed point -> two int8 digits (hi*256 + lo == q, exact)
__device__ __forceinline__ void qsplit(float v, float S, int8_t& hi, int8_t& lo) {
    int q = __float2int_rn(v * S);
    q = max(-32512, min(32512, q));
    int l = ((q + 128) & 255) - 128;
    hi = (int8_t)((q - l) >> 8);
    lo = (int8_t)l;
}

// ---------------------------------------------------------------------------
// precompute kernels
// ---------------------------------------------------------------------------
__global__ void quant8_kernel(const float* __restrict__ src,
                              int8_t* __restrict__ h, int8_t* __restrict__ l,
                              float S, int n4)
{
    int i = blockIdx.x * blockDim.x + threadIdx.x;
    if (i >= n4) return;
    float4 v = ((const float4*)src)[i];
    int8_t h0, h1, h2, h3, l0, l1, l2, l3;
    qsplit(v.x, S, h0, l0);
    qsplit(v.y, S, h1, l1);
    qsplit(v.z, S, h2, l2);
    qsplit(v.w, S, h3, l3);
    ((char4*)h)[i] = make_char4(h0, h1, h2, h3);
    ((char4*)l)[i] = make_char4(l0, l1, l2, l3);
}

__global__ void conv_w_kernel(const float* __restrict__ src,
                              half* __restrict__ h, int n4)
{
    int i = blockIdx.x * blockDim.x + threadIdx.x;
    if (i >= n4) return;
    float4 v = ((const float4*)src)[i];
    __half2 a = __floats2half2_rn(v.x * 64.f, v.y * 64.f);
    __half2 b = __floats2half2_rn(v.z * 64.f, v.w * 64.f);
    uint2 o;
    o.x = *reinterpret_cast<uint32_t*>(&a);
    o.y = *reinterpret_cast<uint32_t*>(&b);
    ((uint2*)h)[i] = o;
}

// ---------------------------------------------------------------------------
// int8 2-digit GEMM (QKV projections): HH*2^16 + (HL+LH)*2^8, LL dropped.
// ---------------------------------------------------------------------------
#define PI8  48
#define MAT8 (128 * PI8)        /* 6144 B */
#define STG8 (4 * MAT8)         /* 24576 B */
#define GEMM8_SMEM (2 * STG8)   /* 49152 B */

__device__ __forceinline__ void gemm8_mainloop(
    const int8_t* __restrict__ Ah, const int8_t* __restrict__ Al,
    const int8_t* __restrict__ Wh, const int8_t* __restrict__ Wl,
    int K, int m0, int n0, char* smc, int hh[2][8][4], int mid[2][8][4])
{
    const uint32_t sb = smem_u32(smc);
    const int tid  = threadIdx.x;
    const int lane = tid & 31;
    const int wid  = tid >> 5;
    const int wm = (wid & 3) * 32;
    const int wn = (wid >> 2) * 64;

    const int quad  = lane >> 3;
    const int arow  = (lane & 7) + (quad & 1) * 8;
    const int acolB = (quad >> 1) * 16;
    const int brow  = (lane & 7) + (quad >> 1) * 8;
    const int bcolB = (quad & 1) * 16;

    const int row = tid >> 1;
    const int cc  = tid & 1;
    const int nch = K / 32;

#define L8(c, sel) do {                                                       \
    uint32_t d0 = sb + (sel) * STG8 + (uint32_t)(row * PI8 + cc * 16);        \
    size_t ao = (size_t)(m0 + row) * K + (size_t)(c) * 32 + cc * 16;          \
    size_t wo = (size_t)(n0 + row) * K + (size_t)(c) * 32 + cc * 16;          \
    CP16(d0,            Ah + ao);                                             \
    CP16(d0 + MAT8,     Al + ao);                                             \
    CP16(d0 + 2 * MAT8, Wh + wo);                                             \
    CP16(d0 + 3 * MAT8, Wl + wo);                                             \
    CPCOMMIT();                                                               \
} while (0)

    L8(0, 0);

    for (int c = 0; c < nch; c++) {
        if (c + 1 < nch) {
            L8(c + 1, (c + 1) & 1);
            CPWAIT(1);
        } else {
            CPWAIT(0);
        }
        __syncthreads();

        const uint32_t base = sb + (c & 1) * STG8;

        uint32_t ahi[2][4], alo[2][4];
#pragma unroll
        for (int mt = 0; mt < 2; mt++) {
            uint32_t addr = base + (uint32_t)((wm + mt * 16 + arow) * PI8 + acolB);
            ldmx4(ahi[mt][0], ahi[mt][1], ahi[mt][2], ahi[mt][3], addr);
            ldmx4(alo[mt][0], alo[mt][1], alo[mt][2], alo[mt][3], addr + MAT8);
        }
#pragma unroll
        for (int np = 0; np < 4; np++) {
            uint32_t baddr = base + 2 * MAT8 +
                             (uint32_t)((wn + np * 16 + brow) * PI8 + bcolB);
            uint32_t bh[4], bl[4];
            ldmx4(bh[0], bh[1], bh[2], bh[3], baddr);
            ldmx4(bl[0], bl[1], bl[2], bl[3], baddr + MAT8);
            uint32_t b0h[2] = {bh[0], bh[1]}, b1h[2] = {bh[2], bh[3]};
            uint32_t b0l[2] = {bl[0], bl[1]}, b1l[2] = {bl[2], bl[3]};
#pragma unroll
            for (int mt = 0; mt < 2; mt++) {
                mma_s8(hh[mt][2 * np],      ahi[mt], b0h);
                mma_s8(hh[mt][2 * np + 1],  ahi[mt], b1h);
                mma_s8(mid[mt][2 * np],     ahi[mt], b0l);
                mma_s8(mid[mt][2 * np + 1], ahi[mt], b1l);
                mma_s8(mid[mt][2 * np],     alo[mt], b0h);
                mma_s8(mid[mt][2 * np + 1], alo[mt], b1h);
            }
        }
        __syncthreads();
    }
#undef L8
}

__device__ __forceinline__ float comb8(int hh, int mid) {
    return fmaf((float)hh, 65536.f, (float)mid * 256.f) * INV_SC;
}

// fp32-output variant (Q, K projections)
__global__ void __launch_bounds__(256, 1)
gemm8_f32(const int8_t* __restrict__ Ah, const int8_t* __restrict__ Al,
          const int8_t* __restrict__ Wh, const int8_t* __restrict__ Wl,
          float* __restrict__ C, int N, int K)
{
    extern __shared__ char smc[];
    const int m0 = blockIdx.y * 128;
    const int n0 = blockIdx.x * 128;
    int hh[2][8][4], mid[2][8][4];
#pragma unroll
    for (int mt = 0; mt < 2; mt++)
#pragma unroll
        for (int nt = 0; nt < 8; nt++)
#pragma unroll
            for (int j = 0; j < 4; j++) { hh[mt][nt][j] = 0; mid[mt][nt][j] = 0; }

    gemm8_mainloop(Ah, Al, Wh, Wl, K, m0, n0, smc, hh, mid);

    const int lane = threadIdx.x & 31;
    const int wid  = threadIdx.x >> 5;
    const int wm = (wid & 3) * 32;
    const int wn = (wid >> 2) * 64;
#pragma unroll
    for (int mt = 0; mt < 2; mt++) {
        int row = m0 + wm + mt * 16 + (lane >> 2);
#pragma unroll
        for (int nt = 0; nt < 8; nt++) {
            int col = n0 + wn + nt * 8 + (lane & 3) * 2;
            *(float2*)(C + (size_t)row * N + col) =
                make_float2(comb8(hh[mt][nt][0], mid[mt][nt][0]),
                            comb8(hh[mt][nt][1], mid[mt][nt][1]));
            *(float2*)(C + (size_t)(row + 8) * N + col) =
                make_float2(comb8(hh[mt][nt][2], mid[mt][nt][2]),
                            comb8(hh[mt][nt][3], mid[mt][nt][3]));
        }
    }
}

// V variant: write transposed single fp16 (b,g,d,t)
__global__ void __launch_bounds__(256, 1)
gemm8_vt(const int8_t* __restrict__ Ah, const int8_t* __restrict__ Al,
         const int8_t* __restrict__ Wh, const int8_t* __restrict__ Wl,
         half* __restrict__ Ch, int K)
{
    extern __shared__ char smc[];
    const int m0 = blockIdx.y * 128;
    const int n0 = blockIdx.x * 128;
    int hh[2][8][4], mid[2][8][4];
#pragma unroll
    for (int mt = 0; mt < 2; mt++)
#pragma unroll
        for (int nt = 0; nt < 8; nt++)
#pragma unroll
            for (int j = 0; j < 4; j++) { hh[mt][nt][j] = 0; mid[mt][nt][j] = 0; }

    gemm8_mainloop(Ah, Al, Wh, Wl, K, m0, n0, smc, hh, mid);

    const int lane = threadIdx.x & 31;
    const int wid  = threadIdx.x >> 5;
    const int wm = (wid & 3) * 32;
    const int wn = (wid >> 2) * 64;
#pragma unroll
    for (int mt = 0; mt < 2; mt++) {
        int rowt = m0 + wm + mt * 16 + (lane >> 2);
#pragma unroll
        for (int nt = 0; nt < 8; nt++) {
            int col = n0 + wn + nt * 8 + (lane & 3) * 2;
#pragma unroll
            for (int j = 0; j < 4; j++) {
                int r = rowt + ((j >> 1) << 3);
                int cc2 = col + (j & 1);
                int b = r >> 11, t = r & (TT - 1);
                size_t di = (((size_t)b * NKV + (cc2 >> 6)) * DH + (cc2 & 63)) * TT + t;
                Ch[di] = __float2half_rn(comb8(hh[mt][nt][j], mid[mt][nt][j]));
            }
        }
    }
}

// ---------------------------------------------------------------------------
// fp16 1-term GEMM (output projection): C = Ah @ Wh^T, scale 2^-10.
// ---------------------------------------------------------------------------
#define PITCH 40
#define MAT2  (128 * PITCH * 2)
#define STAGE2 (2 * MAT2)
#define GEMM2_SMEM (2 * STAGE2)
#define OUT_SCALE (1.f / 1024.f)

__global__ void __launch_bounds__(256, 1)
gemm2_f32(const half* __restrict__ Ah, const half* __restrict__ Wh,
          float* __restrict__ C, int N, int K)
{
    extern __shared__ char smc[];
    const uint32_t sb = smem_u32(smc);
    const int tid  = threadIdx.x;
    const int lane = tid & 31;
    const int wid  = tid >> 5;
    const int wm = (wid & 3) * 32;
    const int wn = (wid >> 2) * 64;
    const int m0 = blockIdx.y * 128;
    const int n0 = blockIdx.x * 128;

    float acc[2][8][4];
#pragma unroll
    for (int mt = 0; mt < 2; mt++)
#pragma unroll
        for (int nt = 0; nt < 8; nt++)
#pragma unroll
            for (int j = 0; j < 4; j++) acc[mt][nt][j] = 0.f;

    const int quad = lane >> 3;
    const int arow_off = (lane & 7) + (quad & 1) * 8;
    const int acol_off = (quad >> 1) * 8;
    const int brow_off = (lane & 7) + (quad >> 1) * 8;
    const int bcol_off = (quad & 1) * 8;

    const int nch = K / 32;
    const int r_  = tid >> 2;
    const int q_  = tid & 3;

#define LOAD2(c, sel) do {                                                    \
    const uint32_t d0 = sb + (sel) * STAGE2;                                  \
    _Pragma("unroll")                                                         \
    for (int l = 0; l < 2; l++) {                                             \
        int row = r_ + l * 64;                                                \
        uint32_t doff = (uint32_t)(row * PITCH + q_ * 8) * 2;                 \
        size_t aoff = (size_t)(m0 + row) * K + (c) * 32 + q_ * 8;             \
        size_t woff = (size_t)(n0 + row) * K + (c) * 32 + q_ * 8;             \
        CP16(d0 + doff,        Ah + aoff);                                    \
        CP16(d0 + MAT2 + doff, Wh + woff);                                    \
    }                                                                         \
    CPCOMMIT();                                                               \
} while (0)

    LOAD2(0, 0);

    for (int c = 0; c < nch; c++) {
        if (c + 1 < nch) {
            LOAD2(c + 1, (c + 1) & 1);
            CPWAIT(1);
        } else {
            CPWAIT(0);
        }
        __syncthreads();

        const uint32_t base = sb + (c & 1) * STAGE2;
#pragma unroll
        for (int ks = 0; ks < 32; ks += 16) {
            uint32_t ah[2][4];
#pragma unroll
            for (int mt = 0; mt < 2; mt++) {
                uint32_t addr = base +
                    ((uint32_t)((wm + mt * 16 + arow_off) * PITCH + ks + acol_off) << 1);
                ldmx4(ah[mt][0], ah[mt][1], ah[mt][2], ah[mt][3], addr);
            }
            uint32_t bh[8][2];
#pragma unroll
            for (int np = 0; np < 4; np++) {
                uint32_t addr = base + MAT2 +
                    ((uint32_t)((wn + np * 16 + brow_off) * PITCH + ks + bcol_off) << 1);
                uint32_t r0, r1, r2, r3;
                ldmx4(r0, r1, r2, r3, addr);
                bh[2 * np][0] = r0; bh[2 * np][1] = r1;
                bh[2 * np + 1][0] = r2; bh[2 * np + 1][1] = r3;
            }
#pragma unroll
            for (int mt = 0; mt < 2; mt++)
#pragma unroll
                for (int nt = 0; nt < 8; nt++)
                    mma16816(acc[mt][nt], ah[mt], bh[nt]);
        }
        __syncthreads();
    }
#undef LOAD2

#pragma unroll
    for (int mt = 0; mt < 2; mt++) {
        int row = m0 + wm + mt * 16 + (lane >> 2);
#pragma unroll
        for (int nt = 0; nt < 8; nt++) {
            int col = n0 + wn + nt * 8 + (lane & 3) * 2;
            *(float2*)(C + (size_t)row * N + col) =
                make_float2(acc[mt][nt][0] * OUT_SCALE, acc[mt][nt][1] * OUT_SCALE);
            *(float2*)(C + (size_t)(row + 8) * N + col) =
                make_float2(acc[mt][nt][2] * OUT_SCALE, acc[mt][nt][3] * OUT_SCALE);
        }
    }
}

// ---------------------------------------------------------------------------
// RoPE
// ---------------------------------------------------------------------------
__global__ void rope_table_kernel()
{
    int idx = blockIdx.x * blockDim.x + threadIdx.x;
    if (idx >= TT * 32) return;
    int t = idx >> 5;
    int i = idx & 31;
    double inv = pow(10000.0, -(double)i / 32.0);
    double a   = (double)t * inv;
    g_cos[idx] = (float)cos(a);
    g_sin[idx] = (float)sin(a);
}

__global__ void rope_apply_kernel()
{
    int idx = blockIdx.x * blockDim.x + threadIdx.x;
    const int total = BT * (NH + NKV) * 32;
    if (idx >= total) return;
    int i    = idx & 31;
    int rest = idx >> 5;
    int h    = rest % (NH + NKV);
    int bt   = rest / (NH + NKV);
    int t    = bt & (TT - 1);

    float c = g_cos[t * 32 + i];
    float s = g_sin[t * 32 + i];

    if (h < NH) {
        size_t base = (size_t)bt * DM + h * DH;
        float v0 = g_Q[base + i];
        float v1 = g_Q[base + i + 32];
        g_Qh[base + i]      = __float2half_rn((v0 * c - v1 * s) * 0.125f);
        g_Qh[base + i + 32] = __float2half_rn((v1 * c + v0 * s) * 0.125f);
    } else {
        size_t base = (size_t)bt * KVD + (h - NH) * DH;
        float v0 = g_K[base + i];
        float v1 = g_K[base + i + 32];
        g_Kh[base + i]      = __float2half_rn(v0 * c - v1 * s);
        g_Kh[base + i + 32] = __float2half_rn(v1 * c + v0 * s);
    }
}

// ---------------------------------------------------------------------------
// Flash attention, fully single-term fp16: S = qh*kh, PV = ph*vh.
// smem: Kh[128][KP] at 0; Vh[64][VP] at VOFF.
// ---------------------------------------------------------------------------
#define KP 72
#define MATK (128 * KP * 2)          /* 18432 */
#define VP 136
#define VOFF MATK
#define VMAT (64 * VP * 2)           /* 17408 */
#define ATTN_SMEM (VOFF + VMAT)      /* 35840 */

__global__ void __launch_bounds__(256, 1) attn_mma()
{
    extern __shared__ char smc[];
    const uint32_t sb = smem_u32(smc);

    const int tid  = threadIdx.x;
    const int lane = tid & 31;
    const int wid  = tid >> 5;
    const int wq   = wid * 16;

    const int quad = lane >> 3;
    const int arow_off = (lane & 7) + (quad & 1) * 8;
    const int acol_off = (quad >> 1) * 8;
    const int brow_off = (lane & 7) + (quad >> 1) * 8;
    const int bcol_off = (quad & 1) * 8;

    const int q0 = (gridDim.x - 1 - blockIdx.x) * 128;
    const int h  = blockIdx.y;
    const int b  = blockIdx.z;
    const int g  = h >> 2;

    // ---- stage Q via K area, then into registers
    {
        const half* Qph = g_Qh + ((size_t)b * TT + q0) * DM + h * DH;
#pragma unroll
        for (int l = 0; l < 4; l++) {
            int idx = tid + l * 256;
            int r   = idx >> 3;
            int cq  = idx & 7;
            uint32_t off = (uint32_t)(r * KP + cq * 8) * 2;
            *(uint4*)(smc + off) = *(const uint4*)(Qph + (size_t)r * DM + cq * 8);
        }
    }
    __syncthreads();

    uint32_t qh[4][4];
#pragma unroll
    for (int ks = 0; ks < 4; ks++) {
        uint32_t addr = sb + ((uint32_t)((wq + arow_off) * KP + ks * 16 + acol_off) << 1);
        ldmx4(qh[ks][0], qh[ks][1], qh[ks][2], qh[ks][3], addr);
    }

    float oacc[8][4];
#pragma unroll
    for (int nt = 0; nt < 8; nt++)
#pragma unroll
        for (int j = 0; j < 4; j++) oacc[nt][j] = 0.f;
    float mrow0 = -1e30f, mrow1 = -1e30f, lrow0 = 0.f, lrow1 = 0.f;

    const int row0 = q0 + wq + (lane >> 2);
    const int row1 = row0 + 8;

    const half* Kb  = g_Kh  + (size_t)b * TT * KVD + g * DH;
    const half* Vbh = g_Vth + ((size_t)b * NKV + g) * DH * TT;

    for (int s0 = 0; s0 <= q0; s0 += 128) {
        __syncthreads();
#pragma unroll
        for (int l = 0; l < 4; l++) {
            int idx = tid + l * 256;
            {
                int s  = idx >> 3;
                int cq = idx & 7;
                size_t gi = (size_t)(s0 + s) * KVD + cq * 8;
                *(uint4*)(smc + (uint32_t)(s * KP + cq * 8) * 2) =
                    *(const uint4*)(Kb + gi);
            }
            if (l < 2) {
                int idx2 = tid + l * 256;       // 0..511
                int d  = idx2 >> 3;             // 0..63
                int cq = idx2 & 7;
                size_t gi = (size_t)d * TT + s0 + cq * 16;
                uint32_t off = VOFF + (uint32_t)(d * VP + cq * 16) * 2;
                *(uint4*)(smc + off)      = *(const uint4*)(Vbh + gi);
                *(uint4*)(smc + off + 16) = *(const uint4*)(Vbh + gi + 8);
            }
        }
        __syncthreads();

        // ---- S = Q K^T (single term)
        float sacc[16][4];
#pragma unroll
        for (int nt = 0; nt < 16; nt++)
#pragma unroll
            for (int j = 0; j < 4; j++) sacc[nt][j] = 0.f;

#pragma unroll
        for (int np = 0; np < 8; np++) {
#pragma unroll
            for (int ks = 0; ks < 4; ks++) {
                uint32_t addr = sb +
                    ((uint32_t)((np * 16 + brow_off) * KP + ks * 16 + bcol_off) << 1);
                uint32_t h0, h1, h2, h3;
                ldmx4(h0, h1, h2, h3, addr);
                uint32_t bh0[2] = {h0, h1}, bh1[2] = {h2, h3};
                mma16816(sacc[2 * np],     qh[ks], bh0);
                mma16816(sacc[2 * np + 1], qh[ks], bh1);
            }
        }

        if (s0 == q0) {
            const int cbase = s0 + (lane & 3) * 2;
#pragma unroll
            for (int nt = 0; nt < 16; nt++) {
                int c0 = cbase + nt * 8;
                if (c0     > row0) sacc[nt][0] = -1e30f;
                if (c0 + 1 > row0) sacc[nt][1] = -1e30f;
                if (c0     > row1) sacc[nt][2] = -1e30f;
                if (c0 + 1 > row1) sacc[nt][3] = -1e30f;
            }
        }

        float mx0 = -1e30f, mx1 = -1e30f;
#pragma unroll
        for (int nt = 0; nt < 16; nt++) {
            mx0 = fmaxf(mx0, fmaxf(sacc[nt][0], sacc[nt][1]));
            mx1 = fmaxf(mx1, fmaxf(sacc[nt][2], sacc[nt][3]));
        }
        mx0 = fmaxf(mx0, __shfl_xor_sync(0xffffffffu, mx0, 1));
        mx0 = fmaxf(mx0, __shfl_xor_sync(0xffffffffu, mx0, 2));
        mx1 = fmaxf(mx1, __shfl_xor_sync(0xffffffffu, mx1, 1));
        mx1 = fmaxf(mx1, __shfl_xor_sync(0xffffffffu, mx1, 2));

        float mnew0 = fmaxf(mrow0, mx0);
        float mnew1 = fmaxf(mrow1, mx1);
        float alpha0 = __expf(mrow0 - mnew0);
        float alpha1 = __expf(mrow1 - mnew1);

        uint32_t ph[8][4];
        float rs0 = 0.f, rs1 = 0.f;
#pragma unroll
        for (int ks = 0; ks < 8; ks++) {
#pragma unroll
            for (int half_ = 0; half_ < 2; half_++) {
                int nt = 2 * ks + half_;
                float p0 = __expf(sacc[nt][0] - mnew0);
                float p1 = __expf(sacc[nt][1] - mnew0);
                float p2 = __expf(sacc[nt][2] - mnew1);
                float p3 = __expf(sacc[nt][3] - mnew1);
                rs0 += p0 + p1;
                rs1 += p2 + p3;
                ph[ks][2 * half_]     = packh(p0, p1);
                ph[ks][2 * half_ + 1] = packh(p2, p3);
            }
        }
        rs0 += __shfl_xor_sync(0xffffffffu, rs0, 1);
        rs0 += __shfl_xor_sync(0xffffffffu, rs0, 2);
        rs1 += __shfl_xor_sync(0xffffffffu, rs1, 1);
        rs1 += __shfl_xor_sync(0xffffffffu, rs1, 2);

        lrow0 = lrow0 * alpha0 + rs0;
        lrow1 = lrow1 * alpha1 + rs1;
        mrow0 = mnew0;
        mrow1 = mnew1;
#pragma unroll
        for (int nt = 0; nt < 8; nt++) {
            oacc[nt][0] *= alpha0;
            oacc[nt][1] *= alpha0;
            oacc[nt][2] *= alpha1;
            oacc[nt][3] *= alpha1;
        }

        // ---- O += P V (single term)
#pragma unroll
        for (int np = 0; np < 4; np++) {
#pragma unroll
            for (int ks = 0; ks < 8; ks++) {
                uint32_t addr = sb + VOFF +
                    ((uint32_t)((np * 16 + brow_off) * VP + ks * 16 + bcol_off) << 1);
                uint32_t h0, h1, h2, h3;
                ldmx4(h0, h1, h2, h3, addr);
                uint32_t bh0[2] = {h0, h1}, bh1[2] = {h2, h3};
                mma16816(oacc[2 * np],     ph[ks], bh0);
                mma16816(oacc[2 * np + 1], ph[ks], bh1);
            }
        }
    }

    // ---- epilogue: normalize, x16, single fp16 for the Wo GEMM
    float inv0 = 16.f / lrow0;
    float inv1 = 16.f / lrow1;
    const size_t o0 = ((size_t)b * TT + row0) * DM + h * DH + (lane & 3) * 2;
    const size_t o1 = ((size_t)b * TT + row1) * DM + h * DH + (lane & 3) * 2;
#pragma unroll
    for (int nt = 0; nt < 8; nt++) {
        *(uint32_t*)(g_Ah + o0 + nt * 8) =
            packh(oacc[nt][0] * inv0, oacc[nt][1] * inv0);
        *(uint32_t*)(g_Ah + o1 + nt * 8) =
            packh(oacc[nt][2] * inv1, oacc[nt][3] * inv1);
    }
}

// ---------------------------------------------------------------------------
extern "C" void kernel_launch(void* const* d_in, const int* in_sizes, int n_in,
                              void* d_out, int out_size)
{
    const float* x  = (const float*)d_in[0];
    const float* Wq = (const float*)d_in[1];
    const float* Wk = (const float*)d_in[2];
    const float* Wv = (const float*)d_in[3];
    const float* Wo = (const float*)d_in[4];
    float* out = (float*)d_out;

    float *gq, *gk;
    int8_t *x8h, *x8l, *wq8h, *wq8l, *wk8h, *wk8l, *wv8h, *wv8l;
    half *wo, *ah, *vth;
    cudaGetSymbolAddress((void**)&gq, g_Q);
    cudaGetSymbolAddress((void**)&gk, g_K);
    cudaGetSymbolAddress((void**)&x8h, g_x8h);   cudaGetSymbolAddress((void**)&x8l, g_x8l);
    cudaGetSymbolAddress((void**)&wq8h, g_Wq8h); cudaGetSymbolAddress((void**)&wq8l, g_Wq8l);
    cudaGetSymbolAddress((void**)&wk8h, g_Wk8h); cudaGetSymbolAddress((void**)&wk8l, g_Wk8l);
    cudaGetSymbolAddress((void**)&wv8h, g_Wv8h); cudaGetSymbolAddress((void**)&wv8l, g_Wv8l);
    cudaGetSymbolAddress((void**)&wo, g_Wo);
    cudaGetSymbolAddress((void**)&ah, g_Ah);
    cudaGetSymbolAddress((void**)&vth, g_Vth);

    cudaFuncSetAttribute(gemm8_f32, cudaFuncAttributeMaxDynamicSharedMemorySize,
                         GEMM8_SMEM);
    cudaFuncSetAttribute(gemm8_vt, cudaFuncAttributeMaxDynamicSharedMemorySize,
                         GEMM8_SMEM);
    cudaFuncSetAttribute(gemm2_f32, cudaFuncAttributeMaxDynamicSharedMemorySize,
                         GEMM2_SMEM);
    cudaFuncSetAttribute(attn_mma, cudaFuncAttributeMaxDynamicSharedMemorySize,
                         ATTN_SMEM);

    // ---- precompute
    {
        int n4 = BT * DM / 4;
        quant8_kernel<<<(n4 + 255) / 256, 256>>>(x, x8h, x8l, S_X, n4);
        n4 = DM * DM / 4;
        quant8_kernel<<<(n4 + 255) / 256, 256>>>(Wq, wq8h, wq8l, S_W, n4);
        conv_w_kernel<<<(n4 + 255) / 256, 256>>>(Wo, wo, n4);
        n4 = KVD * DM / 4;
        quant8_kernel<<<(n4 + 255) / 256, 256>>>(Wk, wk8h, wk8l, S_W, n4);
        quant8_kernel<<<(n4 + 255) / 256, 256>>>(Wv, wv8h, wv8l, S_W, n4);
    }

    // ---- projections (IMMA)
    gemm8_f32<<<dim3(DM / 128, BT / 128), 256, GEMM8_SMEM>>>(
        x8h, x8l, wq8h, wq8l, gq, DM, DM);
    gemm8_f32<<<dim3(KVD / 128, BT / 128), 256, GEMM8_SMEM>>>(
        x8h, x8l, wk8h, wk8l, gk, KVD, DM);
    gemm8_vt<<<dim3(KVD / 128, BT / 128), 256, GEMM8_SMEM>>>(
        x8h, x8l, wv8h, wv8l, vth, DM);

    // ---- RoPE
    rope_table_kernel<<<(TT * 32 + 255) / 256, 256>>>();
    {
        int total = BT * (NH + NKV) * 32;
        rope_apply_kernel<<<(total + 255) / 256, 256>>>();
    }

    // ---- attention (single-term fp16 HMMA)
    attn_mma<<<dim3(TT / 128, NH, BB), 256, ATTN_SMEM>>>();

    // ---- output projection (single-term fp16)
    gemm2_f32<<<dim3(DM / 128, BT / 128), 256, GEMM2_SMEM>>>(ah, wo, out, DM, DM);
}

// round 10
// speedup vs baseline: 4.3207x; 1.0206x over previous
#include <cuda_runtime.h>
#include <cuda_fp16.h>
#include <math.h>
#include <stdint.h>

#define BB  2
#define TT  2048
#define DM  2048
#define NH  32
#define NKV 8
#define DH  64
#define BT  (BB*TT)
#define KVD (NKV*DH)   /* 512 */
#define NC  (DM + 2*KVD)   /* 3072 combined output cols */

#define S_X    4096.f          /* 2^12 */
#define S_W    262144.f        /* 2^18 */
#define INV_SC (1.f / 1073741824.f)   /* 2^-30 */

// ---------------- scratch (device globals; no allocations allowed) ----------
__device__ int8_t g_x8h[(size_t)BT * DM],  g_x8l[(size_t)BT * DM];
__device__ int8_t g_Wc8h[(size_t)NC * DM], g_Wc8l[(size_t)NC * DM]; // Wq|Wk|Wv

__device__ half g_Wo[(size_t)DM * DM];                            // Wo * 64 single
__device__ half g_Ah[(size_t)BT * DM];                            // attn out x16 single

__device__ half g_Qh[(size_t)BT * DM];                            // roped, x0.125 single
__device__ half g_Kh[(size_t)BT * KVD];                           // roped, single
__device__ half g_Vth[(size_t)BT * KVD];                          // (b,g,d,t) single

__device__ float g_cos[TT * 32];
__device__ float g_sin[TT * 32];

// ===================== helpers ======================
__device__ __forceinline__ uint32_t smem_u32(const void* p) {
    uint32_t a;
    asm("{ .reg .u64 t; cvta.to.shared.u64 t, %1; cvt.u32.u64 %0, t; }"
        : "=r"(a) : "l"(p));
    return a;
}

#define CP16(dst, src) \
    asm volatile("cp.async.cg.shared.global [%0], [%1], 16;" \
                 :: "r"(dst), "l"(src) : "memory")
#define CPCOMMIT() asm volatile("cp.async.commit_group;" ::: "memory")
#define CPWAIT(n)  asm volatile("cp.async.wait_group %0;" :: "n"(n) : "memory")

__device__ __forceinline__ void ldmx4(uint32_t& r0, uint32_t& r1,
                                      uint32_t& r2, uint32_t& r3, uint32_t a) {
    asm volatile("ldmatrix.sync.aligned.m8n8.x4.shared.b16 {%0,%1,%2,%3}, [%4];"
                 : "=r"(r0), "=r"(r1), "=r"(r2), "=r"(r3) : "r"(a));
}

__device__ __forceinline__ void mma16816(float* d, const uint32_t* a,
                                         const uint32_t* b) {
    asm volatile(
        "mma.sync.aligned.m16n8k16.row.col.f32.f16.f16.f32 "
        "{%0,%1,%2,%3},{%4,%5,%6,%7},{%8,%9},{%0,%1,%2,%3};"
        : "+f"(d[0]), "+f"(d[1]), "+f"(d[2]), "+f"(d[3])
        : "r"(a[0]), "r"(a[1]), "r"(a[2]), "r"(a[3]), "r"(b[0]), "r"(b[1]));
}

__device__ __forceinline__ void mma_s8(int* d, const uint32_t* a,
                                       const uint32_t* b) {
    asm volatile(
        "mma.sync.aligned.m16n8k32.row.col.s32.s8.s8.s32 "
        "{%0,%1,%2,%3},{%4,%5,%6,%7},{%8,%9},{%0,%1,%2,%3};"
        : "+r"(d[0]), "+r"(d[1]), "+r"(d[2]), "+r"(d[3])
        : "r"(a[0]), "r"(a[1]), "r"(a[2]), "r"(a[3]), "r"(b[0]), "r"(b[1]));
}

__device__ __forceinline__ uint32_t packh(float a, float b) {
    __half2 t = __floats2half2_rn(a, b);
    return *reinterpret_cast<uint32_t*>(&t);
}

// 16-bit fixed point -> two int8 digits (hi*256 + lo == q, exact)
__device__ __forceinline__ void qsplit(float v, float S, int8_t& hi, int8_t& lo) {
    int q = __float2int_rn(v * S);
    q = max(-32512, min(32512, q));
    int l = ((q + 128) & 255) - 128;
    hi = (int8_t)((q - l) >> 8);
    lo = (int8_t)l;
}

__device__ __forceinline__ float comb8(int hh, int mid) {
    return fmaf((float)hh, 65536.f, (float)mid * 256.f) * INV_SC;
}

// ---------------------------------------------------------------------------
// precompute kernels
// ---------------------------------------------------------------------------
__global__ void quant8_kernel(const float* __restrict__ src,
                              int8_t* __restrict__ h, int8_t* __restrict__ l,
                              float S, int n4)
{
    int i = blockIdx.x * blockDim.x + threadIdx.x;
    if (i >= n4) return;
    float4 v = ((const float4*)src)[i];
    int8_t h0, h1, h2, h3, l0, l1, l2, l3;
    qsplit(v.x, S, h0, l0);
    qsplit(v.y, S, h1, l1);
    qsplit(v.z, S, h2, l2);
    qsplit(v.w, S, h3, l3);
    ((char4*)h)[i] = make_char4(h0, h1, h2, h3);
    ((char4*)l)[i] = make_char4(l0, l1, l2, l3);
}

__global__ void conv_w_kernel(const float* __restrict__ src,
                              half* __restrict__ h, int n4)
{
    int i = blockIdx.x * blockDim.x + threadIdx.x;
    if (i >= n4) return;
    float4 v = ((const float4*)src)[i];
    __half2 a = __floats2half2_rn(v.x * 64.f, v.y * 64.f);
    __half2 b = __floats2half2_rn(v.z * 64.f, v.w * 64.f);
    uint2 o;
    o.x = *reinterpret_cast<uint32_t*>(&a);
    o.y = *reinterpret_cast<uint32_t*>(&b);
    ((uint2*)h)[i] = o;
}

__global__ void rope_table_kernel()
{
    int idx = blockIdx.x * blockDim.x + threadIdx.x;
    if (idx >= TT * 32) return;
    int t = idx >> 5;
    int i = idx & 31;
    double inv = pow(10000.0, -(double)i / 32.0);
    double a   = (double)t * inv;
    g_cos[idx] = (float)cos(a);
    g_sin[idx] = (float)sin(a);
}

// ---------------------------------------------------------------------------
// Fused QKV int8 2-digit GEMM + RoPE epilogue.
// Combined weights [NC=3072, 2048]: cols [0,2048)=Q, [2048,2560)=K, [2560,3072)=V.
// Epilogue: Q -> rope*0.125 -> g_Qh;  K -> rope -> g_Kh;  V -> transpose g_Vth.
// RoPE pair (i, i+32) = accumulator tiles nt and nt+4 of the SAME thread.
// ---------------------------------------------------------------------------
#define PI8  48
#define MAT8 (128 * PI8)        /* 6144 B */
#define STG8 (4 * MAT8)         /* 24576 B */
#define GEMM8_SMEM (2 * STG8)   /* 49152 B */

__global__ void __launch_bounds__(256, 1)
gemm8_qkv(const int8_t* __restrict__ Ah, const int8_t* __restrict__ Al,
          const int8_t* __restrict__ Wh, const int8_t* __restrict__ Wl)
{
    extern __shared__ char smc[];
    const uint32_t sb = smem_u32(smc);
    const int tid  = threadIdx.x;
    const int lane = tid & 31;
    const int wid  = tid >> 5;
    const int wm = (wid & 3) * 32;
    const int wn = (wid >> 2) * 64;
    const int m0 = blockIdx.y * 128;
    const int n0 = blockIdx.x * 128;
    const int K  = DM;

    int hh[2][8][4], mid[2][8][4];
#pragma unroll
    for (int mt = 0; mt < 2; mt++)
#pragma unroll
        for (int nt = 0; nt < 8; nt++)
#pragma unroll
            for (int j = 0; j < 4; j++) { hh[mt][nt][j] = 0; mid[mt][nt][j] = 0; }

    const int quad  = lane >> 3;
    const int arow  = (lane & 7) + (quad & 1) * 8;
    const int acolB = (quad >> 1) * 16;
    const int brow  = (lane & 7) + (quad >> 1) * 8;
    const int bcolB = (quad & 1) * 16;

    const int row = tid >> 1;
    const int cc  = tid & 1;
    const int nch = K / 32;

#define L8(c, sel) do {                                                       \
    uint32_t d0 = sb + (sel) * STG8 + (uint32_t)(row * PI8 + cc * 16);        \
    size_t ao = (size_t)(m0 + row) * K + (size_t)(c) * 32 + cc * 16;          \
    size_t wo = (size_t)(n0 + row) * K + (size_t)(c) * 32 + cc * 16;          \
    CP16(d0,            Ah + ao);                                             \
    CP16(d0 + MAT8,     Al + ao);                                             \
    CP16(d0 + 2 * MAT8, Wh + wo);                                             \
    CP16(d0 + 3 * MAT8, Wl + wo);                                             \
    CPCOMMIT();                                                               \
} while (0)

    L8(0, 0);

    for (int c = 0; c < nch; c++) {
        if (c + 1 < nch) {
            L8(c + 1, (c + 1) & 1);
            CPWAIT(1);
        } else {
            CPWAIT(0);
        }
        __syncthreads();

        const uint32_t base = sb + (c & 1) * STG8;

        uint32_t ahi[2][4], alo[2][4];
#pragma unroll
        for (int mt = 0; mt < 2; mt++) {
            uint32_t addr = base + (uint32_t)((wm + mt * 16 + arow) * PI8 + acolB);
            ldmx4(ahi[mt][0], ahi[mt][1], ahi[mt][2], ahi[mt][3], addr);
            ldmx4(alo[mt][0], alo[mt][1], alo[mt][2], alo[mt][3], addr + MAT8);
        }
#pragma unroll
        for (int np = 0; np < 4; np++) {
            uint32_t baddr = base + 2 * MAT8 +
                             (uint32_t)((wn + np * 16 + brow) * PI8 + bcolB);
            uint32_t bh[4], bl[4];
            ldmx4(bh[0], bh[1], bh[2], bh[3], baddr);
            ldmx4(bl[0], bl[1], bl[2], bl[3], baddr + MAT8);
            uint32_t b0h[2] = {bh[0], bh[1]}, b1h[2] = {bh[2], bh[3]};
            uint32_t b0l[2] = {bl[0], bl[1]}, b1l[2] = {bl[2], bl[3]};
#pragma unroll
            for (int mt = 0; mt < 2; mt++) {
                mma_s8(hh[mt][2 * np],      ahi[mt], b0h);
                mma_s8(hh[mt][2 * np + 1],  ahi[mt], b1h);
                mma_s8(mid[mt][2 * np],     ahi[mt], b0l);
                mma_s8(mid[mt][2 * np + 1], ahi[mt], b1l);
                mma_s8(mid[mt][2 * np],     alo[mt], b0h);
                mma_s8(mid[mt][2 * np + 1], alo[mt], b1h);
            }
        }
        __syncthreads();
    }
#undef L8

    // ------------- epilogue (region-uniform per CTA) -------------
    if (n0 < DM || (n0 >= DM && n0 < DM + KVD)) {
        // Q or K region: apply RoPE in registers.
        const bool isQ = (n0 < DM);
        const float osc = isQ ? 0.125f : 1.f;
        half* dst = isQ ? g_Qh : g_Kh;
        const int dstride = isQ ? DM : KVD;
        const int coff = isQ ? 0 : DM;
#pragma unroll
        for (int mt = 0; mt < 2; mt++) {
            const int r0 = m0 + wm + mt * 16 + (lane >> 2);
#pragma unroll
            for (int nt = 0; nt < 4; nt++) {
                const int colb = n0 + wn + nt * 8 + (lane & 3) * 2;  // channel i<32
                const int i = colb & 31;
                float o0[4], o1[4];
#pragma unroll
                for (int j = 0; j < 4; j++) {
                    int rr = r0 + ((j >> 1) << 3);
                    int t  = rr & (TT - 1);
                    int ii = i + (j & 1);
                    float cv = g_cos[t * 32 + ii];
                    float sv = g_sin[t * 32 + ii];
                    float v0 = comb8(hh[mt][nt][j],     mid[mt][nt][j]);
                    float v1 = comb8(hh[mt][nt + 4][j], mid[mt][nt + 4][j]);
                    o0[j] = (v0 * cv - v1 * sv) * osc;
                    o1[j] = (v1 * cv + v0 * sv) * osc;
                }
                size_t b0 = (size_t)r0 * dstride + (colb - coff);
                size_t b1 = (size_t)(r0 + 8) * dstride + (colb - coff);
                *(uint32_t*)(dst + b0)      = packh(o0[0], o0[1]);
                *(uint32_t*)(dst + b0 + 32) = packh(o1[0], o1[1]);
                *(uint32_t*)(dst + b1)      = packh(o0[2], o0[3]);
                *(uint32_t*)(dst + b1 + 32) = packh(o1[2], o1[3]);
            }
        }
    } else {
        // V region: transposed single fp16 store (b,g,d,t)
#pragma unroll
        for (int mt = 0; mt < 2; mt++) {
            int rowt = m0 + wm + mt * 16 + (lane >> 2);
#pragma unroll
            for (int nt = 0; nt < 8; nt++) {
                int col = n0 - (DM + KVD) + wn + nt * 8 + (lane & 3) * 2;
#pragma unroll
                for (int j = 0; j < 4; j++) {
                    int r = rowt + ((j >> 1) << 3);
                    int cc2 = col + (j & 1);
                    int b = r >> 11, t = r & (TT - 1);
                    size_t di = (((size_t)b * NKV + (cc2 >> 6)) * DH + (cc2 & 63)) * TT + t;
                    g_Vth[di] = __float2half_rn(comb8(hh[mt][nt][j], mid[mt][nt][j]));
                }
            }
        }
    }
}

// ---------------------------------------------------------------------------
// fp16 1-term GEMM (output projection): C = Ah @ Wh^T, scale 2^-10.
// ---------------------------------------------------------------------------
#define PITCH 40
#define MAT2  (128 * PITCH * 2)
#define STAGE2 (2 * MAT2)
#define GEMM2_SMEM (2 * STAGE2)
#define OUT_SCALE (1.f / 1024.f)

__global__ void __launch_bounds__(256, 1)
gemm2_f32(const half* __restrict__ Ah, const half* __restrict__ Wh,
          float* __restrict__ C, int N, int K)
{
    extern __shared__ char smc[];
    const uint32_t sb = smem_u32(smc);
    const int tid  = threadIdx.x;
    const int lane = tid & 31;
    const int wid  = tid >> 5;
    const int wm = (wid & 3) * 32;
    const int wn = (wid >> 2) * 64;
    const int m0 = blockIdx.y * 128;
    const int n0 = blockIdx.x * 128;

    float acc[2][8][4];
#pragma unroll
    for (int mt = 0; mt < 2; mt++)
#pragma unroll
        for (int nt = 0; nt < 8; nt++)
#pragma unroll
            for (int j = 0; j < 4; j++) acc[mt][nt][j] = 0.f;

    const int quad = lane >> 3;
    const int arow_off = (lane & 7) + (quad & 1) * 8;
    const int acol_off = (quad >> 1) * 8;
    const int brow_off = (lane & 7) + (quad >> 1) * 8;
    const int bcol_off = (quad & 1) * 8;

    const int nch = K / 32;
    const int r_  = tid >> 2;
    const int q_  = tid & 3;

#define LOAD2(c, sel) do {                                                    \
    const uint32_t d0 = sb + (sel) * STAGE2;                                  \
    _Pragma("unroll")                                                         \
    for (int l = 0; l < 2; l++) {                                             \
        int row = r_ + l * 64;                                                \
        uint32_t doff = (uint32_t)(row * PITCH + q_ * 8) * 2;                 \
        size_t aoff = (size_t)(m0 + row) * K + (c) * 32 + q_ * 8;             \
        size_t woff = (size_t)(n0 + row) * K + (c) * 32 + q_ * 8;             \
        CP16(d0 + doff,        Ah + aoff);                                    \
        CP16(d0 + MAT2 + doff, Wh + woff);                                    \
    }                                                                         \
    CPCOMMIT();                                                               \
} while (0)

    LOAD2(0, 0);

    for (int c = 0; c < nch; c++) {
        if (c + 1 < nch) {
            LOAD2(c + 1, (c + 1) & 1);
            CPWAIT(1);
        } else {
            CPWAIT(0);
        }
        __syncthreads();

        const uint32_t base = sb + (c & 1) * STAGE2;
#pragma unroll
        for (int ks = 0; ks < 32; ks += 16) {
            uint32_t ah[2][4];
#pragma unroll
            for (int mt = 0; mt < 2; mt++) {
                uint32_t addr = base +
                    ((uint32_t)((wm + mt * 16 + arow_off) * PITCH + ks + acol_off) << 1);
                ldmx4(ah[mt][0], ah[mt][1], ah[mt][2], ah[mt][3], addr);
            }
            uint32_t bh[8][2];
#pragma unroll
            for (int np = 0; np < 4; np++) {
                uint32_t addr = base + MAT2 +
                    ((uint32_t)((wn + np * 16 + brow_off) * PITCH + ks + bcol_off) << 1);
                uint32_t r0, r1, r2, r3;
                ldmx4(r0, r1, r2, r3, addr);
                bh[2 * np][0] = r0; bh[2 * np][1] = r1;
                bh[2 * np + 1][0] = r2; bh[2 * np + 1][1] = r3;
            }
#pragma unroll
            for (int mt = 0; mt < 2; mt++)
#pragma unroll
                for (int nt = 0; nt < 8; nt++)
                    mma16816(acc[mt][nt], ah[mt], bh[nt]);
        }
        __syncthreads();
    }
#undef LOAD2

#pragma unroll
    for (int mt = 0; mt < 2; mt++) {
        int row = m0 + wm + mt * 16 + (lane >> 2);
#pragma unroll
        for (int nt = 0; nt < 8; nt++) {
            int col = n0 + wn + nt * 8 + (lane & 3) * 2;
            *(float2*)(C + (size_t)row * N + col) =
                make_float2(acc[mt][nt][0] * OUT_SCALE, acc[mt][nt][1] * OUT_SCALE);
            *(float2*)(C + (size_t)(row + 8) * N + col) =
                make_float2(acc[mt][nt][2] * OUT_SCALE, acc[mt][nt][3] * OUT_SCALE);
        }
    }
}

// ---------------------------------------------------------------------------
// Flash attention, single-term fp16: S = qh*kh, PV = ph*vh.
// ---------------------------------------------------------------------------
#define KP 72
#define MATK (128 * KP * 2)          /* 18432 */
#define VP 136
#define VOFF MATK
#define VMAT (64 * VP * 2)           /* 17408 */
#define ATTN_SMEM (VOFF + VMAT)      /* 35840 */

__global__ void __launch_bounds__(256, 1) attn_mma()
{
    extern __shared__ char smc[];
    const uint32_t sb = smem_u32(smc);

    const int tid  = threadIdx.x;
    const int lane = tid & 31;
    const int wid  = tid >> 5;
    const int wq   = wid * 16;

    const int quad = lane >> 3;
    const int arow_off = (lane & 7) + (quad & 1) * 8;
    const int acol_off = (quad >> 1) * 8;
    const int brow_off = (lane & 7) + (quad >> 1) * 8;
    const int bcol_off = (quad & 1) * 8;

    const int q0 = (gridDim.x - 1 - blockIdx.x) * 128;
    const int h  = blockIdx.y;
    const int b  = blockIdx.z;
    const int g  = h >> 2;

    {
        const half* Qph = g_Qh + ((size_t)b * TT + q0) * DM + h * DH;
#pragma unroll
        for (int l = 0; l < 4; l++) {
            int idx = tid + l * 256;
            int r   = idx >> 3;
            int cq  = idx & 7;
            uint32_t off = (uint32_t)(r * KP + cq * 8) * 2;
            *(uint4*)(smc + off) = *(const uint4*)(Qph + (size_t)r * DM + cq * 8);
        }
    }
    __syncthreads();

    uint32_t qh[4][4];
#pragma unroll
    for (int ks = 0; ks < 4; ks++) {
        uint32_t addr = sb + ((uint32_t)((wq + arow_off) * KP + ks * 16 + acol_off) << 1);
        ldmx4(qh[ks][0], qh[ks][1], qh[ks][2], qh[ks][3], addr);
    }

    float oacc[8][4];
#pragma unroll
    for (int nt = 0; nt < 8; nt++)
#pragma unroll
        for (int j = 0; j < 4; j++) oacc[nt][j] = 0.f;
    float mrow0 = -1e30f, mrow1 = -1e30f, lrow0 = 0.f, lrow1 = 0.f;

    const int row0 = q0 + wq + (lane >> 2);
    const int row1 = row0 + 8;

    const half* Kb  = g_Kh  + (size_t)b * TT * KVD + g * DH;
    const half* Vbh = g_Vth + ((size_t)b * NKV + g) * DH * TT;

    for (int s0 = 0; s0 <= q0; s0 += 128) {
        __syncthreads();
#pragma unroll
        for (int l = 0; l < 4; l++) {
            int idx = tid + l * 256;
            {
                int s  = idx >> 3;
                int cq = idx & 7;
                size_t gi = (size_t)(s0 + s) * KVD + cq * 8;
                *(uint4*)(smc + (uint32_t)(s * KP + cq * 8) * 2) =
                    *(const uint4*)(Kb + gi);
            }
            if (l < 2) {
                int idx2 = tid + l * 256;
                int d  = idx2 >> 3;
                int cq = idx2 & 7;
                size_t gi = (size_t)d * TT + s0 + cq * 16;
                uint32_t off = VOFF + (uint32_t)(d * VP + cq * 16) * 2;
                *(uint4*)(smc + off)      = *(const uint4*)(Vbh + gi);
                *(uint4*)(smc + off + 16) = *(const uint4*)(Vbh + gi + 8);
            }
        }
        __syncthreads();

        float sacc[16][4];
#pragma unroll
        for (int nt = 0; nt < 16; nt++)
#pragma unroll
            for (int j = 0; j < 4; j++) sacc[nt][j] = 0.f;

#pragma unroll
        for (int np = 0; np < 8; np++) {
#pragma unroll
            for (int ks = 0; ks < 4; ks++) {
                uint32_t addr = sb +
                    ((uint32_t)((np * 16 + brow_off) * KP + ks * 16 + bcol_off) << 1);
                uint32_t h0, h1, h2, h3;
                ldmx4(h0, h1, h2, h3, addr);
                uint32_t bh0[2] = {h0, h1}, bh1[2] = {h2, h3};
                mma16816(sacc[2 * np],     qh[ks], bh0);
                mma16816(sacc[2 * np + 1], qh[ks], bh1);
            }
        }

        if (s0 == q0) {
            const int cbase = s0 + (lane & 3) * 2;
#pragma unroll
            for (int nt = 0; nt < 16; nt++) {
                int c0 = cbase + nt * 8;
                if (c0     > row0) sacc[nt][0] = -1e30f;
                if (c0 + 1 > row0) sacc[nt][1] = -1e30f;
                if (c0     > row1) sacc[nt][2] = -1e30f;
                if (c0 + 1 > row1) sacc[nt][3] = -1e30f;
            }
        }

        float mx0 = -1e30f, mx1 = -1e30f;
#pragma unroll
        for (int nt = 0; nt < 16; nt++) {
            mx0 = fmaxf(mx0, fmaxf(sacc[nt][0], sacc[nt][1]));
            mx1 = fmaxf(mx1, fmaxf(sacc[nt][2], sacc[nt][3]));
        }
        mx0 = fmaxf(mx0, __shfl_xor_sync(0xffffffffu, mx0, 1));
        mx0 = fmaxf(mx0, __shfl_xor_sync(0xffffffffu, mx0, 2));
        mx1 = fmaxf(mx1, __shfl_xor_sync(0xffffffffu, mx1, 1));
        mx1 = fmaxf(mx1, __shfl_xor_sync(0xffffffffu, mx1, 2));

        float mnew0 = fmaxf(mrow0, mx0);
        float mnew1 = fmaxf(mrow1, mx1);
        float alpha0 = __expf(mrow0 - mnew0);
        float alpha1 = __expf(mrow1 - mnew1);

        uint32_t ph[8][4];
        float rs0 = 0.f, rs1 = 0.f;
#pragma unroll
        for (int ks = 0; ks < 8; ks++) {
#pragma unroll
            for (int half_ = 0; half_ < 2; half_++) {
                int nt = 2 * ks + half_;
                float p0 = __expf(sacc[nt][0] - mnew0);
                float p1 = __expf(sacc[nt][1] - mnew0);
                float p2 = __expf(sacc[nt][2] - mnew1);
                float p3 = __expf(sacc[nt][3] - mnew1);
                rs0 += p0 + p1;
                rs1 += p2 + p3;
                ph[ks][2 * half_]     = packh(p0, p1);
                ph[ks][2 * half_ + 1] = packh(p2, p3);
            }
        }
        rs0 += __shfl_xor_sync(0xffffffffu, rs0, 1);
        rs0 += __shfl_xor_sync(0xffffffffu, rs0, 2);
        rs1 += __shfl_xor_sync(0xffffffffu, rs1, 1);
        rs1 += __shfl_xor_sync(0xffffffffu, rs1, 2);

        lrow0 = lrow0 * alpha0 + rs0;
        lrow1 = lrow1 * alpha1 + rs1;
        mrow0 = mnew0;
        mrow1 = mnew1;
#pragma unroll
        for (int nt = 0; nt < 8; nt++) {
            oacc[nt][0] *= alpha0;
            oacc[nt][1] *= alpha0;
            oacc[nt][2] *= alpha1;
            oacc[nt][3] *= alpha1;
        }

#pragma unroll
        for (int np = 0; np < 4; np++) {
#pragma unroll
            for (int ks = 0; ks < 8; ks++) {
                uint32_t addr = sb + VOFF +
                    ((uint32_t)((np * 16 + brow_off) * VP + ks * 16 + bcol_off) << 1);
                uint32_t h0, h1, h2, h3;
                ldmx4(h0, h1, h2, h3, addr);
                uint32_t bh0[2] = {h0, h1}, bh1[2] = {h2, h3};
                mma16816(oacc[2 * np],     ph[ks], bh0);
                mma16816(oacc[2 * np + 1], ph[ks], bh1);
            }
        }
    }

    float inv0 = 16.f / lrow0;
    float inv1 = 16.f / lrow1;
    const size_t o0 = ((size_t)b * TT + row0) * DM + h * DH + (lane & 3) * 2;
    const size_t o1 = ((size_t)b * TT + row1) * DM + h * DH + (lane & 3) * 2;
#pragma unroll
    for (int nt = 0; nt < 8; nt++) {
        *(uint32_t*)(g_Ah + o0 + nt * 8) =
            packh(oacc[nt][0] * inv0, oacc[nt][1] * inv0);
        *(uint32_t*)(g_Ah + o1 + nt * 8) =
            packh(oacc[nt][2] * inv1, oacc[nt][3] * inv1);
    }
}

// ---------------------------------------------------------------------------
extern "C" void kernel_launch(void* const* d_in, const int* in_sizes, int n_in,
                              void* d_out, int out_size)
{
    const float* x  = (const float*)d_in[0];
    const float* Wq = (const float*)d_in[1];
    const float* Wk = (const float*)d_in[2];
    const float* Wv = (const float*)d_in[3];
    const float* Wo = (const float*)d_in[4];
    float* out = (float*)d_out;

    int8_t *x8h, *x8l, *wc8h, *wc8l;
    half *wo, *ah, *vth;
    cudaGetSymbolAddress((void**)&x8h, g_x8h);   cudaGetSymbolAddress((void**)&x8l, g_x8l);
    cudaGetSymbolAddress((void**)&wc8h, g_Wc8h); cudaGetSymbolAddress((void**)&wc8l, g_Wc8l);
    cudaGetSymbolAddress((void**)&wo, g_Wo);
    cudaGetSymbolAddress((void**)&ah, g_Ah);
    cudaGetSymbolAddress((void**)&vth, g_Vth);

    cudaFuncSetAttribute(gemm8_qkv, cudaFuncAttributeMaxDynamicSharedMemorySize,
                         GEMM8_SMEM);
    cudaFuncSetAttribute(gemm2_f32, cudaFuncAttributeMaxDynamicSharedMemorySize,
                         GEMM2_SMEM);
    cudaFuncSetAttribute(attn_mma, cudaFuncAttributeMaxDynamicSharedMemorySize,
                         ATTN_SMEM);

    // ---- precompute (rope table first; independent)
    rope_table_kernel<<<(TT * 32 + 255) / 256, 256>>>();
    {
        int n4 = BT * DM / 4;
        quant8_kernel<<<(n4 + 255) / 256, 256>>>(x, x8h, x8l, S_X, n4);
        n4 = DM * DM / 4;
        quant8_kernel<<<(n4 + 255) / 256, 256>>>(Wq, wc8h, wc8l, S_W, n4);
        conv_w_kernel<<<(n4 + 255) / 256, 256>>>(Wo, wo, n4);
        n4 = KVD * DM / 4;
        quant8_kernel<<<(n4 + 255) / 256, 256>>>(
            Wk, wc8h + (size_t)DM * DM, wc8l + (size_t)DM * DM, S_W, n4);
        quant8_kernel<<<(n4 + 255) / 256, 256>>>(
            Wv, wc8h + (size_t)(DM + KVD) * DM, wc8l + (size_t)(DM + KVD) * DM, S_W, n4);
    }

    // ---- fused QKV projection + RoPE (IMMA)
    gemm8_qkv<<<dim3(NC / 128, BT / 128), 256, GEMM8_SMEM>>>(x8h, x8l, wc8h, wc8l);

    // ---- attention (single-term fp16 HMMA)
    attn_mma<<<dim3(TT / 128, NH, BB), 256, ATTN_SMEM>>>();

    // ---- output projection (single-term fp16)
    gemm2_f32<<<dim3(DM / 128, BT / 128), 256, GEMM2_SMEM>>>(ah, wo, out, DM, DM);
}

// round 11
// speedup vs baseline: 4.4103x; 1.0207x over previous
#include <cuda_runtime.h>
#include <cuda_fp16.h>
#include <math.h>
#include <stdint.h>

#define BB  2
#define TT  2048
#define DM  2048
#define NH  32
#define NKV 8
#define DH  64
#define BT  (BB*TT)
#define KVD (NKV*DH)   /* 512 */
#define NC  (DM + 2*KVD)   /* 3072 combined output cols */

#define S_X    4096.f          /* 2^12 */
#define S_W    262144.f        /* 2^18 */
#define INV_SC (1.f / 1073741824.f)   /* 2^-30 */

// ---------------- scratch (device globals; no allocations allowed) ----------
__device__ int8_t g_x8h[(size_t)BT * DM],  g_x8l[(size_t)BT * DM];
__device__ int8_t g_Wc8h[(size_t)NC * DM], g_Wc8l[(size_t)NC * DM]; // Wq|Wk|Wv

__device__ half g_Wo[(size_t)DM * DM];                            // Wo * 64 single
__device__ half g_Ah[(size_t)BT * DM];                            // attn out x16 single

__device__ half g_Qh[(size_t)BT * DM];                            // roped, x0.125 single
__device__ half g_Kh[(size_t)BT * KVD];                           // roped, single
__device__ half g_Vth[(size_t)BT * KVD];                          // (b,g,d,t) single

__device__ float g_cos[TT * 32];
__device__ float g_sin[TT * 32];

// ===================== helpers ======================
__device__ __forceinline__ uint32_t smem_u32(const void* p) {
    uint32_t a;
    asm("{ .reg .u64 t; cvta.to.shared.u64 t, %1; cvt.u32.u64 %0, t; }"
        : "=r"(a) : "l"(p));
    return a;
}

#define CP16(dst, src) \
    asm volatile("cp.async.cg.shared.global [%0], [%1], 16;" \
                 :: "r"(dst), "l"(src) : "memory")
#define CPCOMMIT() asm volatile("cp.async.commit_group;" ::: "memory")
#define CPWAIT(n)  asm volatile("cp.async.wait_group %0;" :: "n"(n) : "memory")

__device__ __forceinline__ void ldmx4(uint32_t& r0, uint32_t& r1,
                                      uint32_t& r2, uint32_t& r3, uint32_t a) {
    asm volatile("ldmatrix.sync.aligned.m8n8.x4.shared.b16 {%0,%1,%2,%3}, [%4];"
                 : "=r"(r0), "=r"(r1), "=r"(r2), "=r"(r3) : "r"(a));
}

__device__ __forceinline__ void mma16816(float* d, const uint32_t* a,
                                         const uint32_t* b) {
    asm volatile(
        "mma.sync.aligned.m16n8k16.row.col.f32.f16.f16.f32 "
        "{%0,%1,%2,%3},{%4,%5,%6,%7},{%8,%9},{%0,%1,%2,%3};"
        : "+f"(d[0]), "+f"(d[1]), "+f"(d[2]), "+f"(d[3])
        : "r"(a[0]), "r"(a[1]), "r"(a[2]), "r"(a[3]), "r"(b[0]), "r"(b[1]));
}

__device__ __forceinline__ void mma_s8(int* d, const uint32_t* a,
                                       const uint32_t* b) {
    asm volatile(
        "mma.sync.aligned.m16n8k32.row.col.s32.s8.s8.s32 "
        "{%0,%1,%2,%3},{%4,%5,%6,%7},{%8,%9},{%0,%1,%2,%3};"
        : "+r"(d[0]), "+r"(d[1]), "+r"(d[2]), "+r"(d[3])
        : "r"(a[0]), "r"(a[1]), "r"(a[2]), "r"(a[3]), "r"(b[0]), "r"(b[1]));
}

__device__ __forceinline__ uint32_t packh(float a, float b) {
    __half2 t = __floats2half2_rn(a, b);
    return *reinterpret_cast<uint32_t*>(&t);
}

// 16-bit fixed point -> two int8 digits (hi*256 + lo == q, exact)
__device__ __forceinline__ void qsplit(float v, float S, int8_t& hi, int8_t& lo) {
    int q = __float2int_rn(v * S);
    q = max(-32512, min(32512, q));
    int l = ((q + 128) & 255) - 128;
    hi = (int8_t)((q - l) >> 8);
    lo = (int8_t)l;
}

__device__ __forceinline__ float comb8(int hh, int mid) {
    return fmaf((float)hh, 65536.f, (float)mid * 256.f) * INV_SC;
}

// ---------------------------------------------------------------------------
// precompute kernels
// ---------------------------------------------------------------------------
__global__ void quant8_kernel(const float* __restrict__ src,
                              int8_t* __restrict__ h, int8_t* __restrict__ l,
                              float S, int n4)
{
    int i = blockIdx.x * blockDim.x + threadIdx.x;
    if (i >= n4) return;
    float4 v = ((const float4*)src)[i];
    int8_t h0, h1, h2, h3, l0, l1, l2, l3;
    qsplit(v.x, S, h0, l0);
    qsplit(v.y, S, h1, l1);
    qsplit(v.z, S, h2, l2);
    qsplit(v.w, S, h3, l3);
    ((char4*)h)[i] = make_char4(h0, h1, h2, h3);
    ((char4*)l)[i] = make_char4(l0, l1, l2, l3);
}

__global__ void conv_w_kernel(const float* __restrict__ src,
                              half* __restrict__ h, int n4)
{
    int i = blockIdx.x * blockDim.x + threadIdx.x;
    if (i >= n4) return;
    float4 v = ((const float4*)src)[i];
    __half2 a = __floats2half2_rn(v.x * 64.f, v.y * 64.f);
    __half2 b = __floats2half2_rn(v.z * 64.f, v.w * 64.f);
    uint2 o;
    o.x = *reinterpret_cast<uint32_t*>(&a);
    o.y = *reinterpret_cast<uint32_t*>(&b);
    ((uint2*)h)[i] = o;
}

__global__ void rope_table_kernel()
{
    int idx = blockIdx.x * blockDim.x + threadIdx.x;
    if (idx >= TT * 32) return;
    int t = idx >> 5;
    int i = idx & 31;
    double inv = pow(10000.0, -(double)i / 32.0);
    double a   = (double)t * inv;
    g_cos[idx] = (float)cos(a);
    g_sin[idx] = (float)sin(a);
}

// ---------------------------------------------------------------------------
// Fused QKV int8 2-digit GEMM + RoPE epilogue. (unchanged from round 10)
// ---------------------------------------------------------------------------
#define PI8  48
#define MAT8 (128 * PI8)        /* 6144 B */
#define STG8 (4 * MAT8)         /* 24576 B */
#define GEMM8_SMEM (2 * STG8)   /* 49152 B */

__global__ void __launch_bounds__(256, 1)
gemm8_qkv(const int8_t* __restrict__ Ah, const int8_t* __restrict__ Al,
          const int8_t* __restrict__ Wh, const int8_t* __restrict__ Wl)
{
    extern __shared__ char smc[];
    const uint32_t sb = smem_u32(smc);
    const int tid  = threadIdx.x;
    const int lane = tid & 31;
    const int wid  = tid >> 5;
    const int wm = (wid & 3) * 32;
    const int wn = (wid >> 2) * 64;
    const int m0 = blockIdx.y * 128;
    const int n0 = blockIdx.x * 128;
    const int K  = DM;

    int hh[2][8][4], mid[2][8][4];
#pragma unroll
    for (int mt = 0; mt < 2; mt++)
#pragma unroll
        for (int nt = 0; nt < 8; nt++)
#pragma unroll
            for (int j = 0; j < 4; j++) { hh[mt][nt][j] = 0; mid[mt][nt][j] = 0; }

    const int quad  = lane >> 3;
    const int arow  = (lane & 7) + (quad & 1) * 8;
    const int acolB = (quad >> 1) * 16;
    const int brow  = (lane & 7) + (quad >> 1) * 8;
    const int bcolB = (quad & 1) * 16;

    const int row = tid >> 1;
    const int cc  = tid & 1;
    const int nch = K / 32;

#define L8(c, sel) do {                                                       \
    uint32_t d0 = sb + (sel) * STG8 + (uint32_t)(row * PI8 + cc * 16);        \
    size_t ao = (size_t)(m0 + row) * K + (size_t)(c) * 32 + cc * 16;          \
    size_t wo = (size_t)(n0 + row) * K + (size_t)(c) * 32 + cc * 16;          \
    CP16(d0,            Ah + ao);                                             \
    CP16(d0 + MAT8,     Al + ao);                                             \
    CP16(d0 + 2 * MAT8, Wh + wo);                                             \
    CP16(d0 + 3 * MAT8, Wl + wo);                                             \
    CPCOMMIT();                                                               \
} while (0)

    L8(0, 0);

    for (int c = 0; c < nch; c++) {
        if (c + 1 < nch) {
            L8(c + 1, (c + 1) & 1);
            CPWAIT(1);
        } else {
            CPWAIT(0);
        }
        __syncthreads();

        const uint32_t base = sb + (c & 1) * STG8;

        uint32_t ahi[2][4], alo[2][4];
#pragma unroll
        for (int mt = 0; mt < 2; mt++) {
            uint32_t addr = base + (uint32_t)((wm + mt * 16 + arow) * PI8 + acolB);
            ldmx4(ahi[mt][0], ahi[mt][1], ahi[mt][2], ahi[mt][3], addr);
            ldmx4(alo[mt][0], alo[mt][1], alo[mt][2], alo[mt][3], addr + MAT8);
        }
#pragma unroll
        for (int np = 0; np < 4; np++) {
            uint32_t baddr = base + 2 * MAT8 +
                             (uint32_t)((wn + np * 16 + brow) * PI8 + bcolB);
            uint32_t bh[4], bl[4];
            ldmx4(bh[0], bh[1], bh[2], bh[3], baddr);
            ldmx4(bl[0], bl[1], bl[2], bl[3], baddr + MAT8);
            uint32_t b0h[2] = {bh[0], bh[1]}, b1h[2] = {bh[2], bh[3]};
            uint32_t b0l[2] = {bl[0], bl[1]}, b1l[2] = {bl[2], bl[3]};
#pragma unroll
            for (int mt = 0; mt < 2; mt++) {
                mma_s8(hh[mt][2 * np],      ahi[mt], b0h);
                mma_s8(hh[mt][2 * np + 1],  ahi[mt], b1h);
                mma_s8(mid[mt][2 * np],     ahi[mt], b0l);
                mma_s8(mid[mt][2 * np + 1], ahi[mt], b1l);
                mma_s8(mid[mt][2 * np],     alo[mt], b0h);
                mma_s8(mid[mt][2 * np + 1], alo[mt], b1h);
            }
        }
        __syncthreads();
    }
#undef L8

    // ------------- epilogue (region-uniform per CTA) -------------
    if (n0 < DM + KVD) {
        const bool isQ = (n0 < DM);
        const float osc = isQ ? 0.125f : 1.f;
        half* dst = isQ ? g_Qh : g_Kh;
        const int dstride = isQ ? DM : KVD;
        const int coff = isQ ? 0 : DM;
#pragma unroll
        for (int mt = 0; mt < 2; mt++) {
            const int r0 = m0 + wm + mt * 16 + (lane >> 2);
#pragma unroll
            for (int nt = 0; nt < 4; nt++) {
                const int colb = n0 + wn + nt * 8 + (lane & 3) * 2;
                const int i = colb & 31;
                float o0[4], o1[4];
#pragma unroll
                for (int j = 0; j < 4; j++) {
                    int rr = r0 + ((j >> 1) << 3);
                    int t  = rr & (TT - 1);
                    int ii = i + (j & 1);
                    float cv = g_cos[t * 32 + ii];
                    float sv = g_sin[t * 32 + ii];
                    float v0 = comb8(hh[mt][nt][j],     mid[mt][nt][j]);
                    float v1 = comb8(hh[mt][nt + 4][j], mid[mt][nt + 4][j]);
                    o0[j] = (v0 * cv - v1 * sv) * osc;
                    o1[j] = (v1 * cv + v0 * sv) * osc;
                }
                size_t b0 = (size_t)r0 * dstride + (colb - coff);
                size_t b1 = (size_t)(r0 + 8) * dstride + (colb - coff);
                *(uint32_t*)(dst + b0)      = packh(o0[0], o0[1]);
                *(uint32_t*)(dst + b0 + 32) = packh(o1[0], o1[1]);
                *(uint32_t*)(dst + b1)      = packh(o0[2], o0[3]);
                *(uint32_t*)(dst + b1 + 32) = packh(o1[2], o1[3]);
            }
        }
    } else {
#pragma unroll
        for (int mt = 0; mt < 2; mt++) {
            int rowt = m0 + wm + mt * 16 + (lane >> 2);
#pragma unroll
            for (int nt = 0; nt < 8; nt++) {
                int col = n0 - (DM + KVD) + wn + nt * 8 + (lane & 3) * 2;
#pragma unroll
                for (int j = 0; j < 4; j++) {
                    int r = rowt + ((j >> 1) << 3);
                    int cc2 = col + (j & 1);
                    int b = r >> 11, t = r & (TT - 1);
                    size_t di = (((size_t)b * NKV + (cc2 >> 6)) * DH + (cc2 & 63)) * TT + t;
                    g_Vth[di] = __float2half_rn(comb8(hh[mt][nt][j], mid[mt][nt][j]));
                }
            }
        }
    }
}

// ---------------------------------------------------------------------------
// fp16 1-term GEMM (output projection): C = Ah @ Wh^T, scale 2^-10. (unchanged)
// ---------------------------------------------------------------------------
#define PITCH 40
#define MAT2  (128 * PITCH * 2)
#define STAGE2 (2 * MAT2)
#define GEMM2_SMEM (2 * STAGE2)
#define OUT_SCALE (1.f / 1024.f)

__global__ void __launch_bounds__(256, 1)
gemm2_f32(const half* __restrict__ Ah, const half* __restrict__ Wh,
          float* __restrict__ C, int N, int K)
{
    extern __shared__ char smc[];
    const uint32_t sb = smem_u32(smc);
    const int tid  = threadIdx.x;
    const int lane = tid & 31;
    const int wid  = tid >> 5;
    const int wm = (wid & 3) * 32;
    const int wn = (wid >> 2) * 64;
    const int m0 = blockIdx.y * 128;
    const int n0 = blockIdx.x * 128;

    float acc[2][8][4];
#pragma unroll
    for (int mt = 0; mt < 2; mt++)
#pragma unroll
        for (int nt = 0; nt < 8; nt++)
#pragma unroll
            for (int j = 0; j < 4; j++) acc[mt][nt][j] = 0.f;

    const int quad = lane >> 3;
    const int arow_off = (lane & 7) + (quad & 1) * 8;
    const int acol_off = (quad >> 1) * 8;
    const int brow_off = (lane & 7) + (quad >> 1) * 8;
    const int bcol_off = (quad & 1) * 8;

    const int nch = K / 32;
    const int r_  = tid >> 2;
    const int q_  = tid & 3;

#define LOAD2(c, sel) do {                                                    \
    const uint32_t d0 = sb + (sel) * STAGE2;                                  \
    _Pragma("unroll")                                                         \
    for (int l = 0; l < 2; l++) {                                             \
        int row = r_ + l * 64;                                                \
        uint32_t doff = (uint32_t)(row * PITCH + q_ * 8) * 2;                 \
        size_t aoff = (size_t)(m0 + row) * K + (c) * 32 + q_ * 8;             \
        size_t woff = (size_t)(n0 + row) * K + (c) * 32 + q_ * 8;             \
        CP16(d0 + doff,        Ah + aoff);                                    \
        CP16(d0 + MAT2 + doff, Wh + woff);                                    \
    }                                                                         \
    CPCOMMIT();                                                               \
} while (0)

    LOAD2(0, 0);

    for (int c = 0; c < nch; c++) {
        if (c + 1 < nch) {
            LOAD2(c + 1, (c + 1) & 1);
            CPWAIT(1);
        } else {
            CPWAIT(0);
        }
        __syncthreads();

        const uint32_t base = sb + (c & 1) * STAGE2;
#pragma unroll
        for (int ks = 0; ks < 32; ks += 16) {
            uint32_t ah[2][4];
#pragma unroll
            for (int mt = 0; mt < 2; mt++) {
                uint32_t addr = base +
                    ((uint32_t)((wm + mt * 16 + arow_off) * PITCH + ks + acol_off) << 1);
                ldmx4(ah[mt][0], ah[mt][1], ah[mt][2], ah[mt][3], addr);
            }
            uint32_t bh[8][2];
#pragma unroll
            for (int np = 0; np < 4; np++) {
                uint32_t addr = base + MAT2 +
                    ((uint32_t)((wn + np * 16 + brow_off) * PITCH + ks + bcol_off) << 1);
                uint32_t r0, r1, r2, r3;
                ldmx4(r0, r1, r2, r3, addr);
                bh[2 * np][0] = r0; bh[2 * np][1] = r1;
                bh[2 * np + 1][0] = r2; bh[2 * np + 1][1] = r3;
            }
#pragma unroll
            for (int mt = 0; mt < 2; mt++)
#pragma unroll
                for (int nt = 0; nt < 8; nt++)
                    mma16816(acc[mt][nt], ah[mt], bh[nt]);
        }
        __syncthreads();
    }
#undef LOAD2

#pragma unroll
    for (int mt = 0; mt < 2; mt++) {
        int row = m0 + wm + mt * 16 + (lane >> 2);
#pragma unroll
        for (int nt = 0; nt < 8; nt++) {
            int col = n0 + wn + nt * 8 + (lane & 3) * 2;
            *(float2*)(C + (size_t)row * N + col) =
                make_float2(acc[mt][nt][0] * OUT_SCALE, acc[mt][nt][1] * OUT_SCALE);
            *(float2*)(C + (size_t)(row + 8) * N + col) =
                make_float2(acc[mt][nt][2] * OUT_SCALE, acc[mt][nt][3] * OUT_SCALE);
        }
    }
}

// ---------------------------------------------------------------------------
// Flash attention, single-term fp16, DOUBLE-BUFFERED cp.async K/V pipeline.
// smem: K[2][128][KP] at 0; V[2][64][VP] at VOFF.
// ---------------------------------------------------------------------------
#define KP 72
#define MATK (128 * KP * 2)          /* 18432 */
#define VP 136
#define VOFF (2 * MATK)              /* 36864 */
#define VMAT (64 * VP * 2)           /* 17408 */
#define ATTN_SMEM (VOFF + 2 * VMAT)  /* 71680 */

__global__ void __launch_bounds__(256, 1) attn_mma()
{
    extern __shared__ char smc[];
    const uint32_t sb = smem_u32(smc);

    const int tid  = threadIdx.x;
    const int lane = tid & 31;
    const int wid  = tid >> 5;
    const int wq   = wid * 16;

    const int quad = lane >> 3;
    const int arow_off = (lane & 7) + (quad & 1) * 8;
    const int acol_off = (quad >> 1) * 8;
    const int brow_off = (lane & 7) + (quad >> 1) * 8;
    const int bcol_off = (quad & 1) * 8;

    const int q0 = (gridDim.x - 1 - blockIdx.x) * 128;
    const int h  = blockIdx.y;
    const int b  = blockIdx.z;
    const int g  = h >> 2;

    const half* Kb  = g_Kh  + (size_t)b * TT * KVD + g * DH;
    const half* Vbh = g_Vth + ((size_t)b * NKV + g) * DH * TT;

    // per-thread cp.async coordinates (1024 x 16B per matrix, 4 per thread)
    const int ks_ = tid >> 1;          // K row pair base: rows ks_, +128? no:
    // K: idx = tid + l*256 (l<4): s = idx>>3 (0..127), cq = idx&7
    // V: idx = tid + l*256 (l<4): d = idx>>4 (0..63),  cq = idx&15

#define ATT_LOAD(s0_, sel_) do {                                              \
    const uint32_t kb = sb + (sel_) * MATK;                                   \
    const uint32_t vb = sb + VOFF + (sel_) * VMAT;                            \
    _Pragma("unroll")                                                         \
    for (int l = 0; l < 4; l++) {                                             \
        int idx = tid + l * 256;                                              \
        int s  = idx >> 3, cq = idx & 7;                                      \
        CP16(kb + (uint32_t)(s * KP + cq * 8) * 2,                            \
             Kb + (size_t)((s0_) + s) * KVD + cq * 8);                        \
        int d  = idx >> 4, cv = idx & 15;                                     \
        CP16(vb + (uint32_t)(d * VP + cv * 8) * 2,                            \
             Vbh + (size_t)d * TT + (s0_) + cv * 8);                          \
    }                                                                         \
    CPCOMMIT();                                                               \
} while (0)

    // ---- stage Q via K buffer 0, read into registers
    {
        const half* Qph = g_Qh + ((size_t)b * TT + q0) * DM + h * DH;
#pragma unroll
        for (int l = 0; l < 4; l++) {
            int idx = tid + l * 256;
            int r   = idx >> 3;
            int cq  = idx & 7;
            uint32_t off = (uint32_t)(r * KP + cq * 8) * 2;
            *(uint4*)(smc + off) = *(const uint4*)(Qph + (size_t)r * DM + cq * 8);
        }
    }
    __syncthreads();

    uint32_t qh[4][4];
#pragma unroll
    for (int ks = 0; ks < 4; ks++) {
        uint32_t addr = sb + ((uint32_t)((wq + arow_off) * KP + ks * 16 + acol_off) << 1);
        ldmx4(qh[ks][0], qh[ks][1], qh[ks][2], qh[ks][3], addr);
    }
    __syncthreads();   // all Q reads done before cp.async overwrites buffer 0

    // prologue: block 0 -> buffer 0
    ATT_LOAD(0, 0);

    float oacc[8][4];
#pragma unroll
    for (int nt = 0; nt < 8; nt++)
#pragma unroll
        for (int j = 0; j < 4; j++) oacc[nt][j] = 0.f;
    float mrow0 = -1e30f, mrow1 = -1e30f, lrow0 = 0.f, lrow1 = 0.f;

    const int row0 = q0 + wq + (lane >> 2);
    const int row1 = row0 + 8;

    int it = 0;
    for (int s0 = 0; s0 <= q0; s0 += 128, it++) {
        const int sel = it & 1;
        if (s0 + 128 <= q0) {
            ATT_LOAD(s0 + 128, sel ^ 1);
            CPWAIT(1);
        } else {
            CPWAIT(0);
        }
        __syncthreads();

        const uint32_t kbuf = sb + sel * MATK;
        const uint32_t vbuf = sb + VOFF + sel * VMAT;

        // ---- S = Q K^T (single term)
        float sacc[16][4];
#pragma unroll
        for (int nt = 0; nt < 16; nt++)
#pragma unroll
            for (int j = 0; j < 4; j++) sacc[nt][j] = 0.f;

#pragma unroll
        for (int np = 0; np < 8; np++) {
#pragma unroll
            for (int ks = 0; ks < 4; ks++) {
                uint32_t addr = kbuf +
                    ((uint32_t)((np * 16 + brow_off) * KP + ks * 16 + bcol_off) << 1);
                uint32_t h0, h1, h2, h3;
                ldmx4(h0, h1, h2, h3, addr);
                uint32_t bh0[2] = {h0, h1}, bh1[2] = {h2, h3};
                mma16816(sacc[2 * np],     qh[ks], bh0);
                mma16816(sacc[2 * np + 1], qh[ks], bh1);
            }
        }

        if (s0 == q0) {
            const int cbase = s0 + (lane & 3) * 2;
#pragma unroll
            for (int nt = 0; nt < 16; nt++) {
                int c0 = cbase + nt * 8;
                if (c0     > row0) sacc[nt][0] = -1e30f;
                if (c0 + 1 > row0) sacc[nt][1] = -1e30f;
                if (c0     > row1) sacc[nt][2] = -1e30f;
                if (c0 + 1 > row1) sacc[nt][3] = -1e30f;
            }
        }

        float mx0 = -1e30f, mx1 = -1e30f;
#pragma unroll
        for (int nt = 0; nt < 16; nt++) {
            mx0 = fmaxf(mx0, fmaxf(sacc[nt][0], sacc[nt][1]));
            mx1 = fmaxf(mx1, fmaxf(sacc[nt][2], sacc[nt][3]));
        }
        mx0 = fmaxf(mx0, __shfl_xor_sync(0xffffffffu, mx0, 1));
        mx0 = fmaxf(mx0, __shfl_xor_sync(0xffffffffu, mx0, 2));
        mx1 = fmaxf(mx1, __shfl_xor_sync(0xffffffffu, mx1, 1));
        mx1 = fmaxf(mx1, __shfl_xor_sync(0xffffffffu, mx1, 2));

        float mnew0 = fmaxf(mrow0, mx0);
        float mnew1 = fmaxf(mrow1, mx1);
        float alpha0 = __expf(mrow0 - mnew0);
        float alpha1 = __expf(mrow1 - mnew1);

        uint32_t ph[8][4];
        float rs0 = 0.f, rs1 = 0.f;
#pragma unroll
        for (int ks = 0; ks < 8; ks++) {
#pragma unroll
            for (int half_ = 0; half_ < 2; half_++) {
                int nt = 2 * ks + half_;
                float p0 = __expf(sacc[nt][0] - mnew0);
                float p1 = __expf(sacc[nt][1] - mnew0);
                float p2 = __expf(sacc[nt][2] - mnew1);
                float p3 = __expf(sacc[nt][3] - mnew1);
                rs0 += p0 + p1;
                rs1 += p2 + p3;
                ph[ks][2 * half_]     = packh(p0, p1);
                ph[ks][2 * half_ + 1] = packh(p2, p3);
            }
        }
        rs0 += __shfl_xor_sync(0xffffffffu, rs0, 1);
        rs0 += __shfl_xor_sync(0xffffffffu, rs0, 2);
        rs1 += __shfl_xor_sync(0xffffffffu, rs1, 1);
        rs1 += __shfl_xor_sync(0xffffffffu, rs1, 2);

        lrow0 = lrow0 * alpha0 + rs0;
        lrow1 = lrow1 * alpha1 + rs1;
        mrow0 = mnew0;
        mrow1 = mnew1;
#pragma unroll
        for (int nt = 0; nt < 8; nt++) {
            oacc[nt][0] *= alpha0;
            oacc[nt][1] *= alpha0;
            oacc[nt][2] *= alpha1;
            oacc[nt][3] *= alpha1;
        }

        // ---- O += P V (single term)
#pragma unroll
        for (int np = 0; np < 4; np++) {
#pragma unroll
            for (int ks = 0; ks < 8; ks++) {
                uint32_t addr = vbuf +
                    ((uint32_t)((np * 16 + brow_off) * VP + ks * 16 + bcol_off) << 1);
                uint32_t h0, h1, h2, h3;
                ldmx4(h0, h1, h2, h3, addr);
                uint32_t bh0[2] = {h0, h1}, bh1[2] = {h2, h3};
                mma16816(oacc[2 * np],     ph[ks], bh0);
                mma16816(oacc[2 * np + 1], ph[ks], bh1);
            }
        }
        __syncthreads();   // all reads of buffer sel done before it is refilled
    }
#undef ATT_LOAD

    float inv0 = 16.f / lrow0;
    float inv1 = 16.f / lrow1;
    const size_t o0 = ((size_t)b * TT + row0) * DM + h * DH + (lane & 3) * 2;
    const size_t o1 = ((size_t)b * TT + row1) * DM + h * DH + (lane & 3) * 2;
#pragma unroll
    for (int nt = 0; nt < 8; nt++) {
        *(uint32_t*)(g_Ah + o0 + nt * 8) =
            packh(oacc[nt][0] * inv0, oacc[nt][1] * inv0);
        *(uint32_t*)(g_Ah + o1 + nt * 8) =
            packh(oacc[nt][2] * inv1, oacc[nt][3] * inv1);
    }
}

// ---------------------------------------------------------------------------
extern "C" void kernel_launch(void* const* d_in, const int* in_sizes, int n_in,
                              void* d_out, int out_size)
{
    const float* x  = (const float*)d_in[0];
    const float* Wq = (const float*)d_in[1];
    const float* Wk = (const float*)d_in[2];
    const float* Wv = (const float*)d_in[3];
    const float* Wo = (const float*)d_in[4];
    float* out = (float*)d_out;

    int8_t *x8h, *x8l, *wc8h, *wc8l;
    half *wo, *ah;
    cudaGetSymbolAddress((void**)&x8h, g_x8h);   cudaGetSymbolAddress((void**)&x8l, g_x8l);
    cudaGetSymbolAddress((void**)&wc8h, g_Wc8h); cudaGetSymbolAddress((void**)&wc8l, g_Wc8l);
    cudaGetSymbolAddress((void**)&wo, g_Wo);
    cudaGetSymbolAddress((void**)&ah, g_Ah);

    cudaFuncSetAttribute(gemm8_qkv, cudaFuncAttributeMaxDynamicSharedMemorySize,
                         GEMM8_SMEM);
    cudaFuncSetAttribute(gemm2_f32, cudaFuncAttributeMaxDynamicSharedMemorySize,
                         GEMM2_SMEM);
    cudaFuncSetAttribute(attn_mma, cudaFuncAttributeMaxDynamicSharedMemorySize,
                         ATTN_SMEM);

    // ---- precompute
    rope_table_kernel<<<(TT * 32 + 255) / 256, 256>>>();
    {
        int n4 = BT * DM / 4;
        quant8_kernel<<<(n4 + 255) / 256, 256>>>(x, x8h, x8l, S_X, n4);
        n4 = DM * DM / 4;
        quant8_kernel<<<(n4 + 255) / 256, 256>>>(Wq, wc8h, wc8l, S_W, n4);
        conv_w_kernel<<<(n4 + 255) / 256, 256>>>(Wo, wo, n4);
        n4 = KVD * DM / 4;
        quant8_kernel<<<(n4 + 255) / 256, 256>>>(
            Wk, wc8h + (size_t)DM * DM, wc8l + (size_t)DM * DM, S_W, n4);
        quant8_kernel<<<(n4 + 255) / 256, 256>>>(
            Wv, wc8h + (size_t)(DM + KVD) * DM, wc8l + (size_t)(DM + KVD) * DM, S_W, n4);
    }

    // ---- fused QKV projection + RoPE (IMMA)
    gemm8_qkv<<<dim3(NC / 128, BT / 128), 256, GEMM8_SMEM>>>(x8h, x8l, wc8h, wc8l);

    // ---- attention (pipelined single-term fp16 HMMA)
    attn_mma<<<dim3(TT / 128, NH, BB), 256, ATTN_SMEM>>>();

    // ---- output projection (single-term fp16)
    gemm2_f32<<<dim3(DM / 128, BT / 128), 256, GEMM2_SMEM>>>(ah, wo, out, DM, DM);
}